// round 5
// baseline (speedup 1.0000x reference)
#include <cuda_runtime.h>
#include <cuda_bf16.h>
#include <cstdint>

#define BS_    2
#define SEQ    1024
#define DMODEL 1024
#define NH     16
#define HD     64
#define MM     32
#define ROWS   (BS_*SEQ)

// ---------------- scratch (device globals) ----------------
__device__ float g_qkv[ROWS*3*DMODEL];
__device__ float g_mem[ROWS*DMODEL];
__device__ float g_hid[ROWS*DMODEL];
__device__ __nv_bfloat16 g_h1h[ROWS*DMODEL],  g_h1l[ROWS*DMODEL];
__device__ __nv_bfloat16 g_atth[ROWS*DMODEL], g_attl[ROWS*DMODEL];
__device__ __nv_bfloat16 g_h2h[ROWS*DMODEL],  g_h2l[ROWS*DMODEL];
__device__ __nv_bfloat16 g_ffh[ROWS*4*DMODEL], g_ffl[ROWS*4*DMODEL];
__device__ __nv_bfloat16 g_wqh[DMODEL*3*DMODEL], g_wql[DMODEL*3*DMODEL];
__device__ __nv_bfloat16 g_wph[DMODEL*DMODEL],   g_wpl[DMODEL*DMODEL];
__device__ __nv_bfloat16 g_wfh[DMODEL*4*DMODEL], g_wfl[DMODEL*4*DMODEL];
__device__ __nv_bfloat16 g_woh[4*DMODEL*DMODEL], g_wol[4*DMODEL*DMODEL];

// ---------------- helpers ----------------
__device__ __forceinline__ uint32_t smem_to_u32(const void* p) {
    uint32_t a;
    asm("{ .reg .u64 t; cvta.to.shared.u64 t, %1; cvt.u32.u64 %0, t; }" : "=r"(a) : "l"(p));
    return a;
}
__device__ __forceinline__ void cp16(uint32_t s, const void* g) {
    asm volatile("cp.async.cg.shared.global [%0], [%1], 16;" :: "r"(s), "l"(g));
}
#define CP_COMMIT() asm volatile("cp.async.commit_group;" ::: "memory")
#define CP_WAIT1()  asm volatile("cp.async.wait_group 1;" ::: "memory")

__device__ __forceinline__ void ldsm4(uint32_t* r, uint32_t addr) {
    asm volatile("ldmatrix.sync.aligned.m8n8.x4.shared.b16 {%0,%1,%2,%3}, [%4];"
        : "=r"(r[0]), "=r"(r[1]), "=r"(r[2]), "=r"(r[3]) : "r"(addr));
}
__device__ __forceinline__ void mma16816(float* d, const uint32_t* a, const uint32_t* b) {
    asm volatile(
      "mma.sync.aligned.m16n8k16.row.col.f32.bf16.bf16.f32 "
      "{%0,%1,%2,%3}, {%4,%5,%6,%7}, {%8,%9}, {%0,%1,%2,%3};"
      : "+f"(d[0]), "+f"(d[1]), "+f"(d[2]), "+f"(d[3])
      : "r"(a[0]), "r"(a[1]), "r"(a[2]), "r"(a[3]), "r"(b[0]), "r"(b[1]));
}

__device__ __forceinline__ float gelu_new(float x) {
    float x3 = x * x * x;
    float t  = tanhf(0.7978845608028654f * (x + 0.044715f * x3));
    return 0.5f * x * (1.f + t);
}
__device__ __forceinline__ uint32_t pack_bf2(float x, float y) {
    __nv_bfloat162 t = __floats2bfloat162_rn(x, y);
    return *reinterpret_cast<uint32_t*>(&t);
}
__device__ __forceinline__ float bf_hi(float x) {
    return __bfloat162float(__float2bfloat16(x));
}

// ---------------- prep: fused 4x weight-convert + LN1 ----------------------
// wconv: W[K,N] f32 -> hi/lo [N,K] bf16 (transpose + split), 32x32 tiles
__device__ void wconv_body(float* shm,
    const float* __restrict__ W, __nv_bfloat16* __restrict__ hi,
    __nv_bfloat16* __restrict__ lo, int K, int N, int bx, int by)
{
    float (*s)[33] = (float(*)[33])shm;
    const int tx = threadIdx.x & 31, ty = threadIdx.x >> 5;
    const int n0 = bx * 32, k0 = by * 32;
    #pragma unroll
    for (int i = 0; i < 4; i++)
        s[ty + 8*i][tx] = W[(size_t)(k0 + ty + 8*i) * N + n0 + tx];
    __syncthreads();
    #pragma unroll
    for (int i = 0; i < 4; i++) {
        int n = ty + 8*i;
        float v = s[tx][n];
        size_t o = (size_t)(n0 + n) * K + k0 + tx;
        hi[o] = __float2bfloat16(v);
        lo[o] = __float2bfloat16(v - bf_hi(v));
    }
}

__device__ void ln_body(float* shm, int row,
    const float* __restrict__ x, const float* __restrict__ g,
    const float* __restrict__ b, __nv_bfloat16* __restrict__ yh,
    __nv_bfloat16* __restrict__ yl)
{
    const int tid = threadIdx.x;
    float* rs = shm; float* rs2 = shm + 8;
    const float* xr = x + (size_t)row * DMODEL;
    float4 v = *(const float4*)(xr + tid * 4);
    float s  = v.x + v.y + v.z + v.w;
    float s2 = v.x*v.x + v.y*v.y + v.z*v.z + v.w*v.w;
    #pragma unroll
    for (int o = 16; o; o >>= 1) {
        s  += __shfl_xor_sync(0xffffffffu, s,  o);
        s2 += __shfl_xor_sync(0xffffffffu, s2, o);
    }
    const int w = tid >> 5, l = tid & 31;
    if (!l) { rs[w] = s; rs2[w] = s2; }
    __syncthreads();
    s = 0.f; s2 = 0.f;
    #pragma unroll
    for (int i = 0; i < 8; i++) { s += rs[i]; s2 += rs2[i]; }
    const float mean = s * (1.f / DMODEL);
    const float var  = s2 * (1.f / DMODEL) - mean * mean;
    const float rstd = rsqrtf(var + 1e-5f);
    const int c = tid * 4;
    float4 gg = *(const float4*)(g + c);
    float4 bb = *(const float4*)(b + c);
    float4 o;
    o.x = (v.x - mean) * rstd * gg.x + bb.x;
    o.y = (v.y - mean) * rstd * gg.y + bb.y;
    o.z = (v.z - mean) * rstd * gg.z + bb.z;
    o.w = (v.w - mean) * rstd * gg.w + bb.w;
    uint2 hh, ll;
    hh.x = pack_bf2(o.x, o.y); hh.y = pack_bf2(o.z, o.w);
    ll.x = pack_bf2(o.x - bf_hi(o.x), o.y - bf_hi(o.y));
    ll.y = pack_bf2(o.z - bf_hi(o.z), o.w - bf_hi(o.w));
    const size_t idx = (size_t)row * DMODEL + c;
    *(uint2*)(yh + idx) = hh;
    *(uint2*)(yl + idx) = ll;
}

// blocks: [0,2048) LN1 | then wconv for attnw(3072), cprw(1024), fcw(4096), pw(4096)
__global__ void __launch_bounds__(256) prep_kernel(
    const float* prev, const float* ln1g, const float* ln1b,
    __nv_bfloat16* h1h, __nv_bfloat16* h1l,
    const float* attnw, __nv_bfloat16* wqh, __nv_bfloat16* wql,
    const float* cprw,  __nv_bfloat16* wph, __nv_bfloat16* wpl,
    const float* fcw,   __nv_bfloat16* wfh, __nv_bfloat16* wfl,
    const float* pw,    __nv_bfloat16* woh, __nv_bfloat16* wol)
{
    __shared__ float shm[32*33];
    int idx = blockIdx.x;
    if (idx < 2048) { ln_body(shm, idx, prev, ln1g, ln1b, h1h, h1l); return; }
    idx -= 2048;
    if (idx < 3072) { wconv_body(shm, attnw, wqh, wql, 1024, 3072, idx % 96, idx / 96); return; }
    idx -= 3072;
    if (idx < 1024) { wconv_body(shm, cprw, wph, wpl, 1024, 1024, idx % 32, idx / 32); return; }
    idx -= 1024;
    if (idx < 4096) { wconv_body(shm, fcw, wfh, wfl, 1024, 4096, idx % 128, idx / 128); return; }
    idx -= 4096;
    wconv_body(shm, pw, woh, wol, 4096, 1024, idx % 32, idx / 32);
}

// ---------------- mma.sync bf16x3 GEMM (3-stage cp.async pipeline) ----------
// C[M,N] = A[M,K] @ B^T (B stored [N,K]); A,B as hi/lo bf16 pairs.
// CTA 128x128, 8 warps (2x4) of 64x32. K-chunk 32, 3-stage, issue-before-compute.
#define PADK    40
#define STAGE_B (128*PADK*2)            // 10240 B per array
#define GSTAGE  (4*STAGE_B)             // 40960 B per stage
#define GEMM_SMEM (3*GSTAGE)            // 122880 B

template<int EPI>
__global__ void __launch_bounds__(256) gemm_mma_kernel(
    const __nv_bfloat16* __restrict__ Ah, const __nv_bfloat16* __restrict__ Al,
    const __nv_bfloat16* __restrict__ Bh, const __nv_bfloat16* __restrict__ Bl,
    const float* __restrict__ bias,
    float* __restrict__ Cf, __nv_bfloat16* __restrict__ Ch, __nv_bfloat16* __restrict__ Cl,
    int M, int N, int K,
    const float* __restrict__ aux1, const float* __restrict__ aux2,
    const float* __restrict__ gp)
{
    extern __shared__ char smp[];
    const uint32_t sb = smem_to_u32(smp);
    const int tid = threadIdx.x;
    const int wid = tid >> 5, lane = tid & 31;
    const int wm = wid & 1, wn = wid >> 1;
    const int bm = blockIdx.y, bn = blockIdx.x;
    const int NC = K >> 5;

    const size_t Abase = (size_t)bm * 128 * K;
    const size_t Bbase = (size_t)bn * 128 * K;

    float acc[4][4][4];
    #pragma unroll
    for (int i = 0; i < 4; i++)
        #pragma unroll
        for (int j = 0; j < 4; j++)
            #pragma unroll
            for (int x = 0; x < 4; x++) acc[i][j][x] = 0.f;

    const int crow = tid >> 2;
    const int cq   = tid & 3;

    auto issue = [&](int buf, int kt) {
        const int k0 = kt << 5;
        const uint32_t sbase = sb + buf * GSTAGE;
        #pragma unroll
        for (int h = 0; h < 2; h++) {
            const int row = crow + h * 64;
            const uint32_t so = (uint32_t)(row * (PADK*2) + cq * 16);
            const size_t go = (size_t)row * K + k0 + cq * 8;
            cp16(sbase + so,               Ah + Abase + go);
            cp16(sbase + STAGE_B + so,     Al + Abase + go);
            cp16(sbase + 2*STAGE_B + so,   Bh + Bbase + go);
            cp16(sbase + 3*STAGE_B + so,   Bl + Bbase + go);
        }
    };

    issue(0, 0); CP_COMMIT();
    issue(1, 1); CP_COMMIT();

    const uint32_t aRow = (uint32_t)(wm * 64 + (lane & 15));
    const uint32_t aKb  = (uint32_t)((lane >> 4) * 16);
    const uint32_t bRow = (uint32_t)(wn * 32 + (lane & 7));
    const uint32_t bKb  = (uint32_t)((lane >> 3) * 16);
    const uint32_t aOff = aRow * (PADK*2) + aKb;
    const uint32_t bOff = bRow * (PADK*2) + bKb;

    int buf = 0;
    for (int c = 0; c < NC; c++) {
        CP_WAIT1();
        __syncthreads();
        // issue chunk c+2 into buffer (c+2)%3 BEFORE computing chunk c
        if (c + 2 < NC) {
            int nb = buf + 2; if (nb >= 3) nb -= 3;
            issue(nb, c + 2);
        }
        CP_COMMIT();

        const uint32_t s0 = sb + buf * GSTAGE;

        uint32_t bh[2][4][2], bl[2][4][2];
        #pragma unroll
        for (int nt = 0; nt < 4; nt++) {
            uint32_t r[4];
            const uint32_t ba = s0 + bOff + (uint32_t)(nt * 8 * (PADK*2));
            ldsm4(r, ba + 2*STAGE_B);
            bh[0][nt][0] = r[0]; bh[0][nt][1] = r[1];
            bh[1][nt][0] = r[2]; bh[1][nt][1] = r[3];
            ldsm4(r, ba + 3*STAGE_B);
            bl[0][nt][0] = r[0]; bl[0][nt][1] = r[1];
            bl[1][nt][0] = r[2]; bl[1][nt][1] = r[3];
        }
        #pragma unroll
        for (int ks = 0; ks < 2; ks++) {
            uint32_t ah[4][4], al[4][4];
            #pragma unroll
            for (int mt = 0; mt < 4; mt++) {
                const uint32_t aa = s0 + aOff + (uint32_t)(mt * 16 * (PADK*2) + ks * 32);
                ldsm4(ah[mt], aa);
                ldsm4(al[mt], aa + STAGE_B);
            }
            #pragma unroll
            for (int mt = 0; mt < 4; mt++)
                #pragma unroll
                for (int nt = 0; nt < 4; nt++) {
                    mma16816(acc[mt][nt], ah[mt], bh[ks][nt]);
                    mma16816(acc[mt][nt], ah[mt], bl[ks][nt]);
                    mma16816(acc[mt][nt], al[mt], bh[ks][nt]);
                }
        }
        buf++; if (buf >= 3) buf = 0;
    }

    // ---------------- epilogue ----------------
    const int r = lane >> 2, q = lane & 3;
    const float g = (EPI == 1) ? *gp : 0.f;
    #pragma unroll
    for (int mt = 0; mt < 4; mt++) {
        #pragma unroll
        for (int nt = 0; nt < 4; nt++) {
            const int col = bn * 128 + wn * 32 + nt * 8 + q * 2;
            const float2 bb = *(const float2*)(bias + col);
            #pragma unroll
            for (int hh = 0; hh < 2; hh++) {
                const int row = bm * 128 + wm * 64 + mt * 16 + r + hh * 8;
                const size_t o = (size_t)row * N + col;
                float v0 = acc[mt][nt][hh*2+0] + bb.x;
                float v1 = acc[mt][nt][hh*2+1] + bb.y;
                if (EPI == 1) {
                    float2 a1 = *(const float2*)(aux1 + o);
                    float2 a2 = *(const float2*)(aux2 + o);
                    v0 = (1.f - g) * v0 + g * a1.x + a2.x;
                    v1 = (1.f - g) * v1 + g * a1.y + a2.y;
                }
                if (EPI == 3) {
                    float2 a1 = *(const float2*)(aux1 + o);
                    v0 += a1.x; v1 += a1.y;
                }
                if (EPI == 2) {
                    v0 = gelu_new(v0); v1 = gelu_new(v1);
                    *(uint32_t*)(Ch + o) = pack_bf2(v0, v1);
                    *(uint32_t*)(Cl + o) = pack_bf2(v0 - bf_hi(v0), v1 - bf_hi(v1));
                } else {
                    *(float2*)(Cf + o) = make_float2(v0, v1);
                }
            }
        }
    }
}

// ---------------- fused attention: flash (512 blocks) + memattn (2048) ------
#define QST 65
#define FLASH_SMEM ((2 * 64 * QST + 64 * 64) * 4)

__device__ void memattn_body(const float* __restrict__ qkv,
                             const float* __restrict__ mkv,
                             float* __restrict__ outm, int row)
{
    const int tid = threadIdx.x;
    __shared__ float sc[NH * MM];
    float4 qv = *(const float4*)(qkv + (size_t)row * 3072 + tid * 4);
    qv.x *= 0.125f; qv.y *= 0.125f; qv.z *= 0.125f; qv.w *= 0.125f;
    const float* kbase = mkv + (size_t)row * MM * 2 * DMODEL;
    const int h = tid >> 4;
    #pragma unroll 4
    for (int m = 0; m < MM; m++) {
        float4 kk = *(const float4*)(kbase + (size_t)m * 2 * DMODEL + tid * 4);
        float d = qv.x * kk.x + qv.y * kk.y + qv.z * kk.z + qv.w * kk.w;
        #pragma unroll
        for (int o = 8; o; o >>= 1) d += __shfl_xor_sync(0xffffffffu, d, o);
        if ((tid & 15) == 0) sc[h * MM + m] = d;
    }
    __syncthreads();
    if (tid < NH) {
        float mx = -1e30f;
        #pragma unroll
        for (int m = 0; m < MM; m++) mx = fmaxf(mx, sc[tid * MM + m]);
        float s = 0.f;
        #pragma unroll
        for (int m = 0; m < MM; m++) {
            float e = __expf(sc[tid * MM + m] - mx);
            sc[tid * MM + m] = e; s += e;
        }
        float inv = 1.f / s;
        #pragma unroll
        for (int m = 0; m < MM; m++) sc[tid * MM + m] *= inv;
    }
    __syncthreads();
    float4 acc = make_float4(0.f, 0.f, 0.f, 0.f);
    #pragma unroll 4
    for (int m = 0; m < MM; m++) {
        float w = sc[h * MM + m];
        float4 vv = *(const float4*)(kbase + (size_t)m * 2 * DMODEL + DMODEL + tid * 4);
        acc.x += w * vv.x; acc.y += w * vv.y; acc.z += w * vv.z; acc.w += w * vv.w;
    }
    *(float4*)(outm + (size_t)row * DMODEL + tid * 4) = acc;
}

__device__ void flash_body(const float* __restrict__ qkv,
                           __nv_bfloat16* __restrict__ outh,
                           __nv_bfloat16* __restrict__ outl,
                           float* sm, int fb)
{
    float* Qs = sm;
    float* KP = sm + 64 * QST;
    float* Vs = sm + 2 * 64 * QST;
    const int tid = threadIdx.x;
    const int ty = tid >> 4, tx = tid & 15;
    const int qt = fb & 15;
    const int bh = fb >> 4;
    const int b = bh >> 4, h = bh & 15;
    const int qbase = qt * 64;
    const size_t srow = (size_t)b * SEQ;
    const int li = tid >> 2;
    const int lc0 = (tid & 3) * 4;

    {
        const float* gq = qkv + (srow + qbase + li) * (size_t)3072 + h * 64;
        #pragma unroll
        for (int u = 0; u < 4; u++) {
            const int c = lc0 + u * 16;
            float4 v = *(const float4*)(gq + c);
            Qs[li*QST+c]   = v.x * 0.125f; Qs[li*QST+c+1] = v.y * 0.125f;
            Qs[li*QST+c+2] = v.z * 0.125f; Qs[li*QST+c+3] = v.w * 0.125f;
        }
    }
    float m_i[4], l_i[4], o[4][4];
    #pragma unroll
    for (int v = 0; v < 4; v++) {
        m_i[v] = -1e30f; l_i[v] = 0.f;
        o[v][0] = o[v][1] = o[v][2] = o[v][3] = 0.f;
    }

    for (int kt = 0; kt <= qt; kt++) {
        __syncthreads();
        const int kbase = kt * 64;
        const float* gk = qkv + (srow + kbase + li) * (size_t)3072 + 1024 + h * 64;
        const float* gv = qkv + (srow + kbase + li) * (size_t)3072 + 2048 + h * 64;
        #pragma unroll
        for (int u = 0; u < 4; u++) {
            const int c = lc0 + u * 16;
            float4 kv = *(const float4*)(gk + c);
            KP[li*QST+c]   = kv.x; KP[li*QST+c+1] = kv.y;
            KP[li*QST+c+2] = kv.z; KP[li*QST+c+3] = kv.w;
            float4 vv = *(const float4*)(gv + c);
            *(float4*)&Vs[li * 64 + c] = vv;
        }
        __syncthreads();
        float s[4][4];
        #pragma unroll
        for (int v = 0; v < 4; v++) s[v][0] = s[v][1] = s[v][2] = s[v][3] = 0.f;
        #pragma unroll 8
        for (int dd = 0; dd < 64; dd++) {
            float a[4], bf[4];
            #pragma unroll
            for (int v = 0; v < 4; v++) a[v]  = Qs[(ty * 4 + v) * QST + dd];
            #pragma unroll
            for (int u = 0; u < 4; u++) bf[u] = KP[(tx * 4 + u) * QST + dd];
            #pragma unroll
            for (int v = 0; v < 4; v++)
                #pragma unroll
                for (int u = 0; u < 4; u++) s[v][u] += a[v] * bf[u];
        }
        if (kt == qt) {
            #pragma unroll
            for (int v = 0; v < 4; v++)
                #pragma unroll
                for (int u = 0; u < 4; u++)
                    if (tx * 4 + u > ty * 4 + v) s[v][u] = -1e30f;
        }
        float mnew[4], alpha[4], p[4][4], rsum[4];
        #pragma unroll
        for (int v = 0; v < 4; v++) {
            float mx = fmaxf(fmaxf(s[v][0], s[v][1]), fmaxf(s[v][2], s[v][3]));
            #pragma unroll
            for (int off = 8; off; off >>= 1)
                mx = fmaxf(mx, __shfl_xor_sync(0xffffffffu, mx, off));
            mnew[v]  = fmaxf(m_i[v], mx);
            alpha[v] = __expf(m_i[v] - mnew[v]);
            float rs = 0.f;
            #pragma unroll
            for (int u = 0; u < 4; u++) { p[v][u] = __expf(s[v][u] - mnew[v]); rs += p[v][u]; }
            #pragma unroll
            for (int off = 8; off; off >>= 1)
                rs += __shfl_xor_sync(0xffffffffu, rs, off);
            rsum[v] = rs;
        }
        #pragma unroll
        for (int v = 0; v < 4; v++) {
            l_i[v] = alpha[v] * l_i[v] + rsum[v];
            m_i[v] = mnew[v];
            o[v][0] *= alpha[v]; o[v][1] *= alpha[v]; o[v][2] *= alpha[v]; o[v][3] *= alpha[v];
        }
        __syncthreads();
        #pragma unroll
        for (int v = 0; v < 4; v++)
            #pragma unroll
            for (int u = 0; u < 4; u++)
                KP[(ty * 4 + v) * QST + tx * 4 + u] = p[v][u];
        __syncthreads();
        #pragma unroll 4
        for (int jj = 0; jj < 64; jj++) {
            float4 bv = *(const float4*)&Vs[jj * 64 + tx * 4];
            #pragma unroll
            for (int v = 0; v < 4; v++) {
                float a = KP[(ty * 4 + v) * QST + jj];
                o[v][0] += a * bv.x; o[v][1] += a * bv.y;
                o[v][2] += a * bv.z; o[v][3] += a * bv.w;
            }
        }
    }
    #pragma unroll
    for (int v = 0; v < 4; v++) {
        const float inv = 1.f / l_i[v];
        const int qi = qbase + ty * 4 + v;
        float4 ov = make_float4(o[v][0]*inv, o[v][1]*inv, o[v][2]*inv, o[v][3]*inv);
        uint2 hh, ll;
        hh.x = pack_bf2(ov.x, ov.y); hh.y = pack_bf2(ov.z, ov.w);
        ll.x = pack_bf2(ov.x - bf_hi(ov.x), ov.y - bf_hi(ov.y));
        ll.y = pack_bf2(ov.z - bf_hi(ov.z), ov.w - bf_hi(ov.w));
        const size_t oo = (srow + qi) * (size_t)DMODEL + h * 64 + tx * 4;
        *(uint2*)(outh + oo) = hh;
        *(uint2*)(outl + oo) = ll;
    }
}

__global__ void __launch_bounds__(256) attn_kernel(
    const float* __restrict__ qkv, const float* __restrict__ mkv,
    float* __restrict__ outm,
    __nv_bfloat16* __restrict__ outh, __nv_bfloat16* __restrict__ outl)
{
    extern __shared__ float sm[];
    if (blockIdx.x < 512) {
        flash_body(qkv, outh, outl, sm, blockIdx.x);
    } else {
        memattn_body(qkv, mkv, outm, blockIdx.x - 512);
    }
}

// ------------------------------ launcher ------------------------------------
extern "C" void kernel_launch(void* const* d_in, const int* in_sizes, int n_in,
                              void* d_out, int out_size)
{
    (void)in_sizes; (void)n_in; (void)out_size;
    const float* prev  = (const float*)d_in[0];
    const float* memkv = (const float*)d_in[1];
    const float* gval  = (const float*)d_in[2];
    const float* ln1g  = (const float*)d_in[3];
    const float* ln1b  = (const float*)d_in[4];
    const float* attnw = (const float*)d_in[5];
    const float* attnb = (const float*)d_in[6];
    const float* cprw  = (const float*)d_in[7];
    const float* cprb  = (const float*)d_in[8];
    const float* ln2g  = (const float*)d_in[9];
    const float* ln2b  = (const float*)d_in[10];
    const float* fcw   = (const float*)d_in[11];
    const float* fcb   = (const float*)d_in[12];
    const float* pw    = (const float*)d_in[13];
    const float* pb    = (const float*)d_in[14];
    float* out = (float*)d_out;

    float *qkv, *mem, *hid;
    __nv_bfloat16 *h1h, *h1l, *atth, *attl, *h2h, *h2l, *ffh, *ffl;
    __nv_bfloat16 *wqh, *wql, *wph, *wpl, *wfh, *wfl, *woh, *wol;
    cudaGetSymbolAddress((void**)&qkv, g_qkv);
    cudaGetSymbolAddress((void**)&mem, g_mem);
    cudaGetSymbolAddress((void**)&hid, g_hid);
    cudaGetSymbolAddress((void**)&h1h, g_h1h);  cudaGetSymbolAddress((void**)&h1l, g_h1l);
    cudaGetSymbolAddress((void**)&atth, g_atth); cudaGetSymbolAddress((void**)&attl, g_attl);
    cudaGetSymbolAddress((void**)&h2h, g_h2h);  cudaGetSymbolAddress((void**)&h2l, g_h2l);
    cudaGetSymbolAddress((void**)&ffh, g_ffh);  cudaGetSymbolAddress((void**)&ffl, g_ffl);
    cudaGetSymbolAddress((void**)&wqh, g_wqh);  cudaGetSymbolAddress((void**)&wql, g_wql);
    cudaGetSymbolAddress((void**)&wph, g_wph);  cudaGetSymbolAddress((void**)&wpl, g_wpl);
    cudaGetSymbolAddress((void**)&wfh, g_wfh);  cudaGetSymbolAddress((void**)&wfl, g_wfl);
    cudaGetSymbolAddress((void**)&woh, g_woh);  cudaGetSymbolAddress((void**)&wol, g_wol);

    cudaFuncSetAttribute(attn_kernel, cudaFuncAttributeMaxDynamicSharedMemorySize, FLASH_SMEM);
    cudaFuncSetAttribute(gemm_mma_kernel<0>, cudaFuncAttributeMaxDynamicSharedMemorySize, GEMM_SMEM);
    cudaFuncSetAttribute(gemm_mma_kernel<1>, cudaFuncAttributeMaxDynamicSharedMemorySize, GEMM_SMEM);
    cudaFuncSetAttribute(gemm_mma_kernel<2>, cudaFuncAttributeMaxDynamicSharedMemorySize, GEMM_SMEM);
    cudaFuncSetAttribute(gemm_mma_kernel<3>, cudaFuncAttributeMaxDynamicSharedMemorySize, GEMM_SMEM);

    // 1) prep: LN1 + all weight converts (fused, overlapped)
    prep_kernel<<<14336, 256>>>(prev, ln1g, ln1b, h1h, h1l,
        attnw, wqh, wql, cprw, wph, wpl, fcw, wfh, wfl, pw, woh, wol);
    // 2) qkv = h1 @ c_attn + b (f32)
    gemm_mma_kernel<0><<<dim3(24, 16), 256, GEMM_SMEM>>>(h1h, h1l, wqh, wql, attnb,
        qkv, nullptr, nullptr, ROWS, 3*DMODEL, DMODEL, nullptr, nullptr, nullptr);
    // 3) fused flash + memattn (overlapped compute/HBM)
    attn_kernel<<<512 + 2048, 256, FLASH_SMEM>>>(qkv, memkv, mem, atth, attl);
    // 4) hid = (1-g)*(att@c_proj+b) + g*mem + prev
    gemm_mma_kernel<1><<<dim3(8, 16), 256, GEMM_SMEM>>>(atth, attl, wph, wpl, cprb,
        hid, nullptr, nullptr, ROWS, DMODEL, DMODEL, mem, prev, gval);
    // 5) LN2 -> h2 hi/lo
    prep_kernel<<<2048, 256>>>(hid, ln2g, ln2b, h2h, h2l,
        nullptr, nullptr, nullptr, nullptr, nullptr, nullptr,
        nullptr, nullptr, nullptr, nullptr, nullptr, nullptr);
    // 6) ff = gelu(h2 @ fc + b) -> hi/lo
    gemm_mma_kernel<2><<<dim3(32, 16), 256, GEMM_SMEM>>>(h2h, h2l, wfh, wfl, fcb,
        nullptr, ffh, ffl, ROWS, 4*DMODEL, DMODEL, nullptr, nullptr, nullptr);
    // 7) out = ff @ proj + b + hid
    gemm_mma_kernel<3><<<dim3(8, 16), 256, GEMM_SMEM>>>(ffh, ffl, woh, wol, pb,
        out, nullptr, nullptr, ROWS, DMODEL, 4*DMODEL, hid, nullptr, nullptr);
}

// round 6
// speedup vs baseline: 1.7821x; 1.7821x over previous
#include <cuda_runtime.h>
#include <cuda_bf16.h>
#include <cstdint>

#define BS_    2
#define SEQ    1024
#define DMODEL 1024
#define NH     16
#define HD     64
#define MM     32
#define ROWS   (BS_*SEQ)

// ---------------- scratch (device globals) ----------------
__device__ float g_qkv[ROWS*3*DMODEL];
__device__ float g_mem[ROWS*DMODEL];
__device__ float g_hid[ROWS*DMODEL];
__device__ __nv_bfloat16 g_h1h[ROWS*DMODEL],  g_h1l[ROWS*DMODEL];
__device__ __nv_bfloat16 g_atth[ROWS*DMODEL], g_attl[ROWS*DMODEL];
__device__ __nv_bfloat16 g_h2h[ROWS*DMODEL],  g_h2l[ROWS*DMODEL];
__device__ __nv_bfloat16 g_ffh[ROWS*4*DMODEL], g_ffl[ROWS*4*DMODEL];
__device__ __nv_bfloat16 g_wqh[DMODEL*3*DMODEL], g_wql[DMODEL*3*DMODEL];
__device__ __nv_bfloat16 g_wph[DMODEL*DMODEL],   g_wpl[DMODEL*DMODEL];
__device__ __nv_bfloat16 g_wfh[DMODEL*4*DMODEL], g_wfl[DMODEL*4*DMODEL];
__device__ __nv_bfloat16 g_woh[4*DMODEL*DMODEL], g_wol[4*DMODEL*DMODEL];

// ---------------- helpers ----------------
__device__ __forceinline__ uint32_t smem_to_u32(const void* p) {
    uint32_t a;
    asm("{ .reg .u64 t; cvta.to.shared.u64 t, %1; cvt.u32.u64 %0, t; }" : "=r"(a) : "l"(p));
    return a;
}
__device__ __forceinline__ void cp16(uint32_t s, const void* g) {
    asm volatile("cp.async.cg.shared.global [%0], [%1], 16;" :: "r"(s), "l"(g));
}
#define CP_COMMIT() asm volatile("cp.async.commit_group;" ::: "memory")
#define CP_WAIT1()  asm volatile("cp.async.wait_group 1;" ::: "memory")

__device__ __forceinline__ void ldsm4(uint32_t* r, uint32_t addr) {
    asm volatile("ldmatrix.sync.aligned.m8n8.x4.shared.b16 {%0,%1,%2,%3}, [%4];"
        : "=r"(r[0]), "=r"(r[1]), "=r"(r[2]), "=r"(r[3]) : "r"(addr));
}
__device__ __forceinline__ void ldsm2(uint32_t* r, uint32_t addr) {
    asm volatile("ldmatrix.sync.aligned.m8n8.x2.shared.b16 {%0,%1}, [%2];"
        : "=r"(r[0]), "=r"(r[1]) : "r"(addr));
}
__device__ __forceinline__ void mma16816(float* d, const uint32_t* a, const uint32_t* b) {
    asm volatile(
      "mma.sync.aligned.m16n8k16.row.col.f32.bf16.bf16.f32 "
      "{%0,%1,%2,%3}, {%4,%5,%6,%7}, {%8,%9}, {%0,%1,%2,%3};"
      : "+f"(d[0]), "+f"(d[1]), "+f"(d[2]), "+f"(d[3])
      : "r"(a[0]), "r"(a[1]), "r"(a[2]), "r"(a[3]), "r"(b[0]), "r"(b[1]));
}

__device__ __forceinline__ float gelu_new(float x) {
    float x3 = x * x * x;
    float t  = tanhf(0.7978845608028654f * (x + 0.044715f * x3));
    return 0.5f * x * (1.f + t);
}
__device__ __forceinline__ uint32_t pack_bf2(float x, float y) {
    __nv_bfloat162 t = __floats2bfloat162_rn(x, y);
    return *reinterpret_cast<uint32_t*>(&t);
}
__device__ __forceinline__ float bf_hi(float x) {
    return __bfloat162float(__float2bfloat16(x));
}

// ---------------- prep: fused 4x weight-convert + LN -----------------------
__device__ void wconv_body(float* shm,
    const float* __restrict__ W, __nv_bfloat16* __restrict__ hi,
    __nv_bfloat16* __restrict__ lo, int K, int N, int bx, int by)
{
    float (*s)[33] = (float(*)[33])shm;
    const int tx = threadIdx.x & 31, ty = threadIdx.x >> 5;
    const int n0 = bx * 32, k0 = by * 32;
    #pragma unroll
    for (int i = 0; i < 4; i++)
        s[ty + 8*i][tx] = W[(size_t)(k0 + ty + 8*i) * N + n0 + tx];
    __syncthreads();
    #pragma unroll
    for (int i = 0; i < 4; i++) {
        int n = ty + 8*i;
        float v = s[tx][n];
        size_t o = (size_t)(n0 + n) * K + k0 + tx;
        hi[o] = __float2bfloat16(v);
        lo[o] = __float2bfloat16(v - bf_hi(v));
    }
}

__device__ void ln_body(float* shm, int row,
    const float* __restrict__ x, const float* __restrict__ g,
    const float* __restrict__ b, __nv_bfloat16* __restrict__ yh,
    __nv_bfloat16* __restrict__ yl)
{
    const int tid = threadIdx.x;
    float* rs = shm; float* rs2 = shm + 8;
    const float* xr = x + (size_t)row * DMODEL;
    float4 v = *(const float4*)(xr + tid * 4);
    float s  = v.x + v.y + v.z + v.w;
    float s2 = v.x*v.x + v.y*v.y + v.z*v.z + v.w*v.w;
    #pragma unroll
    for (int o = 16; o; o >>= 1) {
        s  += __shfl_xor_sync(0xffffffffu, s,  o);
        s2 += __shfl_xor_sync(0xffffffffu, s2, o);
    }
    const int w = tid >> 5, l = tid & 31;
    if (!l) { rs[w] = s; rs2[w] = s2; }
    __syncthreads();
    s = 0.f; s2 = 0.f;
    #pragma unroll
    for (int i = 0; i < 8; i++) { s += rs[i]; s2 += rs2[i]; }
    const float mean = s * (1.f / DMODEL);
    const float var  = s2 * (1.f / DMODEL) - mean * mean;
    const float rstd = rsqrtf(var + 1e-5f);
    const int c = tid * 4;
    float4 gg = *(const float4*)(g + c);
    float4 bb = *(const float4*)(b + c);
    float4 o;
    o.x = (v.x - mean) * rstd * gg.x + bb.x;
    o.y = (v.y - mean) * rstd * gg.y + bb.y;
    o.z = (v.z - mean) * rstd * gg.z + bb.z;
    o.w = (v.w - mean) * rstd * gg.w + bb.w;
    uint2 hh, ll;
    hh.x = pack_bf2(o.x, o.y); hh.y = pack_bf2(o.z, o.w);
    ll.x = pack_bf2(o.x - bf_hi(o.x), o.y - bf_hi(o.y));
    ll.y = pack_bf2(o.z - bf_hi(o.z), o.w - bf_hi(o.w));
    const size_t idx = (size_t)row * DMODEL + c;
    *(uint2*)(yh + idx) = hh;
    *(uint2*)(yl + idx) = ll;
}

__global__ void __launch_bounds__(256) prep_kernel(
    const float* prev, const float* ln1g, const float* ln1b,
    __nv_bfloat16* h1h, __nv_bfloat16* h1l,
    const float* attnw, __nv_bfloat16* wqh, __nv_bfloat16* wql,
    const float* cprw,  __nv_bfloat16* wph, __nv_bfloat16* wpl,
    const float* fcw,   __nv_bfloat16* wfh, __nv_bfloat16* wfl,
    const float* pw,    __nv_bfloat16* woh, __nv_bfloat16* wol)
{
    __shared__ float shm[32*33];
    int idx = blockIdx.x;
    if (idx < 2048) { ln_body(shm, idx, prev, ln1g, ln1b, h1h, h1l); return; }
    idx -= 2048;
    if (idx < 3072) { wconv_body(shm, attnw, wqh, wql, 1024, 3072, idx % 96, idx / 96); return; }
    idx -= 3072;
    if (idx < 1024) { wconv_body(shm, cprw, wph, wpl, 1024, 1024, idx % 32, idx / 32); return; }
    idx -= 1024;
    if (idx < 4096) { wconv_body(shm, fcw, wfh, wfl, 1024, 4096, idx % 128, idx / 128); return; }
    idx -= 4096;
    wconv_body(shm, pw, woh, wol, 4096, 1024, idx % 32, idx / 32);
}

// ---------------- mma.sync bf16x3 GEMM, swizzled 64B rows, 3-stage ----------
// Stage: Ah|Al|Bh|Bl each 128 rows x 64B = 8192B -> 32KB/stage, 3 stages = 96KB.
// 2 CTAs/SM (launch_bounds(256,2)); 8 warps (2x4) of 64x32.
// Swizzle: phys = row*64 + ((q ^ (row&3))<<4), q = 16B quarter index.
#define AB_     8192
#define GSTAGE  (4*AB_)                 // 32768
#define GEMM_SMEM (3*GSTAGE)            // 98304

template<int EPI>
__global__ void __launch_bounds__(256, 2) gemm_mma_kernel(
    const __nv_bfloat16* __restrict__ Ah, const __nv_bfloat16* __restrict__ Al,
    const __nv_bfloat16* __restrict__ Bh, const __nv_bfloat16* __restrict__ Bl,
    const float* __restrict__ bias,
    float* __restrict__ Cf, __nv_bfloat16* __restrict__ Ch, __nv_bfloat16* __restrict__ Cl,
    int M, int N, int K,
    const float* __restrict__ aux1, const float* __restrict__ aux2,
    const float* __restrict__ gp)
{
    extern __shared__ char smp[];
    const uint32_t sb = smem_to_u32(smp);
    const int tid = threadIdx.x;
    const int wid = tid >> 5, lane = tid & 31;
    const int wm = wid & 1, wn = wid >> 1;
    const int bm = blockIdx.y, bn = blockIdx.x;
    const int NC = K >> 5;

    const size_t Abase = (size_t)bm * 128 * K;
    const size_t Bbase = (size_t)bn * 128 * K;

    float acc[4][4][4];
    #pragma unroll
    for (int i = 0; i < 4; i++)
        #pragma unroll
        for (int j = 0; j < 4; j++)
            #pragma unroll
            for (int x = 0; x < 4; x++) acc[i][j][x] = 0.f;

    // cp.async: thread -> rows {crow, crow+64}, 16B quarter cq, swizzled
    const int crow = tid >> 2;
    const int cq   = tid & 3;
    const uint32_t so0 = (uint32_t)(crow * 64 + ((cq ^ (crow & 3)) << 4));
    const uint32_t so1 = so0 + 64 * 64;     // (crow+64)&3 == crow&3

    auto issue = [&](int buf, int kt) {
        const int k0 = kt << 5;
        const uint32_t sbase = sb + buf * GSTAGE;
        const size_t g0 = (size_t)crow * K + k0 + cq * 8;
        const size_t g1 = g0 + (size_t)64 * K;
        cp16(sbase + so0,          Ah + Abase + g0);
        cp16(sbase + so1,          Ah + Abase + g1);
        cp16(sbase + AB_ + so0,    Al + Abase + g0);
        cp16(sbase + AB_ + so1,    Al + Abase + g1);
        cp16(sbase + 2*AB_ + so0,  Bh + Bbase + g0);
        cp16(sbase + 2*AB_ + so1,  Bh + Bbase + g1);
        cp16(sbase + 3*AB_ + so0,  Bl + Bbase + g0);
        cp16(sbase + 3*AB_ + so1,  Bl + Bbase + g1);
    };

    issue(0, 0); CP_COMMIT();
    issue(1, 1); CP_COMMIT();

    // ldmatrix lane constants
    const uint32_t rowA = (uint32_t)(wm * 64 + (lane & 15));
    const uint32_t qa   = (uint32_t)(lane >> 4);        // 0,1
    const uint32_t r3a  = rowA & 3;
    const uint32_t aBase = rowA * 64;
    const uint32_t rowB = (uint32_t)(wn * 32 + (lane & 7));
    const uint32_t qb   = (uint32_t)((lane >> 3) & 1);  // 0,1 (x2 uses lanes 0-15)
    const uint32_t r3b  = rowB & 3;
    const uint32_t bBase = rowB * 64;

    int buf = 0;
    for (int c = 0; c < NC; c++) {
        CP_WAIT1();
        __syncthreads();
        if (c + 2 < NC) { int nb = buf + 2; if (nb >= 3) nb -= 3; issue(nb, c + 2); }
        CP_COMMIT();

        const uint32_t s0 = sb + buf * GSTAGE;
        #pragma unroll
        for (int ks = 0; ks < 2; ks++) {
            uint32_t bh[4][2], bl[4][2];
            const uint32_t qpb = ((qb + 2*ks) ^ r3b) << 4;
            #pragma unroll
            for (int nt = 0; nt < 4; nt++) {
                const uint32_t ba = s0 + bBase + (uint32_t)(nt * 512) + qpb;
                ldsm2(bh[nt], ba + 2*AB_);
                ldsm2(bl[nt], ba + 3*AB_);
            }
            const uint32_t qpa = ((qa + 2*ks) ^ r3a) << 4;
            #pragma unroll
            for (int mt = 0; mt < 4; mt++) {
                uint32_t ah[4], al[4];
                const uint32_t aa = s0 + aBase + (uint32_t)(mt * 1024) + qpa;
                ldsm4(ah, aa);
                ldsm4(al, aa + AB_);
                #pragma unroll
                for (int nt = 0; nt < 4; nt++) {
                    mma16816(acc[mt][nt], ah, bh[nt]);
                    mma16816(acc[mt][nt], ah, bl[nt]);
                    mma16816(acc[mt][nt], al, bh[nt]);
                }
            }
        }
        buf++; if (buf >= 3) buf = 0;
    }

    // ---------------- epilogue ----------------
    const int r = lane >> 2, q = lane & 3;
    const float g = (EPI == 1) ? *gp : 0.f;
    #pragma unroll
    for (int mt = 0; mt < 4; mt++) {
        #pragma unroll
        for (int nt = 0; nt < 4; nt++) {
            const int col = bn * 128 + wn * 32 + nt * 8 + q * 2;
            const float2 bb = *(const float2*)(bias + col);
            #pragma unroll
            for (int hh = 0; hh < 2; hh++) {
                const int row = bm * 128 + wm * 64 + mt * 16 + r + hh * 8;
                const size_t o = (size_t)row * N + col;
                float v0 = acc[mt][nt][hh*2+0] + bb.x;
                float v1 = acc[mt][nt][hh*2+1] + bb.y;
                if (EPI == 1) {
                    float2 a1 = *(const float2*)(aux1 + o);
                    float2 a2 = *(const float2*)(aux2 + o);
                    v0 = (1.f - g) * v0 + g * a1.x + a2.x;
                    v1 = (1.f - g) * v1 + g * a1.y + a2.y;
                }
                if (EPI == 3) {
                    float2 a1 = *(const float2*)(aux1 + o);
                    v0 += a1.x; v1 += a1.y;
                }
                if (EPI == 2) {
                    v0 = gelu_new(v0); v1 = gelu_new(v1);
                    *(uint32_t*)(Ch + o) = pack_bf2(v0, v1);
                    *(uint32_t*)(Cl + o) = pack_bf2(v0 - bf_hi(v0), v1 - bf_hi(v1));
                } else {
                    *(float2*)(Cf + o) = make_float2(v0, v1);
                }
            }
        }
    }
}

// ---------------- fused attention: flash (512 blocks) + memattn (2048) ------
#define QST 65
#define FLASH_SMEM ((2 * 64 * QST + 64 * 64) * 4)

__device__ void memattn_body(const float* __restrict__ qkv,
                             const float* __restrict__ mkv,
                             float* __restrict__ outm, int row)
{
    const int tid = threadIdx.x;
    __shared__ float sc[NH * MM];
    float4 qv = *(const float4*)(qkv + (size_t)row * 3072 + tid * 4);
    qv.x *= 0.125f; qv.y *= 0.125f; qv.z *= 0.125f; qv.w *= 0.125f;
    const float* kbase = mkv + (size_t)row * MM * 2 * DMODEL;
    const int h = tid >> 4;
    #pragma unroll 4
    for (int m = 0; m < MM; m++) {
        float4 kk = *(const float4*)(kbase + (size_t)m * 2 * DMODEL + tid * 4);
        float d = qv.x * kk.x + qv.y * kk.y + qv.z * kk.z + qv.w * kk.w;
        #pragma unroll
        for (int o = 8; o; o >>= 1) d += __shfl_xor_sync(0xffffffffu, d, o);
        if ((tid & 15) == 0) sc[h * MM + m] = d;
    }
    __syncthreads();
    if (tid < NH) {
        float mx = -1e30f;
        #pragma unroll
        for (int m = 0; m < MM; m++) mx = fmaxf(mx, sc[tid * MM + m]);
        float s = 0.f;
        #pragma unroll
        for (int m = 0; m < MM; m++) {
            float e = __expf(sc[tid * MM + m] - mx);
            sc[tid * MM + m] = e; s += e;
        }
        float inv = 1.f / s;
        #pragma unroll
        for (int m = 0; m < MM; m++) sc[tid * MM + m] *= inv;
    }
    __syncthreads();
    float4 acc = make_float4(0.f, 0.f, 0.f, 0.f);
    #pragma unroll 4
    for (int m = 0; m < MM; m++) {
        float w = sc[h * MM + m];
        float4 vv = *(const float4*)(kbase + (size_t)m * 2 * DMODEL + DMODEL + tid * 4);
        acc.x += w * vv.x; acc.y += w * vv.y; acc.z += w * vv.z; acc.w += w * vv.w;
    }
    *(float4*)(outm + (size_t)row * DMODEL + tid * 4) = acc;
}

__device__ void flash_body(const float* __restrict__ qkv,
                           __nv_bfloat16* __restrict__ outh,
                           __nv_bfloat16* __restrict__ outl,
                           float* sm, int fb)
{
    float* Qs = sm;
    float* KP = sm + 64 * QST;
    float* Vs = sm + 2 * 64 * QST;
    const int tid = threadIdx.x;
    const int ty = tid >> 4, tx = tid & 15;
    const int qt = fb & 15;
    const int bh = fb >> 4;
    const int b = bh >> 4, h = bh & 15;
    const int qbase = qt * 64;
    const size_t srow = (size_t)b * SEQ;
    const int li = tid >> 2;
    const int lc0 = (tid & 3) * 4;

    {
        const float* gq = qkv + (srow + qbase + li) * (size_t)3072 + h * 64;
        #pragma unroll
        for (int u = 0; u < 4; u++) {
            const int c = lc0 + u * 16;
            float4 v = *(const float4*)(gq + c);
            Qs[li*QST+c]   = v.x * 0.125f; Qs[li*QST+c+1] = v.y * 0.125f;
            Qs[li*QST+c+2] = v.z * 0.125f; Qs[li*QST+c+3] = v.w * 0.125f;
        }
    }
    float m_i[4], l_i[4], o[4][4];
    #pragma unroll
    for (int v = 0; v < 4; v++) {
        m_i[v] = -1e30f; l_i[v] = 0.f;
        o[v][0] = o[v][1] = o[v][2] = o[v][3] = 0.f;
    }

    for (int kt = 0; kt <= qt; kt++) {
        __syncthreads();
        const int kbase = kt * 64;
        const float* gk = qkv + (srow + kbase + li) * (size_t)3072 + 1024 + h * 64;
        const float* gv = qkv + (srow + kbase + li) * (size_t)3072 + 2048 + h * 64;
        #pragma unroll
        for (int u = 0; u < 4; u++) {
            const int c = lc0 + u * 16;
            float4 kv = *(const float4*)(gk + c);
            KP[li*QST+c]   = kv.x; KP[li*QST+c+1] = kv.y;
            KP[li*QST+c+2] = kv.z; KP[li*QST+c+3] = kv.w;
            float4 vv = *(const float4*)(gv + c);
            *(float4*)&Vs[li * 64 + c] = vv;
        }
        __syncthreads();
        float s[4][4];
        #pragma unroll
        for (int v = 0; v < 4; v++) s[v][0] = s[v][1] = s[v][2] = s[v][3] = 0.f;
        #pragma unroll 8
        for (int dd = 0; dd < 64; dd++) {
            float a[4], bf[4];
            #pragma unroll
            for (int v = 0; v < 4; v++) a[v]  = Qs[(ty * 4 + v) * QST + dd];
            #pragma unroll
            for (int u = 0; u < 4; u++) bf[u] = KP[(tx * 4 + u) * QST + dd];
            #pragma unroll
            for (int v = 0; v < 4; v++)
                #pragma unroll
                for (int u = 0; u < 4; u++) s[v][u] += a[v] * bf[u];
        }
        if (kt == qt) {
            #pragma unroll
            for (int v = 0; v < 4; v++)
                #pragma unroll
                for (int u = 0; u < 4; u++)
                    if (tx * 4 + u > ty * 4 + v) s[v][u] = -1e30f;
        }
        float mnew[4], alpha[4], p[4][4], rsum[4];
        #pragma unroll
        for (int v = 0; v < 4; v++) {
            float mx = fmaxf(fmaxf(s[v][0], s[v][1]), fmaxf(s[v][2], s[v][3]));
            #pragma unroll
            for (int off = 8; off; off >>= 1)
                mx = fmaxf(mx, __shfl_xor_sync(0xffffffffu, mx, off));
            mnew[v]  = fmaxf(m_i[v], mx);
            alpha[v] = __expf(m_i[v] - mnew[v]);
            float rs = 0.f;
            #pragma unroll
            for (int u = 0; u < 4; u++) { p[v][u] = __expf(s[v][u] - mnew[v]); rs += p[v][u]; }
            #pragma unroll
            for (int off = 8; off; off >>= 1)
                rs += __shfl_xor_sync(0xffffffffu, rs, off);
            rsum[v] = rs;
        }
        #pragma unroll
        for (int v = 0; v < 4; v++) {
            l_i[v] = alpha[v] * l_i[v] + rsum[v];
            m_i[v] = mnew[v];
            o[v][0] *= alpha[v]; o[v][1] *= alpha[v]; o[v][2] *= alpha[v]; o[v][3] *= alpha[v];
        }
        __syncthreads();
        #pragma unroll
        for (int v = 0; v < 4; v++)
            #pragma unroll
            for (int u = 0; u < 4; u++)
                KP[(ty * 4 + v) * QST + tx * 4 + u] = p[v][u];
        __syncthreads();
        #pragma unroll 4
        for (int jj = 0; jj < 64; jj++) {
            float4 bv = *(const float4*)&Vs[jj * 64 + tx * 4];
            #pragma unroll
            for (int v = 0; v < 4; v++) {
                float a = KP[(ty * 4 + v) * QST + jj];
                o[v][0] += a * bv.x; o[v][1] += a * bv.y;
                o[v][2] += a * bv.z; o[v][3] += a * bv.w;
            }
        }
    }
    #pragma unroll
    for (int v = 0; v < 4; v++) {
        const float inv = 1.f / l_i[v];
        const int qi = qbase + ty * 4 + v;
        float4 ov = make_float4(o[v][0]*inv, o[v][1]*inv, o[v][2]*inv, o[v][3]*inv);
        uint2 hh, ll;
        hh.x = pack_bf2(ov.x, ov.y); hh.y = pack_bf2(ov.z, ov.w);
        ll.x = pack_bf2(ov.x - bf_hi(ov.x), ov.y - bf_hi(ov.y));
        ll.y = pack_bf2(ov.z - bf_hi(ov.z), ov.w - bf_hi(ov.w));
        const size_t oo = (srow + qi) * (size_t)DMODEL + h * 64 + tx * 4;
        *(uint2*)(outh + oo) = hh;
        *(uint2*)(outl + oo) = ll;
    }
}

__global__ void __launch_bounds__(256) attn_kernel(
    const float* __restrict__ qkv, const float* __restrict__ mkv,
    float* __restrict__ outm,
    __nv_bfloat16* __restrict__ outh, __nv_bfloat16* __restrict__ outl)
{
    extern __shared__ float sm[];
    if (blockIdx.x < 512) {
        flash_body(qkv, outh, outl, sm, blockIdx.x);
    } else {
        memattn_body(qkv, mkv, outm, blockIdx.x - 512);
    }
}

// ------------------------------ launcher ------------------------------------
extern "C" void kernel_launch(void* const* d_in, const int* in_sizes, int n_in,
                              void* d_out, int out_size)
{
    (void)in_sizes; (void)n_in; (void)out_size;
    const float* prev  = (const float*)d_in[0];
    const float* memkv = (const float*)d_in[1];
    const float* gval  = (const float*)d_in[2];
    const float* ln1g  = (const float*)d_in[3];
    const float* ln1b  = (const float*)d_in[4];
    const float* attnw = (const float*)d_in[5];
    const float* attnb = (const float*)d_in[6];
    const float* cprw  = (const float*)d_in[7];
    const float* cprb  = (const float*)d_in[8];
    const float* ln2g  = (const float*)d_in[9];
    const float* ln2b  = (const float*)d_in[10];
    const float* fcw   = (const float*)d_in[11];
    const float* fcb   = (const float*)d_in[12];
    const float* pw    = (const float*)d_in[13];
    const float* pb    = (const float*)d_in[14];
    float* out = (float*)d_out;

    float *qkv, *mem, *hid;
    __nv_bfloat16 *h1h, *h1l, *atth, *attl, *h2h, *h2l, *ffh, *ffl;
    __nv_bfloat16 *wqh, *wql, *wph, *wpl, *wfh, *wfl, *woh, *wol;
    cudaGetSymbolAddress((void**)&qkv, g_qkv);
    cudaGetSymbolAddress((void**)&mem, g_mem);
    cudaGetSymbolAddress((void**)&hid, g_hid);
    cudaGetSymbolAddress((void**)&h1h, g_h1h);  cudaGetSymbolAddress((void**)&h1l, g_h1l);
    cudaGetSymbolAddress((void**)&atth, g_atth); cudaGetSymbolAddress((void**)&attl, g_attl);
    cudaGetSymbolAddress((void**)&h2h, g_h2h);  cudaGetSymbolAddress((void**)&h2l, g_h2l);
    cudaGetSymbolAddress((void**)&ffh, g_ffh);  cudaGetSymbolAddress((void**)&ffl, g_ffl);
    cudaGetSymbolAddress((void**)&wqh, g_wqh);  cudaGetSymbolAddress((void**)&wql, g_wql);
    cudaGetSymbolAddress((void**)&wph, g_wph);  cudaGetSymbolAddress((void**)&wpl, g_wpl);
    cudaGetSymbolAddress((void**)&wfh, g_wfh);  cudaGetSymbolAddress((void**)&wfl, g_wfl);
    cudaGetSymbolAddress((void**)&woh, g_woh);  cudaGetSymbolAddress((void**)&wol, g_wol);

    cudaFuncSetAttribute(attn_kernel, cudaFuncAttributeMaxDynamicSharedMemorySize, FLASH_SMEM);
    cudaFuncSetAttribute(gemm_mma_kernel<0>, cudaFuncAttributeMaxDynamicSharedMemorySize, GEMM_SMEM);
    cudaFuncSetAttribute(gemm_mma_kernel<1>, cudaFuncAttributeMaxDynamicSharedMemorySize, GEMM_SMEM);
    cudaFuncSetAttribute(gemm_mma_kernel<2>, cudaFuncAttributeMaxDynamicSharedMemorySize, GEMM_SMEM);
    cudaFuncSetAttribute(gemm_mma_kernel<3>, cudaFuncAttributeMaxDynamicSharedMemorySize, GEMM_SMEM);

    // 1) prep: LN1 + all weight converts (fused)
    prep_kernel<<<14336, 256>>>(prev, ln1g, ln1b, h1h, h1l,
        attnw, wqh, wql, cprw, wph, wpl, fcw, wfh, wfl, pw, woh, wol);
    // 2) qkv = h1 @ c_attn + b (f32)
    gemm_mma_kernel<0><<<dim3(24, 16), 256, GEMM_SMEM>>>(h1h, h1l, wqh, wql, attnb,
        qkv, nullptr, nullptr, ROWS, 3*DMODEL, DMODEL, nullptr, nullptr, nullptr);
    // 3) fused flash + memattn
    attn_kernel<<<512 + 2048, 256, FLASH_SMEM>>>(qkv, memkv, mem, atth, attl);
    // 4) hid = (1-g)*(att@c_proj+b) + g*mem + prev
    gemm_mma_kernel<1><<<dim3(8, 16), 256, GEMM_SMEM>>>(atth, attl, wph, wpl, cprb,
        hid, nullptr, nullptr, ROWS, DMODEL, DMODEL, mem, prev, gval);
    // 5) LN2 -> h2 hi/lo
    prep_kernel<<<2048, 256>>>(hid, ln2g, ln2b, h2h, h2l,
        nullptr, nullptr, nullptr, nullptr, nullptr, nullptr,
        nullptr, nullptr, nullptr, nullptr, nullptr, nullptr);
    // 6) ff = gelu(h2 @ fc + b) -> hi/lo
    gemm_mma_kernel<2><<<dim3(32, 16), 256, GEMM_SMEM>>>(h2h, h2l, wfh, wfl, fcb,
        nullptr, ffh, ffl, ROWS, 4*DMODEL, DMODEL, nullptr, nullptr, nullptr);
    // 7) out = ff @ proj + b + hid
    gemm_mma_kernel<3><<<dim3(8, 16), 256, GEMM_SMEM>>>(ffh, ffl, woh, wol, pb,
        out, nullptr, nullptr, ROWS, DMODEL, 4*DMODEL, hid, nullptr, nullptr);
}

// round 7
// speedup vs baseline: 1.8921x; 1.0618x over previous
#include <cuda_runtime.h>
#include <cuda_bf16.h>
#include <cstdint>

#define BS_    2
#define SEQ    1024
#define DMODEL 1024
#define NH     16
#define HD     64
#define MM     32
#define ROWS   (BS_*SEQ)

// ---------------- scratch (device globals) ----------------
__device__ float g_qkv[ROWS*3*DMODEL];
__device__ float g_mem[ROWS*DMODEL];
__device__ float g_hid[ROWS*DMODEL];
__device__ __nv_bfloat16 g_h1h[ROWS*DMODEL],  g_h1l[ROWS*DMODEL];
__device__ __nv_bfloat16 g_atth[ROWS*DMODEL], g_attl[ROWS*DMODEL];
__device__ __nv_bfloat16 g_h2h[ROWS*DMODEL],  g_h2l[ROWS*DMODEL];
__device__ __nv_bfloat16 g_ffh[ROWS*4*DMODEL], g_ffl[ROWS*4*DMODEL];
__device__ __nv_bfloat16 g_wqh[DMODEL*3*DMODEL], g_wql[DMODEL*3*DMODEL];
__device__ __nv_bfloat16 g_wph[DMODEL*DMODEL],   g_wpl[DMODEL*DMODEL];
__device__ __nv_bfloat16 g_wfh[DMODEL*4*DMODEL], g_wfl[DMODEL*4*DMODEL];
__device__ __nv_bfloat16 g_woh[4*DMODEL*DMODEL], g_wol[4*DMODEL*DMODEL];

// ---------------- helpers ----------------
__device__ __forceinline__ uint32_t smem_to_u32(const void* p) {
    uint32_t a;
    asm("{ .reg .u64 t; cvta.to.shared.u64 t, %1; cvt.u32.u64 %0, t; }" : "=r"(a) : "l"(p));
    return a;
}
__device__ __forceinline__ void cp16(uint32_t s, const void* g) {
    asm volatile("cp.async.cg.shared.global [%0], [%1], 16;" :: "r"(s), "l"(g));
}
#define CP_COMMIT() asm volatile("cp.async.commit_group;" ::: "memory")
#define CP_WAIT1()  asm volatile("cp.async.wait_group 1;" ::: "memory")

__device__ __forceinline__ void ldsm4(uint32_t* r, uint32_t addr) {
    asm volatile("ldmatrix.sync.aligned.m8n8.x4.shared.b16 {%0,%1,%2,%3}, [%4];"
        : "=r"(r[0]), "=r"(r[1]), "=r"(r[2]), "=r"(r[3]) : "r"(addr));
}
__device__ __forceinline__ void ldsm2(uint32_t* r, uint32_t addr) {
    asm volatile("ldmatrix.sync.aligned.m8n8.x2.shared.b16 {%0,%1}, [%2];"
        : "=r"(r[0]), "=r"(r[1]) : "r"(addr));
}
__device__ __forceinline__ void mma16816(float* d, const uint32_t* a, const uint32_t* b) {
    asm volatile(
      "mma.sync.aligned.m16n8k16.row.col.f32.bf16.bf16.f32 "
      "{%0,%1,%2,%3}, {%4,%5,%6,%7}, {%8,%9}, {%0,%1,%2,%3};"
      : "+f"(d[0]), "+f"(d[1]), "+f"(d[2]), "+f"(d[3])
      : "r"(a[0]), "r"(a[1]), "r"(a[2]), "r"(a[3]), "r"(b[0]), "r"(b[1]));
}

__device__ __forceinline__ float gelu_new(float x) {
    float x3 = x * x * x;
    float t  = tanhf(0.7978845608028654f * (x + 0.044715f * x3));
    return 0.5f * x * (1.f + t);
}
__device__ __forceinline__ uint32_t pack_bf2(float x, float y) {
    __nv_bfloat162 t = __floats2bfloat162_rn(x, y);
    return *reinterpret_cast<uint32_t*>(&t);
}
__device__ __forceinline__ float bf_hi(float x) {
    return __bfloat162float(__float2bfloat16(x));
}

// ---------------- prep: fused 4x weight-convert + LN -----------------------
__device__ void wconv_body(float* shm,
    const float* __restrict__ W, __nv_bfloat16* __restrict__ hi,
    __nv_bfloat16* __restrict__ lo, int K, int N, int bx, int by)
{
    float (*s)[33] = (float(*)[33])shm;
    const int tx = threadIdx.x & 31, ty = threadIdx.x >> 5;
    const int n0 = bx * 32, k0 = by * 32;
    #pragma unroll
    for (int i = 0; i < 4; i++)
        s[ty + 8*i][tx] = W[(size_t)(k0 + ty + 8*i) * N + n0 + tx];
    __syncthreads();
    #pragma unroll
    for (int i = 0; i < 4; i++) {
        int n = ty + 8*i;
        float v = s[tx][n];
        size_t o = (size_t)(n0 + n) * K + k0 + tx;
        hi[o] = __float2bfloat16(v);
        lo[o] = __float2bfloat16(v - bf_hi(v));
    }
}

__device__ void ln_body(float* shm, int row,
    const float* __restrict__ x, const float* __restrict__ g,
    const float* __restrict__ b, __nv_bfloat16* __restrict__ yh,
    __nv_bfloat16* __restrict__ yl)
{
    const int tid = threadIdx.x;
    float* rs = shm; float* rs2 = shm + 8;
    const float* xr = x + (size_t)row * DMODEL;
    float4 v = *(const float4*)(xr + tid * 4);
    float s  = v.x + v.y + v.z + v.w;
    float s2 = v.x*v.x + v.y*v.y + v.z*v.z + v.w*v.w;
    #pragma unroll
    for (int o = 16; o; o >>= 1) {
        s  += __shfl_xor_sync(0xffffffffu, s,  o);
        s2 += __shfl_xor_sync(0xffffffffu, s2, o);
    }
    const int w = tid >> 5, l = tid & 31;
    if (!l) { rs[w] = s; rs2[w] = s2; }
    __syncthreads();
    s = 0.f; s2 = 0.f;
    #pragma unroll
    for (int i = 0; i < 8; i++) { s += rs[i]; s2 += rs2[i]; }
    const float mean = s * (1.f / DMODEL);
    const float var  = s2 * (1.f / DMODEL) - mean * mean;
    const float rstd = rsqrtf(var + 1e-5f);
    const int c = tid * 4;
    float4 gg = *(const float4*)(g + c);
    float4 bb = *(const float4*)(b + c);
    float4 o;
    o.x = (v.x - mean) * rstd * gg.x + bb.x;
    o.y = (v.y - mean) * rstd * gg.y + bb.y;
    o.z = (v.z - mean) * rstd * gg.z + bb.z;
    o.w = (v.w - mean) * rstd * gg.w + bb.w;
    uint2 hh, ll;
    hh.x = pack_bf2(o.x, o.y); hh.y = pack_bf2(o.z, o.w);
    ll.x = pack_bf2(o.x - bf_hi(o.x), o.y - bf_hi(o.y));
    ll.y = pack_bf2(o.z - bf_hi(o.z), o.w - bf_hi(o.w));
    const size_t idx = (size_t)row * DMODEL + c;
    *(uint2*)(yh + idx) = hh;
    *(uint2*)(yl + idx) = ll;
}

__global__ void __launch_bounds__(256) prep_kernel(
    const float* prev, const float* ln1g, const float* ln1b,
    __nv_bfloat16* h1h, __nv_bfloat16* h1l,
    const float* attnw, __nv_bfloat16* wqh, __nv_bfloat16* wql,
    const float* cprw,  __nv_bfloat16* wph, __nv_bfloat16* wpl,
    const float* fcw,   __nv_bfloat16* wfh, __nv_bfloat16* wfl,
    const float* pw,    __nv_bfloat16* woh, __nv_bfloat16* wol)
{
    __shared__ float shm[32*33];
    int idx = blockIdx.x;
    if (idx < 2048) { ln_body(shm, idx, prev, ln1g, ln1b, h1h, h1l); return; }
    idx -= 2048;
    if (idx < 3072) { wconv_body(shm, attnw, wqh, wql, 1024, 3072, idx % 96, idx / 96); return; }
    idx -= 3072;
    if (idx < 1024) { wconv_body(shm, cprw, wph, wpl, 1024, 1024, idx % 32, idx / 32); return; }
    idx -= 1024;
    if (idx < 4096) { wconv_body(shm, fcw, wfh, wfl, 1024, 4096, idx % 128, idx / 128); return; }
    idx -= 4096;
    wconv_body(shm, pw, woh, wol, 4096, 1024, idx % 32, idx / 32);
}

// ---------------- epilogue (shared by both GEMM kernels) --------------------
template<int EPI>
__device__ __forceinline__ void gemm_epilogue_elem(
    float v0, float v1, const float2 bb, size_t o,
    float* Cf, __nv_bfloat16* Ch, __nv_bfloat16* Cl,
    const float* aux1, const float* aux2, float g)
{
    v0 += bb.x; v1 += bb.y;
    if (EPI == 1) {
        float2 a1 = *(const float2*)(aux1 + o);
        float2 a2 = *(const float2*)(aux2 + o);
        v0 = (1.f - g) * v0 + g * a1.x + a2.x;
        v1 = (1.f - g) * v1 + g * a1.y + a2.y;
    }
    if (EPI == 3) {
        float2 a1 = *(const float2*)(aux1 + o);
        v0 += a1.x; v1 += a1.y;
    }
    if (EPI == 2) {
        v0 = gelu_new(v0); v1 = gelu_new(v1);
        *(uint32_t*)(Ch + o) = pack_bf2(v0, v1);
        *(uint32_t*)(Cl + o) = pack_bf2(v0 - bf_hi(v0), v1 - bf_hi(v1));
    } else {
        *(float2*)(Cf + o) = make_float2(v0, v1);
    }
}

// ---------------- GEMM 128x128 tile (grids >= 296) --------------------------
#define AB_     8192
#define GSTAGE  (4*AB_)                 // 32768
#define GEMM_SMEM (3*GSTAGE)            // 98304

template<int EPI>
__global__ void __launch_bounds__(256, 2) gemm_mma_kernel(
    const __nv_bfloat16* __restrict__ Ah, const __nv_bfloat16* __restrict__ Al,
    const __nv_bfloat16* __restrict__ Bh, const __nv_bfloat16* __restrict__ Bl,
    const float* __restrict__ bias,
    float* __restrict__ Cf, __nv_bfloat16* __restrict__ Ch, __nv_bfloat16* __restrict__ Cl,
    int M, int N, int K,
    const float* __restrict__ aux1, const float* __restrict__ aux2,
    const float* __restrict__ gp)
{
    extern __shared__ char smp[];
    const uint32_t sb = smem_to_u32(smp);
    const int tid = threadIdx.x;
    const int wid = tid >> 5, lane = tid & 31;
    const int wm = wid & 1, wn = wid >> 1;
    const int bm = blockIdx.y, bn = blockIdx.x;
    const int NC = K >> 5;

    const size_t Abase = (size_t)bm * 128 * K;
    const size_t Bbase = (size_t)bn * 128 * K;

    float acc[4][4][4];
    #pragma unroll
    for (int i = 0; i < 4; i++)
        #pragma unroll
        for (int j = 0; j < 4; j++)
            #pragma unroll
            for (int x = 0; x < 4; x++) acc[i][j][x] = 0.f;

    const int crow = tid >> 2;
    const int cq   = tid & 3;
    const uint32_t so0 = (uint32_t)(crow * 64 + ((cq ^ (crow & 3)) << 4));
    const uint32_t so1 = so0 + 64 * 64;

    auto issue = [&](int buf, int kt) {
        const int k0 = kt << 5;
        const uint32_t sbase = sb + buf * GSTAGE;
        const size_t g0 = (size_t)crow * K + k0 + cq * 8;
        const size_t g1 = g0 + (size_t)64 * K;
        cp16(sbase + so0,          Ah + Abase + g0);
        cp16(sbase + so1,          Ah + Abase + g1);
        cp16(sbase + AB_ + so0,    Al + Abase + g0);
        cp16(sbase + AB_ + so1,    Al + Abase + g1);
        cp16(sbase + 2*AB_ + so0,  Bh + Bbase + g0);
        cp16(sbase + 2*AB_ + so1,  Bh + Bbase + g1);
        cp16(sbase + 3*AB_ + so0,  Bl + Bbase + g0);
        cp16(sbase + 3*AB_ + so1,  Bl + Bbase + g1);
    };

    issue(0, 0); CP_COMMIT();
    issue(1, 1); CP_COMMIT();

    const uint32_t rowA = (uint32_t)(wm * 64 + (lane & 15));
    const uint32_t qa   = (uint32_t)(lane >> 4);
    const uint32_t r3a  = rowA & 3;
    const uint32_t aBase = rowA * 64;
    const uint32_t rowB = (uint32_t)(wn * 32 + (lane & 7));
    const uint32_t qb   = (uint32_t)((lane >> 3) & 1);
    const uint32_t r3b  = rowB & 3;
    const uint32_t bBase = rowB * 64;

    int buf = 0;
    for (int c = 0; c < NC; c++) {
        CP_WAIT1();
        __syncthreads();
        if (c + 2 < NC) { int nb = buf + 2; if (nb >= 3) nb -= 3; issue(nb, c + 2); }
        CP_COMMIT();

        const uint32_t s0 = sb + buf * GSTAGE;
        #pragma unroll
        for (int ks = 0; ks < 2; ks++) {
            uint32_t bh[4][2], bl[4][2];
            const uint32_t qpb = ((qb + 2*ks) ^ r3b) << 4;
            #pragma unroll
            for (int nt = 0; nt < 4; nt++) {
                const uint32_t ba = s0 + bBase + (uint32_t)(nt * 512) + qpb;
                ldsm2(bh[nt], ba + 2*AB_);
                ldsm2(bl[nt], ba + 3*AB_);
            }
            const uint32_t qpa = ((qa + 2*ks) ^ r3a) << 4;
            #pragma unroll
            for (int mt = 0; mt < 4; mt++) {
                uint32_t ah[4], al[4];
                const uint32_t aa = s0 + aBase + (uint32_t)(mt * 1024) + qpa;
                ldsm4(ah, aa);
                ldsm4(al, aa + AB_);
                #pragma unroll
                for (int nt = 0; nt < 4; nt++) {
                    mma16816(acc[mt][nt], ah, bh[nt]);
                    mma16816(acc[mt][nt], ah, bl[nt]);
                    mma16816(acc[mt][nt], al, bh[nt]);
                }
            }
        }
        buf++; if (buf >= 3) buf = 0;
    }

    const int r = lane >> 2, q = lane & 3;
    const float g = (EPI == 1) ? *gp : 0.f;
    #pragma unroll
    for (int mt = 0; mt < 4; mt++) {
        #pragma unroll
        for (int nt = 0; nt < 4; nt++) {
            const int col = bn * 128 + wn * 32 + nt * 8 + q * 2;
            const float2 bb = *(const float2*)(bias + col);
            #pragma unroll
            for (int hh = 0; hh < 2; hh++) {
                const int row = bm * 128 + wm * 64 + mt * 16 + r + hh * 8;
                gemm_epilogue_elem<EPI>(acc[mt][nt][hh*2], acc[mt][nt][hh*2+1], bb,
                    (size_t)row * N + col, Cf, Ch, Cl, aux1, aux2, g);
            }
        }
    }
}

// ---------------- GEMM 64x128 tile (for 128-tile-starved grids) -------------
// Stage: A 64x64B x2 (hi/lo) + B 128x64B x2 = 24576B; 3 stages = 73728B.
// 128 threads (4 warps), each warp 64x32.
#define A64_      4096
#define B64_      8192
#define GSTAGE64  (2*A64_ + 2*B64_)     // 24576
#define GEMM64_SMEM (3*GSTAGE64)        // 73728

template<int EPI>
__global__ void __launch_bounds__(128, 3) gemm_mma64_kernel(
    const __nv_bfloat16* __restrict__ Ah, const __nv_bfloat16* __restrict__ Al,
    const __nv_bfloat16* __restrict__ Bh, const __nv_bfloat16* __restrict__ Bl,
    const float* __restrict__ bias,
    float* __restrict__ Cf, __nv_bfloat16* __restrict__ Ch, __nv_bfloat16* __restrict__ Cl,
    int M, int N, int K,
    const float* __restrict__ aux1, const float* __restrict__ aux2,
    const float* __restrict__ gp)
{
    extern __shared__ char smp[];
    const uint32_t sb = smem_to_u32(smp);
    const int tid = threadIdx.x;
    const int wn = tid >> 5, lane = tid & 31;
    const int bm = blockIdx.y, bn = blockIdx.x;
    const int NC = K >> 5;

    const size_t Abase = (size_t)bm * 64 * K;
    const size_t Bbase = (size_t)bn * 128 * K;

    float acc[4][4][4];
    #pragma unroll
    for (int i = 0; i < 4; i++)
        #pragma unroll
        for (int j = 0; j < 4; j++)
            #pragma unroll
            for (int x = 0; x < 4; x++) acc[i][j][x] = 0.f;

    const int crow = tid >> 2;          // 0..31
    const int cq   = tid & 3;
    const uint32_t soA = (uint32_t)(crow * 64 + ((cq ^ (crow & 3)) << 4));

    auto issue = [&](int buf, int kt) {
        const int k0 = kt << 5;
        const uint32_t sbase = sb + buf * GSTAGE64;
        const size_t gc = (size_t)crow * K + k0 + cq * 8;
        cp16(sbase + soA,                 Ah + Abase + gc);
        cp16(sbase + soA + 2048,          Ah + Abase + gc + (size_t)32 * K);
        cp16(sbase + A64_ + soA,          Al + Abase + gc);
        cp16(sbase + A64_ + soA + 2048,   Al + Abase + gc + (size_t)32 * K);
        #pragma unroll
        for (int j = 0; j < 4; j++) {
            const size_t gB = gc + (size_t)(32 * j) * K;
            cp16(sbase + 2*A64_ + soA + j*2048,        Bh + Bbase + gB);
            cp16(sbase + 2*A64_ + B64_ + soA + j*2048, Bl + Bbase + gB);
        }
    };

    issue(0, 0); CP_COMMIT();
    issue(1, 1); CP_COMMIT();

    const uint32_t rowA = (uint32_t)(lane & 15);
    const uint32_t qa   = (uint32_t)(lane >> 4);
    const uint32_t r3a  = rowA & 3;
    const uint32_t aBase = rowA * 64;
    const uint32_t rowB = (uint32_t)(wn * 32 + (lane & 7));
    const uint32_t qb   = (uint32_t)((lane >> 3) & 1);
    const uint32_t r3b  = rowB & 3;
    const uint32_t bBase = rowB * 64;

    int buf = 0;
    for (int c = 0; c < NC; c++) {
        CP_WAIT1();
        __syncthreads();
        if (c + 2 < NC) { int nb = buf + 2; if (nb >= 3) nb -= 3; issue(nb, c + 2); }
        CP_COMMIT();

        const uint32_t s0 = sb + buf * GSTAGE64;
        #pragma unroll
        for (int ks = 0; ks < 2; ks++) {
            uint32_t bh[4][2], bl[4][2];
            const uint32_t qpb = ((qb + 2*ks) ^ r3b) << 4;
            #pragma unroll
            for (int nt = 0; nt < 4; nt++) {
                const uint32_t ba = s0 + 2*A64_ + bBase + (uint32_t)(nt * 512) + qpb;
                ldsm2(bh[nt], ba);
                ldsm2(bl[nt], ba + B64_);
            }
            const uint32_t qpa = ((qa + 2*ks) ^ r3a) << 4;
            #pragma unroll
            for (int mt = 0; mt < 4; mt++) {
                uint32_t ah[4], al[4];
                const uint32_t aa = s0 + aBase + (uint32_t)(mt * 1024) + qpa;
                ldsm4(ah, aa);
                ldsm4(al, aa + A64_);
                #pragma unroll
                for (int nt = 0; nt < 4; nt++) {
                    mma16816(acc[mt][nt], ah, bh[nt]);
                    mma16816(acc[mt][nt], ah, bl[nt]);
                    mma16816(acc[mt][nt], al, bh[nt]);
                }
            }
        }
        buf++; if (buf >= 3) buf = 0;
    }

    const int r = lane >> 2, q = lane & 3;
    const float g = (EPI == 1) ? *gp : 0.f;
    #pragma unroll
    for (int mt = 0; mt < 4; mt++) {
        #pragma unroll
        for (int nt = 0; nt < 4; nt++) {
            const int col = bn * 128 + wn * 32 + nt * 8 + q * 2;
            const float2 bb = *(const float2*)(bias + col);
            #pragma unroll
            for (int hh = 0; hh < 2; hh++) {
                const int row = bm * 64 + mt * 16 + r + hh * 8;
                gemm_epilogue_elem<EPI>(acc[mt][nt][hh*2], acc[mt][nt][hh*2+1], bb,
                    (size_t)row * N + col, Cf, Ch, Cl, aux1, aux2, g);
            }
        }
    }
}

// ---------------- fused attention: flash-mma (512) + memattn (2048) ---------
// flash smem: Qh|Ql|Kh|Kl|Vth|Vtl each [64][72] bf16 (9216B) + stats 1KB
#define FROW 144
#define FLASH_SMEM (6*9216 + 1024)

__device__ void memattn_body(const float* __restrict__ qkv,
                             const float* __restrict__ mkv,
                             float* __restrict__ outm, int row)
{
    const int tid = threadIdx.x;
    __shared__ float sc[NH * MM];
    float4 qv = *(const float4*)(qkv + (size_t)row * 3072 + tid * 4);
    qv.x *= 0.125f; qv.y *= 0.125f; qv.z *= 0.125f; qv.w *= 0.125f;
    const float* kbase = mkv + (size_t)row * MM * 2 * DMODEL;
    const int h = tid >> 4;
    #pragma unroll 4
    for (int m = 0; m < MM; m++) {
        float4 kk = *(const float4*)(kbase + (size_t)m * 2 * DMODEL + tid * 4);
        float d = qv.x * kk.x + qv.y * kk.y + qv.z * kk.z + qv.w * kk.w;
        #pragma unroll
        for (int o = 8; o; o >>= 1) d += __shfl_xor_sync(0xffffffffu, d, o);
        if ((tid & 15) == 0) sc[h * MM + m] = d;
    }
    __syncthreads();
    if (tid < NH) {
        float mx = -1e30f;
        #pragma unroll
        for (int m = 0; m < MM; m++) mx = fmaxf(mx, sc[tid * MM + m]);
        float s = 0.f;
        #pragma unroll
        for (int m = 0; m < MM; m++) {
            float e = __expf(sc[tid * MM + m] - mx);
            sc[tid * MM + m] = e; s += e;
        }
        float inv = 1.f / s;
        #pragma unroll
        for (int m = 0; m < MM; m++) sc[tid * MM + m] *= inv;
    }
    __syncthreads();
    float4 acc = make_float4(0.f, 0.f, 0.f, 0.f);
    #pragma unroll 4
    for (int m = 0; m < MM; m++) {
        float w = sc[h * MM + m];
        float4 vv = *(const float4*)(kbase + (size_t)m * 2 * DMODEL + DMODEL + tid * 4);
        acc.x += w * vv.x; acc.y += w * vv.y; acc.z += w * vv.z; acc.w += w * vv.w;
    }
    *(float4*)(outm + (size_t)row * DMODEL + tid * 4) = acc;
}

__device__ void flash_body(const float* __restrict__ qkv,
                           __nv_bfloat16* __restrict__ outh,
                           __nv_bfloat16* __restrict__ outl,
                           char* sm, int fb)
{
    const int tid = threadIdx.x, lane = tid & 31, wid = tid >> 5;
    const int wm = wid & 3, wn = wid >> 2;       // warp tile: rows wm*16, cols wn*32
    const int qt = fb & 15, bhh = fb >> 4, b = bhh >> 4, h = bhh & 15;
    const int qbase = qt * 64;
    const size_t srow = (size_t)b * SEQ;

    char* Qh  = sm;                  // + 9216 = Ql
    char* Kh  = sm + 2*9216;         // + 9216 = Kl
    char* Vth = sm + 4*9216;         // + 9216 = Vtl  ([hd][seq] transposed)
    float* msb = (float*)(sm + 6*9216);
    float* lsb = msb + 128;

    const int lrow = tid >> 2;           // 0..63
    const int lc0  = (tid & 3) * 16;

    {   // Q load, scale, hi/lo split
        const float* gq = qkv + (srow + qbase + lrow) * 3072 + h * 64 + lc0;
        char* qh = Qh + lrow * FROW + lc0 * 2;
        #pragma unroll
        for (int u = 0; u < 4; u++) {
            float4 v = *(const float4*)(gq + u * 4);
            v.x *= 0.125f; v.y *= 0.125f; v.z *= 0.125f; v.w *= 0.125f;
            *(uint32_t*)(qh + u*8)            = pack_bf2(v.x, v.y);
            *(uint32_t*)(qh + u*8 + 4)        = pack_bf2(v.z, v.w);
            *(uint32_t*)(qh + 9216 + u*8)     = pack_bf2(v.x - bf_hi(v.x), v.y - bf_hi(v.y));
            *(uint32_t*)(qh + 9216 + u*8 + 4) = pack_bf2(v.z - bf_hi(v.z), v.w - bf_hi(v.w));
        }
    }

    const int r = lane >> 2, q = lane & 3;
    float m0 = -1e30f, m1 = -1e30f, l0 = 0.f, l1 = 0.f;
    float o[8][4];
    #pragma unroll
    for (int i = 0; i < 8; i++) o[i][0]=o[i][1]=o[i][2]=o[i][3]=0.f;

    const uint32_t QA = smem_to_u32(Qh);
    const uint32_t qaddr0 = QA + (uint32_t)((wm*16 + (lane & 15)) * FROW + ((lane >> 4) & 1) * 16);
    const uint32_t kaddr0 = QA + 2*9216 + (uint32_t)((wn*32 + (lane & 7)) * FROW + ((lane >> 3) & 1) * 16);
    const uint32_t vaddr0 = QA + 4*9216 + (uint32_t)((lane & 7) * FROW + wn*64 + ((lane >> 3) & 1) * 16);

    for (int kt = 0; kt <= qt; kt++) {
        __syncthreads();
        {   // K (row-major) + V (transposed) load, hi/lo split
            const float* gk = qkv + (srow + kt*64 + lrow) * 3072 + 1024 + h * 64 + lc0;
            char* kh = Kh + lrow * FROW + lc0 * 2;
            #pragma unroll
            for (int u = 0; u < 4; u++) {
                float4 kv = *(const float4*)(gk + u * 4);
                *(uint32_t*)(kh + u*8)            = pack_bf2(kv.x, kv.y);
                *(uint32_t*)(kh + u*8 + 4)        = pack_bf2(kv.z, kv.w);
                *(uint32_t*)(kh + 9216 + u*8)     = pack_bf2(kv.x - bf_hi(kv.x), kv.y - bf_hi(kv.y));
                *(uint32_t*)(kh + 9216 + u*8 + 4) = pack_bf2(kv.z - bf_hi(kv.z), kv.w - bf_hi(kv.w));
                float4 vv = *(const float4*)(gk + 1024 + u * 4);
                float vals[4] = {vv.x, vv.y, vv.z, vv.w};
                #pragma unroll
                for (int j = 0; j < 4; j++) {
                    const int c = lc0 + u*4 + j;
                    *(__nv_bfloat16*)(Vth + c*FROW + lrow*2) = __float2bfloat16(vals[j]);
                    *(__nv_bfloat16*)(Vth + 9216 + c*FROW + lrow*2) =
                        __float2bfloat16(vals[j] - bf_hi(vals[j]));
                }
            }
        }
        __syncthreads();

        // ---- S = Q K^T (bf16x3) ----
        float s[4][4];
        #pragma unroll
        for (int nt = 0; nt < 4; nt++) s[nt][0]=s[nt][1]=s[nt][2]=s[nt][3]=0.f;
        #pragma unroll
        for (int ks = 0; ks < 4; ks++) {
            uint32_t aQh[4], aQl[4];
            ldsm4(aQh, qaddr0 + ks*32);
            ldsm4(aQl, qaddr0 + 9216 + ks*32);
            #pragma unroll
            for (int nt = 0; nt < 4; nt++) {
                uint32_t bKh[2], bKl[2];
                const uint32_t ka = kaddr0 + (uint32_t)(nt * 8 * FROW + ks * 32);
                ldsm2(bKh, ka);
                ldsm2(bKl, ka + 9216);
                mma16816(s[nt], aQh, bKh);
                mma16816(s[nt], aQh, bKl);
                mma16816(s[nt], aQl, bKh);
            }
        }

        if (kt == qt) {
            const int r0 = wm*16 + r;
            #pragma unroll
            for (int nt = 0; nt < 4; nt++) {
                const int cb = wn*32 + nt*8 + q*2;
                if (cb     > r0)     s[nt][0] = -1e30f;
                if (cb + 1 > r0)     s[nt][1] = -1e30f;
                if (cb     > r0 + 8) s[nt][2] = -1e30f;
                if (cb + 1 > r0 + 8) s[nt][3] = -1e30f;
            }
        }

        // ---- online softmax stats ----
        float mx0 = fmaxf(fmaxf(s[0][0], s[0][1]), fmaxf(s[1][0], s[1][1]));
        mx0 = fmaxf(mx0, fmaxf(fmaxf(s[2][0], s[2][1]), fmaxf(s[3][0], s[3][1])));
        float mx1 = fmaxf(fmaxf(s[0][2], s[0][3]), fmaxf(s[1][2], s[1][3]));
        mx1 = fmaxf(mx1, fmaxf(fmaxf(s[2][2], s[2][3]), fmaxf(s[3][2], s[3][3])));
        mx0 = fmaxf(mx0, __shfl_xor_sync(0xffffffffu, mx0, 1));
        mx0 = fmaxf(mx0, __shfl_xor_sync(0xffffffffu, mx0, 2));
        mx1 = fmaxf(mx1, __shfl_xor_sync(0xffffffffu, mx1, 1));
        mx1 = fmaxf(mx1, __shfl_xor_sync(0xffffffffu, mx1, 2));
        if (q == 0) {
            msb[wn*64 + wm*16 + r]     = mx0;
            msb[wn*64 + wm*16 + r + 8] = mx1;
        }
        __syncthreads();
        const float mn0 = fmaxf(m0, fmaxf(mx0, msb[(1-wn)*64 + wm*16 + r]));
        const float mn1 = fmaxf(m1, fmaxf(mx1, msb[(1-wn)*64 + wm*16 + r + 8]));
        const float al0 = __expf(m0 - mn0), al1 = __expf(m1 - mn1);
        float sum0 = 0.f, sum1 = 0.f;
        #pragma unroll
        for (int nt = 0; nt < 4; nt++) {
            s[nt][0] = __expf(s[nt][0] - mn0);
            s[nt][1] = __expf(s[nt][1] - mn0);
            s[nt][2] = __expf(s[nt][2] - mn1);
            s[nt][3] = __expf(s[nt][3] - mn1);
            sum0 += s[nt][0] + s[nt][1];
            sum1 += s[nt][2] + s[nt][3];
        }
        sum0 += __shfl_xor_sync(0xffffffffu, sum0, 1);
        sum0 += __shfl_xor_sync(0xffffffffu, sum0, 2);
        sum1 += __shfl_xor_sync(0xffffffffu, sum1, 1);
        sum1 += __shfl_xor_sync(0xffffffffu, sum1, 2);
        if (q == 0) {
            lsb[wn*64 + wm*16 + r]     = sum0;
            lsb[wn*64 + wm*16 + r + 8] = sum1;
        }
        __syncthreads();
        l0 = al0 * l0 + sum0 + lsb[(1-wn)*64 + wm*16 + r];
        l1 = al1 * l1 + sum1 + lsb[(1-wn)*64 + wm*16 + r + 8];
        m0 = mn0; m1 = mn1;
        #pragma unroll
        for (int i = 0; i < 8; i++) {
            o[i][0] *= al0; o[i][1] *= al0; o[i][2] *= al1; o[i][3] *= al1;
        }

        // ---- P fragments (hi/lo) ----
        uint32_t aPh[2][4], aPl[2][4];
        #pragma unroll
        for (int ks = 0; ks < 2; ks++) {
            const int n0 = 2*ks, n1 = 2*ks + 1;
            aPh[ks][0] = pack_bf2(s[n0][0], s[n0][1]);
            aPh[ks][1] = pack_bf2(s[n0][2], s[n0][3]);
            aPh[ks][2] = pack_bf2(s[n1][0], s[n1][1]);
            aPh[ks][3] = pack_bf2(s[n1][2], s[n1][3]);
            aPl[ks][0] = pack_bf2(s[n0][0]-bf_hi(s[n0][0]), s[n0][1]-bf_hi(s[n0][1]));
            aPl[ks][1] = pack_bf2(s[n0][2]-bf_hi(s[n0][2]), s[n0][3]-bf_hi(s[n0][3]));
            aPl[ks][2] = pack_bf2(s[n1][0]-bf_hi(s[n1][0]), s[n1][1]-bf_hi(s[n1][1]));
            aPl[ks][3] = pack_bf2(s[n1][2]-bf_hi(s[n1][2]), s[n1][3]-bf_hi(s[n1][3]));
        }
        // ---- O += P V (bf16x3); warp covers k = wn*32..+31 ----
        #pragma unroll
        for (int ks = 0; ks < 2; ks++) {
            #pragma unroll
            for (int ntv = 0; ntv < 8; ntv++) {
                uint32_t bVh[2], bVl[2];
                const uint32_t va = vaddr0 + (uint32_t)(ntv * 8 * FROW + ks * 32);
                ldsm2(bVh, va);
                ldsm2(bVl, va + 9216);
                mma16816(o[ntv], aPh[ks], bVh);
                mma16816(o[ntv], aPh[ks], bVl);
                mma16816(o[ntv], aPl[ks], bVh);
            }
        }
    }

    // ---- combine wn partials, normalize, output ----
    __syncthreads();
    float* osum = (float*)sm;            // reuse Q region (16KB)
    if (wn == 1) {
        #pragma unroll
        for (int ntv = 0; ntv < 8; ntv++) {
            const int rg = wm*16 + r, cg = ntv*8 + q*2;
            osum[rg*64 + cg]         = o[ntv][0];
            osum[rg*64 + cg + 1]     = o[ntv][1];
            osum[(rg+8)*64 + cg]     = o[ntv][2];
            osum[(rg+8)*64 + cg + 1] = o[ntv][3];
        }
    }
    __syncthreads();
    if (wn == 0) {
        const float i0 = 1.f / l0, i1 = 1.f / l1;
        #pragma unroll
        for (int ntv = 0; ntv < 8; ntv++) {
            const int rg = wm*16 + r, cg = ntv*8 + q*2;
            float v0 = (o[ntv][0] + osum[rg*64 + cg])         * i0;
            float v1 = (o[ntv][1] + osum[rg*64 + cg + 1])     * i0;
            float v2 = (o[ntv][2] + osum[(rg+8)*64 + cg])     * i1;
            float v3 = (o[ntv][3] + osum[(rg+8)*64 + cg + 1]) * i1;
            const size_t o0 = (srow + qbase + rg) * (size_t)DMODEL + h*64 + cg;
            const size_t o1 = o0 + 8 * DMODEL;
            *(uint32_t*)(outh + o0) = pack_bf2(v0, v1);
            *(uint32_t*)(outl + o0) = pack_bf2(v0 - bf_hi(v0), v1 - bf_hi(v1));
            *(uint32_t*)(outh + o1) = pack_bf2(v2, v3);
            *(uint32_t*)(outl + o1) = pack_bf2(v2 - bf_hi(v2), v3 - bf_hi(v3));
        }
    }
}

__global__ void __launch_bounds__(256) attn_kernel(
    const float* __restrict__ qkv, const float* __restrict__ mkv,
    float* __restrict__ outm,
    __nv_bfloat16* __restrict__ outh, __nv_bfloat16* __restrict__ outl)
{
    extern __shared__ char sm[];
    if (blockIdx.x < 512) {
        flash_body(qkv, outh, outl, sm, blockIdx.x);
    } else {
        memattn_body(qkv, mkv, outm, blockIdx.x - 512);
    }
}

// ------------------------------ launcher ------------------------------------
extern "C" void kernel_launch(void* const* d_in, const int* in_sizes, int n_in,
                              void* d_out, int out_size)
{
    (void)in_sizes; (void)n_in; (void)out_size;
    const float* prev  = (const float*)d_in[0];
    const float* memkv = (const float*)d_in[1];
    const float* gval  = (const float*)d_in[2];
    const float* ln1g  = (const float*)d_in[3];
    const float* ln1b  = (const float*)d_in[4];
    const float* attnw = (const float*)d_in[5];
    const float* attnb = (const float*)d_in[6];
    const float* cprw  = (const float*)d_in[7];
    const float* cprb  = (const float*)d_in[8];
    const float* ln2g  = (const float*)d_in[9];
    const float* ln2b  = (const float*)d_in[10];
    const float* fcw   = (const float*)d_in[11];
    const float* fcb   = (const float*)d_in[12];
    const float* pw    = (const float*)d_in[13];
    const float* pb    = (const float*)d_in[14];
    float* out = (float*)d_out;

    float *qkv, *mem, *hid;
    __nv_bfloat16 *h1h, *h1l, *atth, *attl, *h2h, *h2l, *ffh, *ffl;
    __nv_bfloat16 *wqh, *wql, *wph, *wpl, *wfh, *wfl, *woh, *wol;
    cudaGetSymbolAddress((void**)&qkv, g_qkv);
    cudaGetSymbolAddress((void**)&mem, g_mem);
    cudaGetSymbolAddress((void**)&hid, g_hid);
    cudaGetSymbolAddress((void**)&h1h, g_h1h);  cudaGetSymbolAddress((void**)&h1l, g_h1l);
    cudaGetSymbolAddress((void**)&atth, g_atth); cudaGetSymbolAddress((void**)&attl, g_attl);
    cudaGetSymbolAddress((void**)&h2h, g_h2h);  cudaGetSymbolAddress((void**)&h2l, g_h2l);
    cudaGetSymbolAddress((void**)&ffh, g_ffh);  cudaGetSymbolAddress((void**)&ffl, g_ffl);
    cudaGetSymbolAddress((void**)&wqh, g_wqh);  cudaGetSymbolAddress((void**)&wql, g_wql);
    cudaGetSymbolAddress((void**)&wph, g_wph);  cudaGetSymbolAddress((void**)&wpl, g_wpl);
    cudaGetSymbolAddress((void**)&wfh, g_wfh);  cudaGetSymbolAddress((void**)&wfl, g_wfl);
    cudaGetSymbolAddress((void**)&woh, g_woh);  cudaGetSymbolAddress((void**)&wol, g_wol);

    cudaFuncSetAttribute(attn_kernel, cudaFuncAttributeMaxDynamicSharedMemorySize, FLASH_SMEM);
    cudaFuncSetAttribute(gemm_mma_kernel<0>, cudaFuncAttributeMaxDynamicSharedMemorySize, GEMM_SMEM);
    cudaFuncSetAttribute(gemm_mma_kernel<2>, cudaFuncAttributeMaxDynamicSharedMemorySize, GEMM_SMEM);
    cudaFuncSetAttribute(gemm_mma64_kernel<1>, cudaFuncAttributeMaxDynamicSharedMemorySize, GEMM64_SMEM);
    cudaFuncSetAttribute(gemm_mma64_kernel<3>, cudaFuncAttributeMaxDynamicSharedMemorySize, GEMM64_SMEM);

    // 1) prep: LN1 + all weight converts (fused)
    prep_kernel<<<14336, 256>>>(prev, ln1g, ln1b, h1h, h1l,
        attnw, wqh, wql, cprw, wph, wpl, fcw, wfh, wfl, pw, woh, wol);
    // 2) qkv = h1 @ c_attn + b (f32)
    gemm_mma_kernel<0><<<dim3(24, 16), 256, GEMM_SMEM>>>(h1h, h1l, wqh, wql, attnb,
        qkv, nullptr, nullptr, ROWS, 3*DMODEL, DMODEL, nullptr, nullptr, nullptr);
    // 3) fused flash-mma + memattn
    attn_kernel<<<512 + 2048, 256, FLASH_SMEM>>>(qkv, memkv, mem, atth, attl);
    // 4) hid = (1-g)*(att@c_proj+b) + g*mem + prev   (64-tile, grid 256)
    gemm_mma64_kernel<1><<<dim3(8, 32), 128, GEMM64_SMEM>>>(atth, attl, wph, wpl, cprb,
        hid, nullptr, nullptr, ROWS, DMODEL, DMODEL, mem, prev, gval);
    // 5) LN2 -> h2 hi/lo
    prep_kernel<<<2048, 256>>>(hid, ln2g, ln2b, h2h, h2l,
        nullptr, nullptr, nullptr, nullptr, nullptr, nullptr,
        nullptr, nullptr, nullptr, nullptr, nullptr, nullptr);
    // 6) ff = gelu(h2 @ fc + b) -> hi/lo
    gemm_mma_kernel<2><<<dim3(32, 16), 256, GEMM_SMEM>>>(h2h, h2l, wfh, wfl, fcb,
        nullptr, ffh, ffl, ROWS, 4*DMODEL, DMODEL, nullptr, nullptr, nullptr);
    // 7) out = ff @ proj + b + hid   (64-tile, grid 256)
    gemm_mma64_kernel<3><<<dim3(8, 32), 128, GEMM64_SMEM>>>(ffh, ffl, woh, wol, pb,
        out, nullptr, nullptr, ROWS, DMODEL, 4*DMODEL, hid, nullptr, nullptr);
}

// round 8
// speedup vs baseline: 1.8931x; 1.0005x over previous
#include <cuda_runtime.h>
#include <cuda_bf16.h>
#include <cstdint>

#define BS_    2
#define SEQ    1024
#define DMODEL 1024
#define NH     16
#define HD     64
#define MM     32
#define ROWS   (BS_*SEQ)

// ---------------- scratch (device globals) ----------------
__device__ float g_qkv[ROWS*3*DMODEL];
__device__ float g_mem[ROWS*DMODEL];
__device__ float g_hid[ROWS*DMODEL];
__device__ __nv_bfloat16 g_h1h[ROWS*DMODEL],  g_h1l[ROWS*DMODEL];
__device__ __nv_bfloat16 g_atth[ROWS*DMODEL], g_attl[ROWS*DMODEL];
__device__ __nv_bfloat16 g_h2h[ROWS*DMODEL],  g_h2l[ROWS*DMODEL];
__device__ __nv_bfloat16 g_ffh[ROWS*4*DMODEL], g_ffl[ROWS*4*DMODEL];
__device__ __nv_bfloat16 g_wqh[DMODEL*3*DMODEL], g_wql[DMODEL*3*DMODEL];
__device__ __nv_bfloat16 g_wph[DMODEL*DMODEL],   g_wpl[DMODEL*DMODEL];
__device__ __nv_bfloat16 g_wfh[DMODEL*4*DMODEL], g_wfl[DMODEL*4*DMODEL];
__device__ __nv_bfloat16 g_woh[4*DMODEL*DMODEL], g_wol[4*DMODEL*DMODEL];

// ---------------- helpers ----------------
__device__ __forceinline__ uint32_t smem_to_u32(const void* p) {
    uint32_t a;
    asm("{ .reg .u64 t; cvta.to.shared.u64 t, %1; cvt.u32.u64 %0, t; }" : "=r"(a) : "l"(p));
    return a;
}
__device__ __forceinline__ void cp16(uint32_t s, const void* g) {
    asm volatile("cp.async.cg.shared.global [%0], [%1], 16;" :: "r"(s), "l"(g));
}
#define CP_COMMIT() asm volatile("cp.async.commit_group;" ::: "memory")
#define CP_WAIT1()  asm volatile("cp.async.wait_group 1;" ::: "memory")

__device__ __forceinline__ void ldsm4(uint32_t* r, uint32_t addr) {
    asm volatile("ldmatrix.sync.aligned.m8n8.x4.shared.b16 {%0,%1,%2,%3}, [%4];"
        : "=r"(r[0]), "=r"(r[1]), "=r"(r[2]), "=r"(r[3]) : "r"(addr));
}
__device__ __forceinline__ void ldsm2(uint32_t* r, uint32_t addr) {
    asm volatile("ldmatrix.sync.aligned.m8n8.x2.shared.b16 {%0,%1}, [%2];"
        : "=r"(r[0]), "=r"(r[1]) : "r"(addr));
}
__device__ __forceinline__ void mma16816(float* d, const uint32_t* a, const uint32_t* b) {
    asm volatile(
      "mma.sync.aligned.m16n8k16.row.col.f32.bf16.bf16.f32 "
      "{%0,%1,%2,%3}, {%4,%5,%6,%7}, {%8,%9}, {%0,%1,%2,%3};"
      : "+f"(d[0]), "+f"(d[1]), "+f"(d[2]), "+f"(d[3])
      : "r"(a[0]), "r"(a[1]), "r"(a[2]), "r"(a[3]), "r"(b[0]), "r"(b[1]));
}

__device__ __forceinline__ float gelu_new(float x) {
    float x3 = x * x * x;
    float t  = tanhf(0.7978845608028654f * (x + 0.044715f * x3));
    return 0.5f * x * (1.f + t);
}
__device__ __forceinline__ uint32_t pack_bf2(float x, float y) {
    __nv_bfloat162 t = __floats2bfloat162_rn(x, y);
    return *reinterpret_cast<uint32_t*>(&t);
}
__device__ __forceinline__ float bf_hi(float x) {
    return __bfloat162float(__float2bfloat16(x));
}

// ---------------- prep: fused 4x weight-convert + LN -----------------------
__device__ void wconv_body(float* shm,
    const float* __restrict__ W, __nv_bfloat16* __restrict__ hi,
    __nv_bfloat16* __restrict__ lo, int K, int N, int bx, int by)
{
    float (*s)[33] = (float(*)[33])shm;
    const int tx = threadIdx.x & 31, ty = threadIdx.x >> 5;
    const int n0 = bx * 32, k0 = by * 32;
    #pragma unroll
    for (int i = 0; i < 4; i++)
        s[ty + 8*i][tx] = W[(size_t)(k0 + ty + 8*i) * N + n0 + tx];
    __syncthreads();
    #pragma unroll
    for (int i = 0; i < 4; i++) {
        int n = ty + 8*i;
        float v = s[tx][n];
        size_t o = (size_t)(n0 + n) * K + k0 + tx;
        hi[o] = __float2bfloat16(v);
        lo[o] = __float2bfloat16(v - bf_hi(v));
    }
}

__device__ void ln_body(float* shm, int row,
    const float* __restrict__ x, const float* __restrict__ g,
    const float* __restrict__ b, __nv_bfloat16* __restrict__ yh,
    __nv_bfloat16* __restrict__ yl)
{
    const int tid = threadIdx.x;
    float* rs = shm; float* rs2 = shm + 8;
    const float* xr = x + (size_t)row * DMODEL;
    float4 v = *(const float4*)(xr + tid * 4);
    float s  = v.x + v.y + v.z + v.w;
    float s2 = v.x*v.x + v.y*v.y + v.z*v.z + v.w*v.w;
    #pragma unroll
    for (int o = 16; o; o >>= 1) {
        s  += __shfl_xor_sync(0xffffffffu, s,  o);
        s2 += __shfl_xor_sync(0xffffffffu, s2, o);
    }
    const int w = tid >> 5, l = tid & 31;
    if (!l) { rs[w] = s; rs2[w] = s2; }
    __syncthreads();
    s = 0.f; s2 = 0.f;
    #pragma unroll
    for (int i = 0; i < 8; i++) { s += rs[i]; s2 += rs2[i]; }
    const float mean = s * (1.f / DMODEL);
    const float var  = s2 * (1.f / DMODEL) - mean * mean;
    const float rstd = rsqrtf(var + 1e-5f);
    const int c = tid * 4;
    float4 gg = *(const float4*)(g + c);
    float4 bb = *(const float4*)(b + c);
    float4 o;
    o.x = (v.x - mean) * rstd * gg.x + bb.x;
    o.y = (v.y - mean) * rstd * gg.y + bb.y;
    o.z = (v.z - mean) * rstd * gg.z + bb.z;
    o.w = (v.w - mean) * rstd * gg.w + bb.w;
    uint2 hh, ll;
    hh.x = pack_bf2(o.x, o.y); hh.y = pack_bf2(o.z, o.w);
    ll.x = pack_bf2(o.x - bf_hi(o.x), o.y - bf_hi(o.y));
    ll.y = pack_bf2(o.z - bf_hi(o.z), o.w - bf_hi(o.w));
    const size_t idx = (size_t)row * DMODEL + c;
    *(uint2*)(yh + idx) = hh;
    *(uint2*)(yl + idx) = ll;
}

__global__ void __launch_bounds__(256) prep_kernel(
    const float* prev, const float* ln1g, const float* ln1b,
    __nv_bfloat16* h1h, __nv_bfloat16* h1l,
    const float* attnw, __nv_bfloat16* wqh, __nv_bfloat16* wql,
    const float* cprw,  __nv_bfloat16* wph, __nv_bfloat16* wpl,
    const float* fcw,   __nv_bfloat16* wfh, __nv_bfloat16* wfl,
    const float* pw,    __nv_bfloat16* woh, __nv_bfloat16* wol)
{
    __shared__ float shm[32*33];
    int idx = blockIdx.x;
    if (idx < 2048) { ln_body(shm, idx, prev, ln1g, ln1b, h1h, h1l); return; }
    idx -= 2048;
    if (idx < 3072) { wconv_body(shm, attnw, wqh, wql, 1024, 3072, idx % 96, idx / 96); return; }
    idx -= 3072;
    if (idx < 1024) { wconv_body(shm, cprw, wph, wpl, 1024, 1024, idx % 32, idx / 32); return; }
    idx -= 1024;
    if (idx < 4096) { wconv_body(shm, fcw, wfh, wfl, 1024, 4096, idx % 128, idx / 128); return; }
    idx -= 4096;
    wconv_body(shm, pw, woh, wol, 4096, 1024, idx % 32, idx / 32);
}

// ---------------- epilogue (shared by both GEMM kernels) --------------------
template<int EPI>
__device__ __forceinline__ void gemm_epilogue_elem(
    float v0, float v1, const float2 bb, size_t o,
    float* Cf, __nv_bfloat16* Ch, __nv_bfloat16* Cl,
    const float* aux1, const float* aux2, float g)
{
    v0 += bb.x; v1 += bb.y;
    if (EPI == 1) {
        float2 a1 = *(const float2*)(aux1 + o);
        float2 a2 = *(const float2*)(aux2 + o);
        v0 = (1.f - g) * v0 + g * a1.x + a2.x;
        v1 = (1.f - g) * v1 + g * a1.y + a2.y;
    }
    if (EPI == 3) {
        float2 a1 = *(const float2*)(aux1 + o);
        v0 += a1.x; v1 += a1.y;
    }
    if (EPI == 2) {
        v0 = gelu_new(v0); v1 = gelu_new(v1);
        *(uint32_t*)(Ch + o) = pack_bf2(v0, v1);
        *(uint32_t*)(Cl + o) = pack_bf2(v0 - bf_hi(v0), v1 - bf_hi(v1));
    } else {
        *(float2*)(Cf + o) = make_float2(v0, v1);
    }
}

// ---------------- GEMM 128x128 tile ------------------------------------------
#define AB_     8192
#define GSTAGE  (4*AB_)                 // 32768
#define GEMM_SMEM (3*GSTAGE)            // 98304

template<int EPI>
__global__ void __launch_bounds__(256, 2) gemm_mma_kernel(
    const __nv_bfloat16* __restrict__ Ah, const __nv_bfloat16* __restrict__ Al,
    const __nv_bfloat16* __restrict__ Bh, const __nv_bfloat16* __restrict__ Bl,
    const float* __restrict__ bias,
    float* __restrict__ Cf, __nv_bfloat16* __restrict__ Ch, __nv_bfloat16* __restrict__ Cl,
    int M, int N, int K,
    const float* __restrict__ aux1, const float* __restrict__ aux2,
    const float* __restrict__ gp)
{
    extern __shared__ char smp[];
    const uint32_t sb = smem_to_u32(smp);
    const int tid = threadIdx.x;
    const int wid = tid >> 5, lane = tid & 31;
    const int wm = wid & 1, wn = wid >> 1;
    const int bm = blockIdx.y, bn = blockIdx.x;
    const int NC = K >> 5;

    const size_t Abase = (size_t)bm * 128 * K;
    const size_t Bbase = (size_t)bn * 128 * K;

    float acc[4][4][4];
    #pragma unroll
    for (int i = 0; i < 4; i++)
        #pragma unroll
        for (int j = 0; j < 4; j++)
            #pragma unroll
            for (int x = 0; x < 4; x++) acc[i][j][x] = 0.f;

    const int crow = tid >> 2;
    const int cq   = tid & 3;
    const uint32_t so0 = (uint32_t)(crow * 64 + ((cq ^ (crow & 3)) << 4));
    const uint32_t so1 = so0 + 64 * 64;

    auto issue = [&](int buf, int kt) {
        const int k0 = kt << 5;
        const uint32_t sbase = sb + buf * GSTAGE;
        const size_t g0 = (size_t)crow * K + k0 + cq * 8;
        const size_t g1 = g0 + (size_t)64 * K;
        cp16(sbase + so0,          Ah + Abase + g0);
        cp16(sbase + so1,          Ah + Abase + g1);
        cp16(sbase + AB_ + so0,    Al + Abase + g0);
        cp16(sbase + AB_ + so1,    Al + Abase + g1);
        cp16(sbase + 2*AB_ + so0,  Bh + Bbase + g0);
        cp16(sbase + 2*AB_ + so1,  Bh + Bbase + g1);
        cp16(sbase + 3*AB_ + so0,  Bl + Bbase + g0);
        cp16(sbase + 3*AB_ + so1,  Bl + Bbase + g1);
    };

    issue(0, 0); CP_COMMIT();
    issue(1, 1); CP_COMMIT();

    const uint32_t rowA = (uint32_t)(wm * 64 + (lane & 15));
    const uint32_t qa   = (uint32_t)(lane >> 4);
    const uint32_t r3a  = rowA & 3;
    const uint32_t aBase = rowA * 64;
    const uint32_t rowB = (uint32_t)(wn * 32 + (lane & 7));
    const uint32_t qb   = (uint32_t)((lane >> 3) & 1);
    const uint32_t r3b  = rowB & 3;
    const uint32_t bBase = rowB * 64;

    int buf = 0;
    for (int c = 0; c < NC; c++) {
        CP_WAIT1();
        __syncthreads();
        if (c + 2 < NC) { int nb = buf + 2; if (nb >= 3) nb -= 3; issue(nb, c + 2); }
        CP_COMMIT();

        const uint32_t s0 = sb + buf * GSTAGE;
        #pragma unroll
        for (int ks = 0; ks < 2; ks++) {
            uint32_t bh[4][2], bl[4][2];
            const uint32_t qpb = ((qb + 2*ks) ^ r3b) << 4;
            #pragma unroll
            for (int nt = 0; nt < 4; nt++) {
                const uint32_t ba = s0 + bBase + (uint32_t)(nt * 512) + qpb;
                ldsm2(bh[nt], ba + 2*AB_);
                ldsm2(bl[nt], ba + 3*AB_);
            }
            const uint32_t qpa = ((qa + 2*ks) ^ r3a) << 4;
            #pragma unroll
            for (int mt = 0; mt < 4; mt++) {
                uint32_t ah[4], al[4];
                const uint32_t aa = s0 + aBase + (uint32_t)(mt * 1024) + qpa;
                ldsm4(ah, aa);
                ldsm4(al, aa + AB_);
                // term-major: same-acc MMAs are 4 issues apart (no RAW stall)
                #pragma unroll
                for (int nt = 0; nt < 4; nt++) mma16816(acc[mt][nt], ah, bh[nt]);
                #pragma unroll
                for (int nt = 0; nt < 4; nt++) mma16816(acc[mt][nt], ah, bl[nt]);
                #pragma unroll
                for (int nt = 0; nt < 4; nt++) mma16816(acc[mt][nt], al, bh[nt]);
            }
        }
        buf++; if (buf >= 3) buf = 0;
    }

    const int r = lane >> 2, q = lane & 3;
    const float g = (EPI == 1) ? *gp : 0.f;
    #pragma unroll
    for (int mt = 0; mt < 4; mt++) {
        #pragma unroll
        for (int nt = 0; nt < 4; nt++) {
            const int col = bn * 128 + wn * 32 + nt * 8 + q * 2;
            const float2 bb = *(const float2*)(bias + col);
            #pragma unroll
            for (int hh = 0; hh < 2; hh++) {
                const int row = bm * 128 + wm * 64 + mt * 16 + r + hh * 8;
                gemm_epilogue_elem<EPI>(acc[mt][nt][hh*2], acc[mt][nt][hh*2+1], bb,
                    (size_t)row * N + col, Cf, Ch, Cl, aux1, aux2, g);
            }
        }
    }
}

// ---------------- GEMM 64x128 tile -------------------------------------------
#define A64_      4096
#define B64_      8192
#define GSTAGE64  (2*A64_ + 2*B64_)     // 24576
#define GEMM64_SMEM (3*GSTAGE64)        // 73728

template<int EPI>
__global__ void __launch_bounds__(128, 3) gemm_mma64_kernel(
    const __nv_bfloat16* __restrict__ Ah, const __nv_bfloat16* __restrict__ Al,
    const __nv_bfloat16* __restrict__ Bh, const __nv_bfloat16* __restrict__ Bl,
    const float* __restrict__ bias,
    float* __restrict__ Cf, __nv_bfloat16* __restrict__ Ch, __nv_bfloat16* __restrict__ Cl,
    int M, int N, int K,
    const float* __restrict__ aux1, const float* __restrict__ aux2,
    const float* __restrict__ gp)
{
    extern __shared__ char smp[];
    const uint32_t sb = smem_to_u32(smp);
    const int tid = threadIdx.x;
    const int wn = tid >> 5, lane = tid & 31;
    const int bm = blockIdx.y, bn = blockIdx.x;
    const int NC = K >> 5;

    const size_t Abase = (size_t)bm * 64 * K;
    const size_t Bbase = (size_t)bn * 128 * K;

    float acc[4][4][4];
    #pragma unroll
    for (int i = 0; i < 4; i++)
        #pragma unroll
        for (int j = 0; j < 4; j++)
            #pragma unroll
            for (int x = 0; x < 4; x++) acc[i][j][x] = 0.f;

    const int crow = tid >> 2;
    const int cq   = tid & 3;
    const uint32_t soA = (uint32_t)(crow * 64 + ((cq ^ (crow & 3)) << 4));

    auto issue = [&](int buf, int kt) {
        const int k0 = kt << 5;
        const uint32_t sbase = sb + buf * GSTAGE64;
        const size_t gc = (size_t)crow * K + k0 + cq * 8;
        cp16(sbase + soA,                 Ah + Abase + gc);
        cp16(sbase + soA + 2048,          Ah + Abase + gc + (size_t)32 * K);
        cp16(sbase + A64_ + soA,          Al + Abase + gc);
        cp16(sbase + A64_ + soA + 2048,   Al + Abase + gc + (size_t)32 * K);
        #pragma unroll
        for (int j = 0; j < 4; j++) {
            const size_t gB = gc + (size_t)(32 * j) * K;
            cp16(sbase + 2*A64_ + soA + j*2048,        Bh + Bbase + gB);
            cp16(sbase + 2*A64_ + B64_ + soA + j*2048, Bl + Bbase + gB);
        }
    };

    issue(0, 0); CP_COMMIT();
    issue(1, 1); CP_COMMIT();

    const uint32_t rowA = (uint32_t)(lane & 15);
    const uint32_t qa   = (uint32_t)(lane >> 4);
    const uint32_t r3a  = rowA & 3;
    const uint32_t aBase = rowA * 64;
    const uint32_t rowB = (uint32_t)(wn * 32 + (lane & 7));
    const uint32_t qb   = (uint32_t)((lane >> 3) & 1);
    const uint32_t r3b  = rowB & 3;
    const uint32_t bBase = rowB * 64;

    int buf = 0;
    for (int c = 0; c < NC; c++) {
        CP_WAIT1();
        __syncthreads();
        if (c + 2 < NC) { int nb = buf + 2; if (nb >= 3) nb -= 3; issue(nb, c + 2); }
        CP_COMMIT();

        const uint32_t s0 = sb + buf * GSTAGE64;
        #pragma unroll
        for (int ks = 0; ks < 2; ks++) {
            uint32_t bh[4][2], bl[4][2];
            const uint32_t qpb = ((qb + 2*ks) ^ r3b) << 4;
            #pragma unroll
            for (int nt = 0; nt < 4; nt++) {
                const uint32_t ba = s0 + 2*A64_ + bBase + (uint32_t)(nt * 512) + qpb;
                ldsm2(bh[nt], ba);
                ldsm2(bl[nt], ba + B64_);
            }
            const uint32_t qpa = ((qa + 2*ks) ^ r3a) << 4;
            #pragma unroll
            for (int mt = 0; mt < 4; mt++) {
                uint32_t ah[4], al[4];
                const uint32_t aa = s0 + aBase + (uint32_t)(mt * 1024) + qpa;
                ldsm4(ah, aa);
                ldsm4(al, aa + A64_);
                #pragma unroll
                for (int nt = 0; nt < 4; nt++) mma16816(acc[mt][nt], ah, bh[nt]);
                #pragma unroll
                for (int nt = 0; nt < 4; nt++) mma16816(acc[mt][nt], ah, bl[nt]);
                #pragma unroll
                for (int nt = 0; nt < 4; nt++) mma16816(acc[mt][nt], al, bh[nt]);
            }
        }
        buf++; if (buf >= 3) buf = 0;
    }

    const int r = lane >> 2, q = lane & 3;
    const float g = (EPI == 1) ? *gp : 0.f;
    #pragma unroll
    for (int mt = 0; mt < 4; mt++) {
        #pragma unroll
        for (int nt = 0; nt < 4; nt++) {
            const int col = bn * 128 + wn * 32 + nt * 8 + q * 2;
            const float2 bb = *(const float2*)(bias + col);
            #pragma unroll
            for (int hh = 0; hh < 2; hh++) {
                const int row = bm * 64 + mt * 16 + r + hh * 8;
                gemm_epilogue_elem<EPI>(acc[mt][nt][hh*2], acc[mt][nt][hh*2+1], bb,
                    (size_t)row * N + col, Cf, Ch, Cl, aux1, aux2, g);
            }
        }
    }
}

// ---------------- fused attention: flash-mma (512) + memattn (2048) ---------
#define FROW 144
#define FLASH_SMEM (6*9216 + 1024)

__device__ void memattn_body(const float* __restrict__ qkv,
                             const float* __restrict__ mkv,
                             float* __restrict__ outm, int row)
{
    const int tid = threadIdx.x;
    __shared__ float sc[NH * MM];
    float4 qv = *(const float4*)(qkv + (size_t)row * 3072 + tid * 4);
    qv.x *= 0.125f; qv.y *= 0.125f; qv.z *= 0.125f; qv.w *= 0.125f;
    const float* kbase = mkv + (size_t)row * MM * 2 * DMODEL;
    const int h = tid >> 4;
    #pragma unroll 4
    for (int m = 0; m < MM; m++) {
        float4 kk = *(const float4*)(kbase + (size_t)m * 2 * DMODEL + tid * 4);
        float d = qv.x * kk.x + qv.y * kk.y + qv.z * kk.z + qv.w * kk.w;
        #pragma unroll
        for (int o = 8; o; o >>= 1) d += __shfl_xor_sync(0xffffffffu, d, o);
        if ((tid & 15) == 0) sc[h * MM + m] = d;
    }
    __syncthreads();
    if (tid < NH) {
        float mx = -1e30f;
        #pragma unroll
        for (int m = 0; m < MM; m++) mx = fmaxf(mx, sc[tid * MM + m]);
        float s = 0.f;
        #pragma unroll
        for (int m = 0; m < MM; m++) {
            float e = __expf(sc[tid * MM + m] - mx);
            sc[tid * MM + m] = e; s += e;
        }
        float inv = 1.f / s;
        #pragma unroll
        for (int m = 0; m < MM; m++) sc[tid * MM + m] *= inv;
    }
    __syncthreads();
    float4 acc = make_float4(0.f, 0.f, 0.f, 0.f);
    #pragma unroll 4
    for (int m = 0; m < MM; m++) {
        float w = sc[h * MM + m];
        float4 vv = *(const float4*)(kbase + (size_t)m * 2 * DMODEL + DMODEL + tid * 4);
        acc.x += w * vv.x; acc.y += w * vv.y; acc.z += w * vv.z; acc.w += w * vv.w;
    }
    *(float4*)(outm + (size_t)row * DMODEL + tid * 4) = acc;
}

__device__ void flash_body(const float* __restrict__ qkv,
                           __nv_bfloat16* __restrict__ outh,
                           __nv_bfloat16* __restrict__ outl,
                           char* sm, int fb)
{
    const int tid = threadIdx.x, lane = tid & 31, wid = tid >> 5;
    const int wm = wid & 3, wn = wid >> 2;
    const int qt = fb & 15, bhh = fb >> 4, b = bhh >> 4, h = bhh & 15;
    const int qbase = qt * 64;
    const size_t srow = (size_t)b * SEQ;

    char* Qh  = sm;
    char* Kh  = sm + 2*9216;
    char* Vth = sm + 4*9216;
    float* msb = (float*)(sm + 6*9216);
    float* lsb = msb + 128;

    const int lrow = tid >> 2;
    const int lc0  = (tid & 3) * 16;

    {
        const float* gq = qkv + (srow + qbase + lrow) * 3072 + h * 64 + lc0;
        char* qh = Qh + lrow * FROW + lc0 * 2;
        #pragma unroll
        for (int u = 0; u < 4; u++) {
            float4 v = *(const float4*)(gq + u * 4);
            v.x *= 0.125f; v.y *= 0.125f; v.z *= 0.125f; v.w *= 0.125f;
            *(uint32_t*)(qh + u*8)            = pack_bf2(v.x, v.y);
            *(uint32_t*)(qh + u*8 + 4)        = pack_bf2(v.z, v.w);
            *(uint32_t*)(qh + 9216 + u*8)     = pack_bf2(v.x - bf_hi(v.x), v.y - bf_hi(v.y));
            *(uint32_t*)(qh + 9216 + u*8 + 4) = pack_bf2(v.z - bf_hi(v.z), v.w - bf_hi(v.w));
        }
    }

    const int r = lane >> 2, q = lane & 3;
    float m0 = -1e30f, m1 = -1e30f, l0 = 0.f, l1 = 0.f;
    float o[8][4];
    #pragma unroll
    for (int i = 0; i < 8; i++) o[i][0]=o[i][1]=o[i][2]=o[i][3]=0.f;

    const uint32_t QA = smem_to_u32(Qh);
    const uint32_t qaddr0 = QA + (uint32_t)((wm*16 + (lane & 15)) * FROW + ((lane >> 4) & 1) * 16);
    const uint32_t kaddr0 = QA + 2*9216 + (uint32_t)((wn*32 + (lane & 7)) * FROW + ((lane >> 3) & 1) * 16);
    const uint32_t vaddr0 = QA + 4*9216 + (uint32_t)((lane & 7) * FROW + wn*64 + ((lane >> 3) & 1) * 16);

    for (int kt = 0; kt <= qt; kt++) {
        __syncthreads();
        {
            const float* gk = qkv + (srow + kt*64 + lrow) * 3072 + 1024 + h * 64 + lc0;
            char* kh = Kh + lrow * FROW + lc0 * 2;
            #pragma unroll
            for (int u = 0; u < 4; u++) {
                float4 kv = *(const float4*)(gk + u * 4);
                *(uint32_t*)(kh + u*8)            = pack_bf2(kv.x, kv.y);
                *(uint32_t*)(kh + u*8 + 4)        = pack_bf2(kv.z, kv.w);
                *(uint32_t*)(kh + 9216 + u*8)     = pack_bf2(kv.x - bf_hi(kv.x), kv.y - bf_hi(kv.y));
                *(uint32_t*)(kh + 9216 + u*8 + 4) = pack_bf2(kv.z - bf_hi(kv.z), kv.w - bf_hi(kv.w));
                float4 vv = *(const float4*)(gk + 1024 + u * 4);
                float vals[4] = {vv.x, vv.y, vv.z, vv.w};
                #pragma unroll
                for (int j = 0; j < 4; j++) {
                    const int c = lc0 + u*4 + j;
                    *(__nv_bfloat16*)(Vth + c*FROW + lrow*2) = __float2bfloat16(vals[j]);
                    *(__nv_bfloat16*)(Vth + 9216 + c*FROW + lrow*2) =
                        __float2bfloat16(vals[j] - bf_hi(vals[j]));
                }
            }
        }
        __syncthreads();

        // ---- S = Q K^T (bf16x3, term-major) ----
        float s[4][4];
        #pragma unroll
        for (int nt = 0; nt < 4; nt++) s[nt][0]=s[nt][1]=s[nt][2]=s[nt][3]=0.f;
        #pragma unroll
        for (int ks = 0; ks < 4; ks++) {
            uint32_t aQh[4], aQl[4];
            ldsm4(aQh, qaddr0 + ks*32);
            ldsm4(aQl, qaddr0 + 9216 + ks*32);
            uint32_t bKh[4][2], bKl[4][2];
            #pragma unroll
            for (int nt = 0; nt < 4; nt++) {
                const uint32_t ka = kaddr0 + (uint32_t)(nt * 8 * FROW + ks * 32);
                ldsm2(bKh[nt], ka);
                ldsm2(bKl[nt], ka + 9216);
            }
            #pragma unroll
            for (int nt = 0; nt < 4; nt++) mma16816(s[nt], aQh, bKh[nt]);
            #pragma unroll
            for (int nt = 0; nt < 4; nt++) mma16816(s[nt], aQh, bKl[nt]);
            #pragma unroll
            for (int nt = 0; nt < 4; nt++) mma16816(s[nt], aQl, bKh[nt]);
        }

        if (kt == qt) {
            const int r0 = wm*16 + r;
            #pragma unroll
            for (int nt = 0; nt < 4; nt++) {
                const int cb = wn*32 + nt*8 + q*2;
                if (cb     > r0)     s[nt][0] = -1e30f;
                if (cb + 1 > r0)     s[nt][1] = -1e30f;
                if (cb     > r0 + 8) s[nt][2] = -1e30f;
                if (cb + 1 > r0 + 8) s[nt][3] = -1e30f;
            }
        }

        // ---- online softmax stats ----
        float mx0 = fmaxf(fmaxf(s[0][0], s[0][1]), fmaxf(s[1][0], s[1][1]));
        mx0 = fmaxf(mx0, fmaxf(fmaxf(s[2][0], s[2][1]), fmaxf(s[3][0], s[3][1])));
        float mx1 = fmaxf(fmaxf(s[0][2], s[0][3]), fmaxf(s[1][2], s[1][3]));
        mx1 = fmaxf(mx1, fmaxf(fmaxf(s[2][2], s[2][3]), fmaxf(s[3][2], s[3][3])));
        mx0 = fmaxf(mx0, __shfl_xor_sync(0xffffffffu, mx0, 1));
        mx0 = fmaxf(mx0, __shfl_xor_sync(0xffffffffu, mx0, 2));
        mx1 = fmaxf(mx1, __shfl_xor_sync(0xffffffffu, mx1, 1));
        mx1 = fmaxf(mx1, __shfl_xor_sync(0xffffffffu, mx1, 2));
        if (q == 0) {
            msb[wn*64 + wm*16 + r]     = mx0;
            msb[wn*64 + wm*16 + r + 8] = mx1;
        }
        __syncthreads();
        const float mn0 = fmaxf(m0, fmaxf(mx0, msb[(1-wn)*64 + wm*16 + r]));
        const float mn1 = fmaxf(m1, fmaxf(mx1, msb[(1-wn)*64 + wm*16 + r + 8]));
        const float al0 = __expf(m0 - mn0), al1 = __expf(m1 - mn1);
        float sum0 = 0.f, sum1 = 0.f;
        #pragma unroll
        for (int nt = 0; nt < 4; nt++) {
            s[nt][0] = __expf(s[nt][0] - mn0);
            s[nt][1] = __expf(s[nt][1] - mn0);
            s[nt][2] = __expf(s[nt][2] - mn1);
            s[nt][3] = __expf(s[nt][3] - mn1);
            sum0 += s[nt][0] + s[nt][1];
            sum1 += s[nt][2] + s[nt][3];
        }
        sum0 += __shfl_xor_sync(0xffffffffu, sum0, 1);
        sum0 += __shfl_xor_sync(0xffffffffu, sum0, 2);
        sum1 += __shfl_xor_sync(0xffffffffu, sum1, 1);
        sum1 += __shfl_xor_sync(0xffffffffu, sum1, 2);
        if (q == 0) {
            lsb[wn*64 + wm*16 + r]     = sum0;
            lsb[wn*64 + wm*16 + r + 8] = sum1;
        }
        __syncthreads();
        l0 = al0 * l0 + sum0 + lsb[(1-wn)*64 + wm*16 + r];
        l1 = al1 * l1 + sum1 + lsb[(1-wn)*64 + wm*16 + r + 8];
        m0 = mn0; m1 = mn1;
        #pragma unroll
        for (int i = 0; i < 8; i++) {
            o[i][0] *= al0; o[i][1] *= al0; o[i][2] *= al1; o[i][3] *= al1;
        }

        // ---- P fragments (hi/lo) ----
        uint32_t aPh[2][4], aPl[2][4];
        #pragma unroll
        for (int ks = 0; ks < 2; ks++) {
            const int n0 = 2*ks, n1 = 2*ks + 1;
            aPh[ks][0] = pack_bf2(s[n0][0], s[n0][1]);
            aPh[ks][1] = pack_bf2(s[n0][2], s[n0][3]);
            aPh[ks][2] = pack_bf2(s[n1][0], s[n1][1]);
            aPh[ks][3] = pack_bf2(s[n1][2], s[n1][3]);
            aPl[ks][0] = pack_bf2(s[n0][0]-bf_hi(s[n0][0]), s[n0][1]-bf_hi(s[n0][1]));
            aPl[ks][1] = pack_bf2(s[n0][2]-bf_hi(s[n0][2]), s[n0][3]-bf_hi(s[n0][3]));
            aPl[ks][2] = pack_bf2(s[n1][0]-bf_hi(s[n1][0]), s[n1][1]-bf_hi(s[n1][1]));
            aPl[ks][3] = pack_bf2(s[n1][2]-bf_hi(s[n1][2]), s[n1][3]-bf_hi(s[n1][3]));
        }
        // ---- O += P V (bf16x3, term-major in groups of 4) ----
        #pragma unroll
        for (int ks = 0; ks < 2; ks++) {
            #pragma unroll
            for (int gq4 = 0; gq4 < 2; gq4++) {
                uint32_t bVh[4][2], bVl[4][2];
                #pragma unroll
                for (int j = 0; j < 4; j++) {
                    const uint32_t va = vaddr0 + (uint32_t)((gq4*4 + j) * 8 * FROW + ks * 32);
                    ldsm2(bVh[j], va);
                    ldsm2(bVl[j], va + 9216);
                }
                #pragma unroll
                for (int j = 0; j < 4; j++) mma16816(o[gq4*4+j], aPh[ks], bVh[j]);
                #pragma unroll
                for (int j = 0; j < 4; j++) mma16816(o[gq4*4+j], aPh[ks], bVl[j]);
                #pragma unroll
                for (int j = 0; j < 4; j++) mma16816(o[gq4*4+j], aPl[ks], bVh[j]);
            }
        }
    }

    // ---- combine wn partials, normalize, output ----
    __syncthreads();
    float* osum = (float*)sm;
    if (wn == 1) {
        #pragma unroll
        for (int ntv = 0; ntv < 8; ntv++) {
            const int rg = wm*16 + r, cg = ntv*8 + q*2;
            osum[rg*64 + cg]         = o[ntv][0];
            osum[rg*64 + cg + 1]     = o[ntv][1];
            osum[(rg+8)*64 + cg]     = o[ntv][2];
            osum[(rg+8)*64 + cg + 1] = o[ntv][3];
        }
    }
    __syncthreads();
    if (wn == 0) {
        const float i0 = 1.f / l0, i1 = 1.f / l1;
        #pragma unroll
        for (int ntv = 0; ntv < 8; ntv++) {
            const int rg = wm*16 + r, cg = ntv*8 + q*2;
            float v0 = (o[ntv][0] + osum[rg*64 + cg])         * i0;
            float v1 = (o[ntv][1] + osum[rg*64 + cg + 1])     * i0;
            float v2 = (o[ntv][2] + osum[(rg+8)*64 + cg])     * i1;
            float v3 = (o[ntv][3] + osum[(rg+8)*64 + cg + 1]) * i1;
            const size_t o0 = (srow + qbase + rg) * (size_t)DMODEL + h*64 + cg;
            const size_t o1 = o0 + 8 * DMODEL;
            *(uint32_t*)(outh + o0) = pack_bf2(v0, v1);
            *(uint32_t*)(outl + o0) = pack_bf2(v0 - bf_hi(v0), v1 - bf_hi(v1));
            *(uint32_t*)(outh + o1) = pack_bf2(v2, v3);
            *(uint32_t*)(outl + o1) = pack_bf2(v2 - bf_hi(v2), v3 - bf_hi(v3));
        }
    }
}

__global__ void __launch_bounds__(256) attn_kernel(
    const float* __restrict__ qkv, const float* __restrict__ mkv,
    float* __restrict__ outm,
    __nv_bfloat16* __restrict__ outh, __nv_bfloat16* __restrict__ outl)
{
    extern __shared__ char sm[];
    if (blockIdx.x < 512) {
        flash_body(qkv, outh, outl, sm, blockIdx.x);
    } else {
        memattn_body(qkv, mkv, outm, blockIdx.x - 512);
    }
}

// ------------------------------ launcher ------------------------------------
extern "C" void kernel_launch(void* const* d_in, const int* in_sizes, int n_in,
                              void* d_out, int out_size)
{
    (void)in_sizes; (void)n_in; (void)out_size;
    const float* prev  = (const float*)d_in[0];
    const float* memkv = (const float*)d_in[1];
    const float* gval  = (const float*)d_in[2];
    const float* ln1g  = (const float*)d_in[3];
    const float* ln1b  = (const float*)d_in[4];
    const float* attnw = (const float*)d_in[5];
    const float* attnb = (const float*)d_in[6];
    const float* cprw  = (const float*)d_in[7];
    const float* cprb  = (const float*)d_in[8];
    const float* ln2g  = (const float*)d_in[9];
    const float* ln2b  = (const float*)d_in[10];
    const float* fcw   = (const float*)d_in[11];
    const float* fcb   = (const float*)d_in[12];
    const float* pw    = (const float*)d_in[13];
    const float* pb    = (const float*)d_in[14];
    float* out = (float*)d_out;

    float *qkv, *mem, *hid;
    __nv_bfloat16 *h1h, *h1l, *atth, *attl, *h2h, *h2l, *ffh, *ffl;
    __nv_bfloat16 *wqh, *wql, *wph, *wpl, *wfh, *wfl, *woh, *wol;
    cudaGetSymbolAddress((void**)&qkv, g_qkv);
    cudaGetSymbolAddress((void**)&mem, g_mem);
    cudaGetSymbolAddress((void**)&hid, g_hid);
    cudaGetSymbolAddress((void**)&h1h, g_h1h);  cudaGetSymbolAddress((void**)&h1l, g_h1l);
    cudaGetSymbolAddress((void**)&atth, g_atth); cudaGetSymbolAddress((void**)&attl, g_attl);
    cudaGetSymbolAddress((void**)&h2h, g_h2h);  cudaGetSymbolAddress((void**)&h2l, g_h2l);
    cudaGetSymbolAddress((void**)&ffh, g_ffh);  cudaGetSymbolAddress((void**)&ffl, g_ffl);
    cudaGetSymbolAddress((void**)&wqh, g_wqh);  cudaGetSymbolAddress((void**)&wql, g_wql);
    cudaGetSymbolAddress((void**)&wph, g_wph);  cudaGetSymbolAddress((void**)&wpl, g_wpl);
    cudaGetSymbolAddress((void**)&wfh, g_wfh);  cudaGetSymbolAddress((void**)&wfl, g_wfl);
    cudaGetSymbolAddress((void**)&woh, g_woh);  cudaGetSymbolAddress((void**)&wol, g_wol);

    cudaFuncSetAttribute(attn_kernel, cudaFuncAttributeMaxDynamicSharedMemorySize, FLASH_SMEM);
    cudaFuncSetAttribute(gemm_mma_kernel<0>, cudaFuncAttributeMaxDynamicSharedMemorySize, GEMM_SMEM);
    cudaFuncSetAttribute(gemm_mma_kernel<2>, cudaFuncAttributeMaxDynamicSharedMemorySize, GEMM_SMEM);
    cudaFuncSetAttribute(gemm_mma64_kernel<1>, cudaFuncAttributeMaxDynamicSharedMemorySize, GEMM64_SMEM);
    cudaFuncSetAttribute(gemm_mma64_kernel<3>, cudaFuncAttributeMaxDynamicSharedMemorySize, GEMM64_SMEM);

    // 1) prep: LN1 + all weight converts (fused)
    prep_kernel<<<14336, 256>>>(prev, ln1g, ln1b, h1h, h1l,
        attnw, wqh, wql, cprw, wph, wpl, fcw, wfh, wfl, pw, woh, wol);
    // 2) qkv = h1 @ c_attn + b (f32)
    gemm_mma_kernel<0><<<dim3(24, 16), 256, GEMM_SMEM>>>(h1h, h1l, wqh, wql, attnb,
        qkv, nullptr, nullptr, ROWS, 3*DMODEL, DMODEL, nullptr, nullptr, nullptr);
    // 3) fused flash-mma + memattn
    attn_kernel<<<512 + 2048, 256, FLASH_SMEM>>>(qkv, memkv, mem, atth, attl);
    // 4) hid = (1-g)*(att@c_proj+b) + g*mem + prev
    gemm_mma64_kernel<1><<<dim3(8, 32), 128, GEMM64_SMEM>>>(atth, attl, wph, wpl, cprb,
        hid, nullptr, nullptr, ROWS, DMODEL, DMODEL, mem, prev, gval);
    // 5) LN2 -> h2 hi/lo
    prep_kernel<<<2048, 256>>>(hid, ln2g, ln2b, h2h, h2l,
        nullptr, nullptr, nullptr, nullptr, nullptr, nullptr,
        nullptr, nullptr, nullptr, nullptr, nullptr, nullptr);
    // 6) ff = gelu(h2 @ fc + b) -> hi/lo
    gemm_mma_kernel<2><<<dim3(32, 16), 256, GEMM_SMEM>>>(h2h, h2l, wfh, wfl, fcb,
        nullptr, ffh, ffl, ROWS, 4*DMODEL, DMODEL, nullptr, nullptr, nullptr);
    // 7) out = ff @ proj + b + hid
    gemm_mma64_kernel<3><<<dim3(8, 32), 128, GEMM64_SMEM>>>(ffh, ffl, woh, wol, pb,
        out, nullptr, nullptr, ROWS, DMODEL, 4*DMODEL, hid, nullptr, nullptr);
}

// round 9
// speedup vs baseline: 2.5108x; 1.3263x over previous
#include <cuda_runtime.h>
#include <cuda_fp16.h>
#include <cstdint>

#define BS_    2
#define SEQ    1024
#define DMODEL 1024
#define NH     16
#define HD     64
#define MM     32
#define ROWS   (BS_*SEQ)

// ---------------- scratch (device globals) ----------------
__device__ float g_qkv[ROWS*3*DMODEL];
__device__ float g_mem[ROWS*DMODEL];
__device__ float g_hid[ROWS*DMODEL];
__device__ __half g_h1 [ROWS*DMODEL];
__device__ __half g_att[ROWS*DMODEL];
__device__ __half g_h2 [ROWS*DMODEL];
__device__ __half g_ff [ROWS*4*DMODEL];
__device__ __half g_wqh[DMODEL*3*DMODEL], g_wql[DMODEL*3*DMODEL];
__device__ __half g_wph[DMODEL*DMODEL],   g_wpl[DMODEL*DMODEL];
__device__ __half g_wfh[DMODEL*4*DMODEL], g_wfl[DMODEL*4*DMODEL];
__device__ __half g_woh[4*DMODEL*DMODEL], g_wol[4*DMODEL*DMODEL];

// ---------------- helpers ----------------
__device__ __forceinline__ uint32_t smem_to_u32(const void* p) {
    uint32_t a;
    asm("{ .reg .u64 t; cvta.to.shared.u64 t, %1; cvt.u32.u64 %0, t; }" : "=r"(a) : "l"(p));
    return a;
}
__device__ __forceinline__ void cp16(uint32_t s, const void* g) {
    asm volatile("cp.async.cg.shared.global [%0], [%1], 16;" :: "r"(s), "l"(g));
}
#define CP_COMMIT() asm volatile("cp.async.commit_group;" ::: "memory")
#define CP_WAIT1()  asm volatile("cp.async.wait_group 1;" ::: "memory")

__device__ __forceinline__ void ldsm4(uint32_t* r, uint32_t addr) {
    asm volatile("ldmatrix.sync.aligned.m8n8.x4.shared.b16 {%0,%1,%2,%3}, [%4];"
        : "=r"(r[0]), "=r"(r[1]), "=r"(r[2]), "=r"(r[3]) : "r"(addr));
}
__device__ __forceinline__ void ldsm2(uint32_t* r, uint32_t addr) {
    asm volatile("ldmatrix.sync.aligned.m8n8.x2.shared.b16 {%0,%1}, [%2];"
        : "=r"(r[0]), "=r"(r[1]) : "r"(addr));
}
__device__ __forceinline__ void mma16816(float* d, const uint32_t* a, const uint32_t* b) {
    asm volatile(
      "mma.sync.aligned.m16n8k16.row.col.f32.f16.f16.f32 "
      "{%0,%1,%2,%3}, {%4,%5,%6,%7}, {%8,%9}, {%0,%1,%2,%3};"
      : "+f"(d[0]), "+f"(d[1]), "+f"(d[2]), "+f"(d[3])
      : "r"(a[0]), "r"(a[1]), "r"(a[2]), "r"(a[3]), "r"(b[0]), "r"(b[1]));
}

__device__ __forceinline__ float gelu_new(float x) {
    float x3 = x * x * x;
    float t  = tanhf(0.7978845608028654f * (x + 0.044715f * x3));
    return 0.5f * x * (1.f + t);
}
__device__ __forceinline__ uint32_t pack_h2(float x, float y) {
    __half2 t = __floats2half2_rn(x, y);
    return *reinterpret_cast<uint32_t*>(&t);
}
__device__ __forceinline__ float f16_hi(float x) {
    return __half2float(__float2half(x));
}

// ---------------- prep: fused 4x weight-convert + LN -----------------------
__device__ void wconv_body(float* shm,
    const float* __restrict__ W, __half* __restrict__ hi,
    __half* __restrict__ lo, int K, int N, int bx, int by)
{
    float (*s)[33] = (float(*)[33])shm;
    const int tx = threadIdx.x & 31, ty = threadIdx.x >> 5;
    const int n0 = bx * 32, k0 = by * 32;
    #pragma unroll
    for (int i = 0; i < 4; i++)
        s[ty + 8*i][tx] = W[(size_t)(k0 + ty + 8*i) * N + n0 + tx];
    __syncthreads();
    #pragma unroll
    for (int i = 0; i < 4; i++) {
        int n = ty + 8*i;
        float v = s[tx][n];
        size_t o = (size_t)(n0 + n) * K + k0 + tx;
        __half h = __float2half(v);
        hi[o] = h;
        lo[o] = __float2half(v - __half2float(h));
    }
}

__device__ void ln_body(float* shm, int row,
    const float* __restrict__ x, const float* __restrict__ g,
    const float* __restrict__ b, __half* __restrict__ y)
{
    const int tid = threadIdx.x;
    float* rs = shm; float* rs2 = shm + 8;
    const float* xr = x + (size_t)row * DMODEL;
    float4 v = *(const float4*)(xr + tid * 4);
    float s  = v.x + v.y + v.z + v.w;
    float s2 = v.x*v.x + v.y*v.y + v.z*v.z + v.w*v.w;
    #pragma unroll
    for (int o = 16; o; o >>= 1) {
        s  += __shfl_xor_sync(0xffffffffu, s,  o);
        s2 += __shfl_xor_sync(0xffffffffu, s2, o);
    }
    const int w = tid >> 5, l = tid & 31;
    if (!l) { rs[w] = s; rs2[w] = s2; }
    __syncthreads();
    s = 0.f; s2 = 0.f;
    #pragma unroll
    for (int i = 0; i < 8; i++) { s += rs[i]; s2 += rs2[i]; }
    const float mean = s * (1.f / DMODEL);
    const float var  = s2 * (1.f / DMODEL) - mean * mean;
    const float rstd = rsqrtf(var + 1e-5f);
    const int c = tid * 4;
    float4 gg = *(const float4*)(g + c);
    float4 bb = *(const float4*)(b + c);
    float4 o;
    o.x = (v.x - mean) * rstd * gg.x + bb.x;
    o.y = (v.y - mean) * rstd * gg.y + bb.y;
    o.z = (v.z - mean) * rstd * gg.z + bb.z;
    o.w = (v.w - mean) * rstd * gg.w + bb.w;
    uint2 hh;
    hh.x = pack_h2(o.x, o.y); hh.y = pack_h2(o.z, o.w);
    *(uint2*)(y + (size_t)row * DMODEL + c) = hh;
}

__global__ void __launch_bounds__(256) prep_kernel(
    const float* prev, const float* ln1g, const float* ln1b, __half* h1,
    const float* attnw, __half* wqh, __half* wql,
    const float* cprw,  __half* wph, __half* wpl,
    const float* fcw,   __half* wfh, __half* wfl,
    const float* pw,    __half* woh, __half* wol)
{
    __shared__ float shm[32*33];
    int idx = blockIdx.x;
    if (idx < 2048) { ln_body(shm, idx, prev, ln1g, ln1b, h1); return; }
    idx -= 2048;
    if (idx < 3072) { wconv_body(shm, attnw, wqh, wql, 1024, 3072, idx % 96, idx / 96); return; }
    idx -= 3072;
    if (idx < 1024) { wconv_body(shm, cprw, wph, wpl, 1024, 1024, idx % 32, idx / 32); return; }
    idx -= 1024;
    if (idx < 4096) { wconv_body(shm, fcw, wfh, wfl, 1024, 4096, idx % 128, idx / 128); return; }
    idx -= 4096;
    wconv_body(shm, pw, woh, wol, 4096, 1024, idx % 32, idx / 32);
}

// ---------------- epilogue (shared) -----------------------------------------
template<int EPI>
__device__ __forceinline__ void gemm_epilogue_elem(
    float v0, float v1, const float2 bb, size_t o,
    float* Cf, __half* Ch,
    const float* aux1, const float* aux2, float g)
{
    v0 += bb.x; v1 += bb.y;
    if (EPI == 1) {
        float2 a1 = *(const float2*)(aux1 + o);
        float2 a2 = *(const float2*)(aux2 + o);
        v0 = (1.f - g) * v0 + g * a1.x + a2.x;
        v1 = (1.f - g) * v1 + g * a1.y + a2.y;
    }
    if (EPI == 3) {
        float2 a1 = *(const float2*)(aux1 + o);
        v0 += a1.x; v1 += a1.y;
    }
    if (EPI == 2) {
        v0 = gelu_new(v0); v1 = gelu_new(v1);
        *(uint32_t*)(Ch + o) = pack_h2(v0, v1);
    } else {
        *(float2*)(Cf + o) = make_float2(v0, v1);
    }
}

// ---------------- GEMM 128x128 tile, fp16 2-term -----------------------------
// Stage: A | Bh | Bl each 128x64B = 8192B -> 24KB/stage, 3 stages = 72KB.
#define AB_     8192
#define GSTAGE  (3*AB_)                 // 24576
#define GEMM_SMEM (3*GSTAGE)            // 73728

template<int EPI>
__global__ void __launch_bounds__(256, 2) gemm_mma_kernel(
    const __half* __restrict__ A,
    const __half* __restrict__ Bh, const __half* __restrict__ Bl,
    const float* __restrict__ bias,
    float* __restrict__ Cf, __half* __restrict__ Ch,
    int M, int N, int K,
    const float* __restrict__ aux1, const float* __restrict__ aux2,
    const float* __restrict__ gp)
{
    extern __shared__ char smp[];
    const uint32_t sb = smem_to_u32(smp);
    const int tid = threadIdx.x;
    const int wid = tid >> 5, lane = tid & 31;
    const int wm = wid & 1, wn = wid >> 1;
    const int bm = blockIdx.y, bn = blockIdx.x;
    const int NC = K >> 5;

    const size_t Abase = (size_t)bm * 128 * K;
    const size_t Bbase = (size_t)bn * 128 * K;

    float acc[4][4][4];
    #pragma unroll
    for (int i = 0; i < 4; i++)
        #pragma unroll
        for (int j = 0; j < 4; j++)
            #pragma unroll
            for (int x = 0; x < 4; x++) acc[i][j][x] = 0.f;

    const int crow = tid >> 2;
    const int cq   = tid & 3;
    const uint32_t so0 = (uint32_t)(crow * 64 + ((cq ^ (crow & 3)) << 4));
    const uint32_t so1 = so0 + 64 * 64;

    auto issue = [&](int buf, int kt) {
        const int k0 = kt << 5;
        const uint32_t sbase = sb + buf * GSTAGE;
        const size_t g0 = (size_t)crow * K + k0 + cq * 8;
        const size_t g1 = g0 + (size_t)64 * K;
        cp16(sbase + so0,          A  + Abase + g0);
        cp16(sbase + so1,          A  + Abase + g1);
        cp16(sbase + AB_ + so0,    Bh + Bbase + g0);
        cp16(sbase + AB_ + so1,    Bh + Bbase + g1);
        cp16(sbase + 2*AB_ + so0,  Bl + Bbase + g0);
        cp16(sbase + 2*AB_ + so1,  Bl + Bbase + g1);
    };

    issue(0, 0); CP_COMMIT();
    issue(1, 1); CP_COMMIT();

    const uint32_t rowA = (uint32_t)(wm * 64 + (lane & 15));
    const uint32_t qa   = (uint32_t)(lane >> 4);
    const uint32_t r3a  = rowA & 3;
    const uint32_t aBase = rowA * 64;
    const uint32_t rowB = (uint32_t)(wn * 32 + (lane & 7));
    const uint32_t qb   = (uint32_t)((lane >> 3) & 1);
    const uint32_t r3b  = rowB & 3;
    const uint32_t bBase = rowB * 64;

    int buf = 0;
    for (int c = 0; c < NC; c++) {
        CP_WAIT1();
        __syncthreads();
        if (c + 2 < NC) { int nb = buf + 2; if (nb >= 3) nb -= 3; issue(nb, c + 2); }
        CP_COMMIT();

        const uint32_t s0 = sb + buf * GSTAGE;
        #pragma unroll
        for (int ks = 0; ks < 2; ks++) {
            uint32_t bh[4][2], bl[4][2];
            const uint32_t qpb = ((qb + 2*ks) ^ r3b) << 4;
            #pragma unroll
            for (int nt = 0; nt < 4; nt++) {
                const uint32_t ba = s0 + bBase + (uint32_t)(nt * 512) + qpb;
                ldsm2(bh[nt], ba + AB_);
                ldsm2(bl[nt], ba + 2*AB_);
            }
            const uint32_t qpa = ((qa + 2*ks) ^ r3a) << 4;
            #pragma unroll
            for (int mt = 0; mt < 4; mt++) {
                uint32_t a[4];
                ldsm4(a, s0 + aBase + (uint32_t)(mt * 1024) + qpa);
                #pragma unroll
                for (int nt = 0; nt < 4; nt++) mma16816(acc[mt][nt], a, bh[nt]);
                #pragma unroll
                for (int nt = 0; nt < 4; nt++) mma16816(acc[mt][nt], a, bl[nt]);
            }
        }
        buf++; if (buf >= 3) buf = 0;
    }

    const int r = lane >> 2, q = lane & 3;
    const float g = (EPI == 1) ? *gp : 0.f;
    #pragma unroll
    for (int mt = 0; mt < 4; mt++) {
        #pragma unroll
        for (int nt = 0; nt < 4; nt++) {
            const int col = bn * 128 + wn * 32 + nt * 8 + q * 2;
            const float2 bb = *(const float2*)(bias + col);
            #pragma unroll
            for (int hh = 0; hh < 2; hh++) {
                const int row = bm * 128 + wm * 64 + mt * 16 + r + hh * 8;
                gemm_epilogue_elem<EPI>(acc[mt][nt][hh*2], acc[mt][nt][hh*2+1], bb,
                    (size_t)row * N + col, Cf, Ch, aux1, aux2, g);
            }
        }
    }
}

// ---------------- GEMM 64x128 tile, fp16 2-term ------------------------------
#define A64_      4096
#define B64_      8192
#define GSTAGE64  (A64_ + 2*B64_)       // 20480
#define GEMM64_SMEM (3*GSTAGE64)        // 61440

template<int EPI>
__global__ void __launch_bounds__(128, 3) gemm_mma64_kernel(
    const __half* __restrict__ A,
    const __half* __restrict__ Bh, const __half* __restrict__ Bl,
    const float* __restrict__ bias,
    float* __restrict__ Cf, __half* __restrict__ Ch,
    int M, int N, int K,
    const float* __restrict__ aux1, const float* __restrict__ aux2,
    const float* __restrict__ gp)
{
    extern __shared__ char smp[];
    const uint32_t sb = smem_to_u32(smp);
    const int tid = threadIdx.x;
    const int wn = tid >> 5, lane = tid & 31;
    const int bm = blockIdx.y, bn = blockIdx.x;
    const int NC = K >> 5;

    const size_t Abase = (size_t)bm * 64 * K;
    const size_t Bbase = (size_t)bn * 128 * K;

    float acc[4][4][4];
    #pragma unroll
    for (int i = 0; i < 4; i++)
        #pragma unroll
        for (int j = 0; j < 4; j++)
            #pragma unroll
            for (int x = 0; x < 4; x++) acc[i][j][x] = 0.f;

    const int crow = tid >> 2;
    const int cq   = tid & 3;
    const uint32_t soA = (uint32_t)(crow * 64 + ((cq ^ (crow & 3)) << 4));

    auto issue = [&](int buf, int kt) {
        const int k0 = kt << 5;
        const uint32_t sbase = sb + buf * GSTAGE64;
        const size_t gc = (size_t)crow * K + k0 + cq * 8;
        cp16(sbase + soA,          A + Abase + gc);
        cp16(sbase + soA + 2048,   A + Abase + gc + (size_t)32 * K);
        #pragma unroll
        for (int j = 0; j < 4; j++) {
            const size_t gB = gc + (size_t)(32 * j) * K;
            cp16(sbase + A64_ + soA + j*2048,        Bh + Bbase + gB);
            cp16(sbase + A64_ + B64_ + soA + j*2048, Bl + Bbase + gB);
        }
    };

    issue(0, 0); CP_COMMIT();
    issue(1, 1); CP_COMMIT();

    const uint32_t rowA = (uint32_t)(lane & 15);
    const uint32_t qa   = (uint32_t)(lane >> 4);
    const uint32_t r3a  = rowA & 3;
    const uint32_t aBase = rowA * 64;
    const uint32_t rowB = (uint32_t)(wn * 32 + (lane & 7));
    const uint32_t qb   = (uint32_t)((lane >> 3) & 1);
    const uint32_t r3b  = rowB & 3;
    const uint32_t bBase = rowB * 64;

    int buf = 0;
    for (int c = 0; c < NC; c++) {
        CP_WAIT1();
        __syncthreads();
        if (c + 2 < NC) { int nb = buf + 2; if (nb >= 3) nb -= 3; issue(nb, c + 2); }
        CP_COMMIT();

        const uint32_t s0 = sb + buf * GSTAGE64;
        #pragma unroll
        for (int ks = 0; ks < 2; ks++) {
            uint32_t bh[4][2], bl[4][2];
            const uint32_t qpb = ((qb + 2*ks) ^ r3b) << 4;
            #pragma unroll
            for (int nt = 0; nt < 4; nt++) {
                const uint32_t ba = s0 + A64_ + bBase + (uint32_t)(nt * 512) + qpb;
                ldsm2(bh[nt], ba);
                ldsm2(bl[nt], ba + B64_);
            }
            const uint32_t qpa = ((qa + 2*ks) ^ r3a) << 4;
            #pragma unroll
            for (int mt = 0; mt < 4; mt++) {
                uint32_t a[4];
                ldsm4(a, s0 + aBase + (uint32_t)(mt * 1024) + qpa);
                #pragma unroll
                for (int nt = 0; nt < 4; nt++) mma16816(acc[mt][nt], a, bh[nt]);
                #pragma unroll
                for (int nt = 0; nt < 4; nt++) mma16816(acc[mt][nt], a, bl[nt]);
            }
        }
        buf++; if (buf >= 3) buf = 0;
    }

    const int r = lane >> 2, q = lane & 3;
    const float g = (EPI == 1) ? *gp : 0.f;
    #pragma unroll
    for (int mt = 0; mt < 4; mt++) {
        #pragma unroll
        for (int nt = 0; nt < 4; nt++) {
            const int col = bn * 128 + wn * 32 + nt * 8 + q * 2;
            const float2 bb = *(const float2*)(bias + col);
            #pragma unroll
            for (int hh = 0; hh < 2; hh++) {
                const int row = bm * 64 + mt * 16 + r + hh * 8;
                gemm_epilogue_elem<EPI>(acc[mt][nt][hh*2], acc[mt][nt][hh*2+1], bb,
                    (size_t)row * N + col, Cf, Ch, aux1, aux2, g);
            }
        }
    }
}

// ---------------- fused attention: flash-mma (512) + memattn (2048) ---------
// flash smem: Q | Kh | Kl | Vth | Vtl each [64][72] fp16 (9216B) + stats 1KB
#define FROW 144
#define FLASH_SMEM (5*9216 + 1024)

__device__ void memattn_body(const float* __restrict__ qkv,
                             const float* __restrict__ mkv,
                             float* __restrict__ outm, int row)
{
    const int tid = threadIdx.x;
    __shared__ float sc[NH * MM];
    float4 qv = *(const float4*)(qkv + (size_t)row * 3072 + tid * 4);
    qv.x *= 0.125f; qv.y *= 0.125f; qv.z *= 0.125f; qv.w *= 0.125f;
    const float* kbase = mkv + (size_t)row * MM * 2 * DMODEL;
    const int h = tid >> 4;
    #pragma unroll 4
    for (int m = 0; m < MM; m++) {
        float4 kk = *(const float4*)(kbase + (size_t)m * 2 * DMODEL + tid * 4);
        float d = qv.x * kk.x + qv.y * kk.y + qv.z * kk.z + qv.w * kk.w;
        #pragma unroll
        for (int o = 8; o; o >>= 1) d += __shfl_xor_sync(0xffffffffu, d, o);
        if ((tid & 15) == 0) sc[h * MM + m] = d;
    }
    __syncthreads();
    if (tid < NH) {
        float mx = -1e30f;
        #pragma unroll
        for (int m = 0; m < MM; m++) mx = fmaxf(mx, sc[tid * MM + m]);
        float s = 0.f;
        #pragma unroll
        for (int m = 0; m < MM; m++) {
            float e = __expf(sc[tid * MM + m] - mx);
            sc[tid * MM + m] = e; s += e;
        }
        float inv = 1.f / s;
        #pragma unroll
        for (int m = 0; m < MM; m++) sc[tid * MM + m] *= inv;
    }
    __syncthreads();
    float4 acc = make_float4(0.f, 0.f, 0.f, 0.f);
    #pragma unroll 4
    for (int m = 0; m < MM; m++) {
        float w = sc[h * MM + m];
        float4 vv = *(const float4*)(kbase + (size_t)m * 2 * DMODEL + DMODEL + tid * 4);
        acc.x += w * vv.x; acc.y += w * vv.y; acc.z += w * vv.z; acc.w += w * vv.w;
    }
    *(float4*)(outm + (size_t)row * DMODEL + tid * 4) = acc;
}

__device__ void flash_body(const float* __restrict__ qkv,
                           __half* __restrict__ outO,
                           char* sm, int fb)
{
    const int tid = threadIdx.x, lane = tid & 31, wid = tid >> 5;
    const int wm = wid & 3, wn = wid >> 2;
    const int qt = fb & 15, bhh = fb >> 4, b = bhh >> 4, h = bhh & 15;
    const int qbase = qt * 64;
    const size_t srow = (size_t)b * SEQ;

    char* Qs  = sm;                  // single
    char* Kh  = sm + 9216;           // +9216 = Kl
    char* Vth = sm + 3*9216;         // +9216 = Vtl
    float* msb = (float*)(sm + 5*9216);
    float* lsb = msb + 128;

    const int lrow = tid >> 2;
    const int lc0  = (tid & 3) * 16;

    {   // Q load, scale, single fp16
        const float* gq = qkv + (srow + qbase + lrow) * 3072 + h * 64 + lc0;
        char* qh = Qs + lrow * FROW + lc0 * 2;
        #pragma unroll
        for (int u = 0; u < 4; u++) {
            float4 v = *(const float4*)(gq + u * 4);
            *(uint32_t*)(qh + u*8)     = pack_h2(v.x * 0.125f, v.y * 0.125f);
            *(uint32_t*)(qh + u*8 + 4) = pack_h2(v.z * 0.125f, v.w * 0.125f);
        }
    }

    const int r = lane >> 2, q = lane & 3;
    float m0 = -1e30f, m1 = -1e30f, l0 = 0.f, l1 = 0.f;
    float o[8][4];
    #pragma unroll
    for (int i = 0; i < 8; i++) o[i][0]=o[i][1]=o[i][2]=o[i][3]=0.f;

    const uint32_t QA = smem_to_u32(Qs);
    const uint32_t qaddr0 = QA + (uint32_t)((wm*16 + (lane & 15)) * FROW + ((lane >> 4) & 1) * 16);
    const uint32_t kaddr0 = QA + 9216 + (uint32_t)((wn*32 + (lane & 7)) * FROW + ((lane >> 3) & 1) * 16);
    const uint32_t vaddr0 = QA + 3*9216 + (uint32_t)((lane & 7) * FROW + wn*64 + ((lane >> 3) & 1) * 16);

    for (int kt = 0; kt <= qt; kt++) {
        __syncthreads();
        {   // K hi/lo + V transposed hi/lo
            const float* gk = qkv + (srow + kt*64 + lrow) * 3072 + 1024 + h * 64 + lc0;
            char* kh = Kh + lrow * FROW + lc0 * 2;
            #pragma unroll
            for (int u = 0; u < 4; u++) {
                float4 kv = *(const float4*)(gk + u * 4);
                *(uint32_t*)(kh + u*8)            = pack_h2(kv.x, kv.y);
                *(uint32_t*)(kh + u*8 + 4)        = pack_h2(kv.z, kv.w);
                *(uint32_t*)(kh + 9216 + u*8)     = pack_h2(kv.x - f16_hi(kv.x), kv.y - f16_hi(kv.y));
                *(uint32_t*)(kh + 9216 + u*8 + 4) = pack_h2(kv.z - f16_hi(kv.z), kv.w - f16_hi(kv.w));
                float4 vv = *(const float4*)(gk + 1024 + u * 4);
                float vals[4] = {vv.x, vv.y, vv.z, vv.w};
                #pragma unroll
                for (int j = 0; j < 4; j++) {
                    const int c = lc0 + u*4 + j;
                    *(__half*)(Vth + c*FROW + lrow*2) = __float2half(vals[j]);
                    *(__half*)(Vth + 9216 + c*FROW + lrow*2) =
                        __float2half(vals[j] - f16_hi(vals[j]));
                }
            }
        }
        __syncthreads();

        // ---- S = Q K^T (fp16 2-term) ----
        float s[4][4];
        #pragma unroll
        for (int nt = 0; nt < 4; nt++) s[nt][0]=s[nt][1]=s[nt][2]=s[nt][3]=0.f;
        #pragma unroll
        for (int ks = 0; ks < 4; ks++) {
            uint32_t aQ[4];
            ldsm4(aQ, qaddr0 + ks*32);
            uint32_t bKh[4][2], bKl[4][2];
            #pragma unroll
            for (int nt = 0; nt < 4; nt++) {
                const uint32_t ka = kaddr0 + (uint32_t)(nt * 8 * FROW + ks * 32);
                ldsm2(bKh[nt], ka);
                ldsm2(bKl[nt], ka + 9216);
            }
            #pragma unroll
            for (int nt = 0; nt < 4; nt++) mma16816(s[nt], aQ, bKh[nt]);
            #pragma unroll
            for (int nt = 0; nt < 4; nt++) mma16816(s[nt], aQ, bKl[nt]);
        }

        if (kt == qt) {
            const int r0 = wm*16 + r;
            #pragma unroll
            for (int nt = 0; nt < 4; nt++) {
                const int cb = wn*32 + nt*8 + q*2;
                if (cb     > r0)     s[nt][0] = -1e30f;
                if (cb + 1 > r0)     s[nt][1] = -1e30f;
                if (cb     > r0 + 8) s[nt][2] = -1e30f;
                if (cb + 1 > r0 + 8) s[nt][3] = -1e30f;
            }
        }

        // ---- online softmax stats ----
        float mx0 = fmaxf(fmaxf(s[0][0], s[0][1]), fmaxf(s[1][0], s[1][1]));
        mx0 = fmaxf(mx0, fmaxf(fmaxf(s[2][0], s[2][1]), fmaxf(s[3][0], s[3][1])));
        float mx1 = fmaxf(fmaxf(s[0][2], s[0][3]), fmaxf(s[1][2], s[1][3]));
        mx1 = fmaxf(mx1, fmaxf(fmaxf(s[2][2], s[2][3]), fmaxf(s[3][2], s[3][3])));
        mx0 = fmaxf(mx0, __shfl_xor_sync(0xffffffffu, mx0, 1));
        mx0 = fmaxf(mx0, __shfl_xor_sync(0xffffffffu, mx0, 2));
        mx1 = fmaxf(mx1, __shfl_xor_sync(0xffffffffu, mx1, 1));
        mx1 = fmaxf(mx1, __shfl_xor_sync(0xffffffffu, mx1, 2));
        if (q == 0) {
            msb[wn*64 + wm*16 + r]     = mx0;
            msb[wn*64 + wm*16 + r + 8] = mx1;
        }
        __syncthreads();
        const float mn0 = fmaxf(m0, fmaxf(mx0, msb[(1-wn)*64 + wm*16 + r]));
        const float mn1 = fmaxf(m1, fmaxf(mx1, msb[(1-wn)*64 + wm*16 + r + 8]));
        const float al0 = __expf(m0 - mn0), al1 = __expf(m1 - mn1);
        float sum0 = 0.f, sum1 = 0.f;
        #pragma unroll
        for (int nt = 0; nt < 4; nt++) {
            s[nt][0] = __expf(s[nt][0] - mn0);
            s[nt][1] = __expf(s[nt][1] - mn0);
            s[nt][2] = __expf(s[nt][2] - mn1);
            s[nt][3] = __expf(s[nt][3] - mn1);
            sum0 += s[nt][0] + s[nt][1];
            sum1 += s[nt][2] + s[nt][3];
        }
        sum0 += __shfl_xor_sync(0xffffffffu, sum0, 1);
        sum0 += __shfl_xor_sync(0xffffffffu, sum0, 2);
        sum1 += __shfl_xor_sync(0xffffffffu, sum1, 1);
        sum1 += __shfl_xor_sync(0xffffffffu, sum1, 2);
        if (q == 0) {
            lsb[wn*64 + wm*16 + r]     = sum0;
            lsb[wn*64 + wm*16 + r + 8] = sum1;
        }
        __syncthreads();
        l0 = al0 * l0 + sum0 + lsb[(1-wn)*64 + wm*16 + r];
        l1 = al1 * l1 + sum1 + lsb[(1-wn)*64 + wm*16 + r + 8];
        m0 = mn0; m1 = mn1;
        #pragma unroll
        for (int i = 0; i < 8; i++) {
            o[i][0] *= al0; o[i][1] *= al0; o[i][2] *= al1; o[i][3] *= al1;
        }

        // ---- P fragments (single fp16; P in [0,1]) ----
        uint32_t aP[2][4];
        #pragma unroll
        for (int ks = 0; ks < 2; ks++) {
            const int n0 = 2*ks, n1 = 2*ks + 1;
            aP[ks][0] = pack_h2(s[n0][0], s[n0][1]);
            aP[ks][1] = pack_h2(s[n0][2], s[n0][3]);
            aP[ks][2] = pack_h2(s[n1][0], s[n1][1]);
            aP[ks][3] = pack_h2(s[n1][2], s[n1][3]);
        }
        // ---- O += P V (fp16 2-term, groups of 4) ----
        #pragma unroll
        for (int ks = 0; ks < 2; ks++) {
            #pragma unroll
            for (int gq4 = 0; gq4 < 2; gq4++) {
                uint32_t bVh[4][2], bVl[4][2];
                #pragma unroll
                for (int j = 0; j < 4; j++) {
                    const uint32_t va = vaddr0 + (uint32_t)((gq4*4 + j) * 8 * FROW + ks * 32);
                    ldsm2(bVh[j], va);
                    ldsm2(bVl[j], va + 9216);
                }
                #pragma unroll
                for (int j = 0; j < 4; j++) mma16816(o[gq4*4+j], aP[ks], bVh[j]);
                #pragma unroll
                for (int j = 0; j < 4; j++) mma16816(o[gq4*4+j], aP[ks], bVl[j]);
            }
        }
    }

    // ---- combine wn partials, normalize, output (single fp16) ----
    __syncthreads();
    float* osum = (float*)sm;        // reuses Q + Kh regions (18432B >= 16384)
    if (wn == 1) {
        #pragma unroll
        for (int ntv = 0; ntv < 8; ntv++) {
            const int rg = wm*16 + r, cg = ntv*8 + q*2;
            osum[rg*64 + cg]         = o[ntv][0];
            osum[rg*64 + cg + 1]     = o[ntv][1];
            osum[(rg+8)*64 + cg]     = o[ntv][2];
            osum[(rg+8)*64 + cg + 1] = o[ntv][3];
        }
    }
    __syncthreads();
    if (wn == 0) {
        const float i0 = 1.f / l0, i1 = 1.f / l1;
        #pragma unroll
        for (int ntv = 0; ntv < 8; ntv++) {
            const int rg = wm*16 + r, cg = ntv*8 + q*2;
            float v0 = (o[ntv][0] + osum[rg*64 + cg])         * i0;
            float v1 = (o[ntv][1] + osum[rg*64 + cg + 1])     * i0;
            float v2 = (o[ntv][2] + osum[(rg+8)*64 + cg])     * i1;
            float v3 = (o[ntv][3] + osum[(rg+8)*64 + cg + 1]) * i1;
            const size_t o0 = (srow + qbase + rg) * (size_t)DMODEL + h*64 + cg;
            const size_t o1 = o0 + 8 * DMODEL;
            *(uint32_t*)(outO + o0) = pack_h2(v0, v1);
            *(uint32_t*)(outO + o1) = pack_h2(v2, v3);
        }
    }
}

__global__ void __launch_bounds__(256) attn_kernel(
    const float* __restrict__ qkv, const float* __restrict__ mkv,
    float* __restrict__ outm, __half* __restrict__ outO)
{
    extern __shared__ char sm[];
    if (blockIdx.x < 512) {
        flash_body(qkv, outO, sm, blockIdx.x);
    } else {
        memattn_body(qkv, mkv, outm, blockIdx.x - 512);
    }
}

// ------------------------------ launcher ------------------------------------
extern "C" void kernel_launch(void* const* d_in, const int* in_sizes, int n_in,
                              void* d_out, int out_size)
{
    (void)in_sizes; (void)n_in; (void)out_size;
    const float* prev  = (const float*)d_in[0];
    const float* memkv = (const float*)d_in[1];
    const float* gval  = (const float*)d_in[2];
    const float* ln1g  = (const float*)d_in[3];
    const float* ln1b  = (const float*)d_in[4];
    const float* attnw = (const float*)d_in[5];
    const float* attnb = (const float*)d_in[6];
    const float* cprw  = (const float*)d_in[7];
    const float* cprb  = (const float*)d_in[8];
    const float* ln2g  = (const float*)d_in[9];
    const float* ln2b  = (const float*)d_in[10];
    const float* fcw   = (const float*)d_in[11];
    const float* fcb   = (const float*)d_in[12];
    const float* pw    = (const float*)d_in[13];
    const float* pb    = (const float*)d_in[14];
    float* out = (float*)d_out;

    float *qkv, *mem, *hid;
    __half *h1, *att, *h2, *ff;
    __half *wqh, *wql, *wph, *wpl, *wfh, *wfl, *woh, *wol;
    cudaGetSymbolAddress((void**)&qkv, g_qkv);
    cudaGetSymbolAddress((void**)&mem, g_mem);
    cudaGetSymbolAddress((void**)&hid, g_hid);
    cudaGetSymbolAddress((void**)&h1,  g_h1);
    cudaGetSymbolAddress((void**)&att, g_att);
    cudaGetSymbolAddress((void**)&h2,  g_h2);
    cudaGetSymbolAddress((void**)&ff,  g_ff);
    cudaGetSymbolAddress((void**)&wqh, g_wqh);  cudaGetSymbolAddress((void**)&wql, g_wql);
    cudaGetSymbolAddress((void**)&wph, g_wph);  cudaGetSymbolAddress((void**)&wpl, g_wpl);
    cudaGetSymbolAddress((void**)&wfh, g_wfh);  cudaGetSymbolAddress((void**)&wfl, g_wfl);
    cudaGetSymbolAddress((void**)&woh, g_woh);  cudaGetSymbolAddress((void**)&wol, g_wol);

    cudaFuncSetAttribute(attn_kernel, cudaFuncAttributeMaxDynamicSharedMemorySize, FLASH_SMEM);
    cudaFuncSetAttribute(gemm_mma_kernel<0>, cudaFuncAttributeMaxDynamicSharedMemorySize, GEMM_SMEM);
    cudaFuncSetAttribute(gemm_mma_kernel<2>, cudaFuncAttributeMaxDynamicSharedMemorySize, GEMM_SMEM);
    cudaFuncSetAttribute(gemm_mma64_kernel<1>, cudaFuncAttributeMaxDynamicSharedMemorySize, GEMM64_SMEM);
    cudaFuncSetAttribute(gemm_mma64_kernel<3>, cudaFuncAttributeMaxDynamicSharedMemorySize, GEMM64_SMEM);

    // 1) prep: LN1 + all weight converts (fused)
    prep_kernel<<<14336, 256>>>(prev, ln1g, ln1b, h1,
        attnw, wqh, wql, cprw, wph, wpl, fcw, wfh, wfl, pw, woh, wol);
    // 2) qkv = h1 @ c_attn + b (f32)
    gemm_mma_kernel<0><<<dim3(24, 16), 256, GEMM_SMEM>>>(h1, wqh, wql, attnb,
        qkv, nullptr, ROWS, 3*DMODEL, DMODEL, nullptr, nullptr, nullptr);
    // 3) fused flash-mma + memattn
    attn_kernel<<<512 + 2048, 256, FLASH_SMEM>>>(qkv, memkv, mem, att);
    // 4) hid = (1-g)*(att@c_proj+b) + g*mem + prev
    gemm_mma64_kernel<1><<<dim3(8, 32), 128, GEMM64_SMEM>>>(att, wph, wpl, cprb,
        hid, nullptr, ROWS, DMODEL, DMODEL, mem, prev, gval);
    // 5) LN2 -> h2
    prep_kernel<<<2048, 256>>>(hid, ln2g, ln2b, h2,
        nullptr, nullptr, nullptr, nullptr, nullptr, nullptr,
        nullptr, nullptr, nullptr, nullptr, nullptr, nullptr);
    // 6) ff = gelu(h2 @ fc + b) -> fp16
    gemm_mma_kernel<2><<<dim3(32, 16), 256, GEMM_SMEM>>>(h2, wfh, wfl, fcb,
        nullptr, ff, ROWS, 4*DMODEL, DMODEL, nullptr, nullptr, nullptr);
    // 7) out = ff @ proj + b + hid
    gemm_mma64_kernel<3><<<dim3(8, 32), 128, GEMM64_SMEM>>>(ff, woh, wol, pb,
        out, nullptr, ROWS, DMODEL, 4*DMODEL, hid, nullptr, nullptr);
}

// round 10
// speedup vs baseline: 3.4077x; 1.3572x over previous
#include <cuda_runtime.h>
#include <cuda_fp16.h>
#include <cstdint>

#define BS_    2
#define SEQ    1024
#define DMODEL 1024
#define NH     16
#define HD     64
#define MM     32
#define ROWS   (BS_*SEQ)

// ---------------- scratch (device globals) ----------------
__device__ float g_qkv[ROWS*3*DMODEL];
__device__ float g_mem[ROWS*DMODEL];
__device__ float g_hid[ROWS*DMODEL];
__device__ __half g_h1 [ROWS*DMODEL];
__device__ __half g_att[ROWS*DMODEL];
__device__ __half g_h2 [ROWS*DMODEL];
__device__ __half g_ff [ROWS*4*DMODEL];
__device__ __half g_wq[DMODEL*3*DMODEL];
__device__ __half g_wp[DMODEL*DMODEL];
__device__ __half g_wf[DMODEL*4*DMODEL];
__device__ __half g_wo[4*DMODEL*DMODEL];

// ---------------- helpers ----------------
__device__ __forceinline__ uint32_t smem_to_u32(const void* p) {
    uint32_t a;
    asm("{ .reg .u64 t; cvta.to.shared.u64 t, %1; cvt.u32.u64 %0, t; }" : "=r"(a) : "l"(p));
    return a;
}
__device__ __forceinline__ void cp16(uint32_t s, const void* g) {
    asm volatile("cp.async.cg.shared.global [%0], [%1], 16;" :: "r"(s), "l"(g));
}
#define CP_COMMIT() asm volatile("cp.async.commit_group;" ::: "memory")
#define CP_WAIT1()  asm volatile("cp.async.wait_group 1;" ::: "memory")

__device__ __forceinline__ void ldsm4(uint32_t* r, uint32_t addr) {
    asm volatile("ldmatrix.sync.aligned.m8n8.x4.shared.b16 {%0,%1,%2,%3}, [%4];"
        : "=r"(r[0]), "=r"(r[1]), "=r"(r[2]), "=r"(r[3]) : "r"(addr));
}
__device__ __forceinline__ void ldsm2(uint32_t* r, uint32_t addr) {
    asm volatile("ldmatrix.sync.aligned.m8n8.x2.shared.b16 {%0,%1}, [%2];"
        : "=r"(r[0]), "=r"(r[1]) : "r"(addr));
}
__device__ __forceinline__ void mma16816(float* d, const uint32_t* a, const uint32_t* b) {
    asm volatile(
      "mma.sync.aligned.m16n8k16.row.col.f32.f16.f16.f32 "
      "{%0,%1,%2,%3}, {%4,%5,%6,%7}, {%8,%9}, {%0,%1,%2,%3};"
      : "+f"(d[0]), "+f"(d[1]), "+f"(d[2]), "+f"(d[3])
      : "r"(a[0]), "r"(a[1]), "r"(a[2]), "r"(a[3]), "r"(b[0]), "r"(b[1]));
}

__device__ __forceinline__ float gelu_new(float x) {
    float x3 = x * x * x;
    float t  = tanhf(0.7978845608028654f * (x + 0.044715f * x3));
    return 0.5f * x * (1.f + t);
}
__device__ __forceinline__ uint32_t pack_h2(float x, float y) {
    __half2 t = __floats2half2_rn(x, y);
    return *reinterpret_cast<uint32_t*>(&t);
}

// ---------------- prep: fused 4x weight-convert + LN -----------------------
__device__ void wconv_body(float* shm,
    const float* __restrict__ W, __half* __restrict__ hi,
    int K, int N, int bx, int by)
{
    float (*s)[33] = (float(*)[33])shm;
    const int tx = threadIdx.x & 31, ty = threadIdx.x >> 5;
    const int n0 = bx * 32, k0 = by * 32;
    #pragma unroll
    for (int i = 0; i < 4; i++)
        s[ty + 8*i][tx] = W[(size_t)(k0 + ty + 8*i) * N + n0 + tx];
    __syncthreads();
    #pragma unroll
    for (int i = 0; i < 4; i++) {
        int n = ty + 8*i;
        hi[(size_t)(n0 + n) * K + k0 + tx] = __float2half(s[tx][n]);
    }
}

__device__ void ln_body(float* shm, int row,
    const float* __restrict__ x, const float* __restrict__ g,
    const float* __restrict__ b, __half* __restrict__ y)
{
    const int tid = threadIdx.x;
    float* rs = shm; float* rs2 = shm + 8;
    const float* xr = x + (size_t)row * DMODEL;
    float4 v = *(const float4*)(xr + tid * 4);
    float s  = v.x + v.y + v.z + v.w;
    float s2 = v.x*v.x + v.y*v.y + v.z*v.z + v.w*v.w;
    #pragma unroll
    for (int o = 16; o; o >>= 1) {
        s  += __shfl_xor_sync(0xffffffffu, s,  o);
        s2 += __shfl_xor_sync(0xffffffffu, s2, o);
    }
    const int w = tid >> 5, l = tid & 31;
    if (!l) { rs[w] = s; rs2[w] = s2; }
    __syncthreads();
    s = 0.f; s2 = 0.f;
    #pragma unroll
    for (int i = 0; i < 8; i++) { s += rs[i]; s2 += rs2[i]; }
    const float mean = s * (1.f / DMODEL);
    const float var  = s2 * (1.f / DMODEL) - mean * mean;
    const float rstd = rsqrtf(var + 1e-5f);
    const int c = tid * 4;
    float4 gg = *(const float4*)(g + c);
    float4 bb = *(const float4*)(b + c);
    float4 o;
    o.x = (v.x - mean) * rstd * gg.x + bb.x;
    o.y = (v.y - mean) * rstd * gg.y + bb.y;
    o.z = (v.z - mean) * rstd * gg.z + bb.z;
    o.w = (v.w - mean) * rstd * gg.w + bb.w;
    uint2 hh;
    hh.x = pack_h2(o.x, o.y); hh.y = pack_h2(o.z, o.w);
    *(uint2*)(y + (size_t)row * DMODEL + c) = hh;
}

__global__ void __launch_bounds__(256) prep_kernel(
    const float* prev, const float* ln1g, const float* ln1b, __half* h1,
    const float* attnw, __half* wq,
    const float* cprw,  __half* wp,
    const float* fcw,   __half* wf,
    const float* pw,    __half* wo)
{
    __shared__ float shm[32*33];
    int idx = blockIdx.x;
    if (idx < 2048) { ln_body(shm, idx, prev, ln1g, ln1b, h1); return; }
    idx -= 2048;
    if (idx < 3072) { wconv_body(shm, attnw, wq, 1024, 3072, idx % 96, idx / 96); return; }
    idx -= 3072;
    if (idx < 1024) { wconv_body(shm, cprw, wp, 1024, 1024, idx % 32, idx / 32); return; }
    idx -= 1024;
    if (idx < 4096) { wconv_body(shm, fcw, wf, 1024, 4096, idx % 128, idx / 128); return; }
    idx -= 4096;
    wconv_body(shm, pw, wo, 4096, 1024, idx % 32, idx / 32);
}

// ---------------- epilogue (shared) -----------------------------------------
template<int EPI>
__device__ __forceinline__ void gemm_epilogue_elem(
    float v0, float v1, const float2 bb, size_t o,
    float* Cf, __half* Ch,
    const float* aux1, const float* aux2, float g)
{
    v0 += bb.x; v1 += bb.y;
    if (EPI == 1) {
        float2 a1 = *(const float2*)(aux1 + o);
        float2 a2 = *(const float2*)(aux2 + o);
        v0 = (1.f - g) * v0 + g * a1.x + a2.x;
        v1 = (1.f - g) * v1 + g * a1.y + a2.y;
    }
    if (EPI == 3) {
        float2 a1 = *(const float2*)(aux1 + o);
        v0 += a1.x; v1 += a1.y;
    }
    if (EPI == 2) {
        v0 = gelu_new(v0); v1 = gelu_new(v1);
        *(uint32_t*)(Ch + o) = pack_h2(v0, v1);
    } else {
        *(float2*)(Cf + o) = make_float2(v0, v1);
    }
}

// ---------------- GEMM 128x128 tile, fp16 single -----------------------------
// Stage: A | B each 128x64B = 8192B -> 16KB/stage, 3 stages = 48KB.
#define AB_     8192
#define GSTAGE  (2*AB_)                 // 16384
#define GEMM_SMEM (3*GSTAGE)            // 49152

template<int EPI>
__global__ void __launch_bounds__(256, 2) gemm_mma_kernel(
    const __half* __restrict__ A, const __half* __restrict__ B,
    const float* __restrict__ bias,
    float* __restrict__ Cf, __half* __restrict__ Ch,
    int M, int N, int K,
    const float* __restrict__ aux1, const float* __restrict__ aux2,
    const float* __restrict__ gp)
{
    extern __shared__ char smp[];
    const uint32_t sb = smem_to_u32(smp);
    const int tid = threadIdx.x;
    const int wid = tid >> 5, lane = tid & 31;
    const int wm = wid & 1, wn = wid >> 1;
    const int bm = blockIdx.y, bn = blockIdx.x;
    const int NC = K >> 5;

    const size_t Abase = (size_t)bm * 128 * K;
    const size_t Bbase = (size_t)bn * 128 * K;

    float acc[4][4][4];
    #pragma unroll
    for (int i = 0; i < 4; i++)
        #pragma unroll
        for (int j = 0; j < 4; j++)
            #pragma unroll
            for (int x = 0; x < 4; x++) acc[i][j][x] = 0.f;

    const int crow = tid >> 2;
    const int cq   = tid & 3;
    const uint32_t so0 = (uint32_t)(crow * 64 + ((cq ^ (crow & 3)) << 4));
    const uint32_t so1 = so0 + 64 * 64;

    auto issue = [&](int buf, int kt) {
        const int k0 = kt << 5;
        const uint32_t sbase = sb + buf * GSTAGE;
        const size_t g0 = (size_t)crow * K + k0 + cq * 8;
        const size_t g1 = g0 + (size_t)64 * K;
        cp16(sbase + so0,        A + Abase + g0);
        cp16(sbase + so1,        A + Abase + g1);
        cp16(sbase + AB_ + so0,  B + Bbase + g0);
        cp16(sbase + AB_ + so1,  B + Bbase + g1);
    };

    issue(0, 0); CP_COMMIT();
    issue(1, 1); CP_COMMIT();

    const uint32_t rowA = (uint32_t)(wm * 64 + (lane & 15));
    const uint32_t qa   = (uint32_t)(lane >> 4);
    const uint32_t r3a  = rowA & 3;
    const uint32_t aBase = rowA * 64;
    const uint32_t rowB = (uint32_t)(wn * 32 + (lane & 7));
    const uint32_t qb   = (uint32_t)((lane >> 3) & 1);
    const uint32_t r3b  = rowB & 3;
    const uint32_t bBase = rowB * 64;

    int buf = 0;
    for (int c = 0; c < NC; c++) {
        CP_WAIT1();
        __syncthreads();
        if (c + 2 < NC) { int nb = buf + 2; if (nb >= 3) nb -= 3; issue(nb, c + 2); }
        CP_COMMIT();

        const uint32_t s0 = sb + buf * GSTAGE;
        #pragma unroll
        for (int ks = 0; ks < 2; ks++) {
            uint32_t bfr[4][2];
            const uint32_t qpb = ((qb + 2*ks) ^ r3b) << 4;
            #pragma unroll
            for (int nt = 0; nt < 4; nt++)
                ldsm2(bfr[nt], s0 + AB_ + bBase + (uint32_t)(nt * 512) + qpb);
            const uint32_t qpa = ((qa + 2*ks) ^ r3a) << 4;
            #pragma unroll
            for (int mt = 0; mt < 4; mt++) {
                uint32_t a[4];
                ldsm4(a, s0 + aBase + (uint32_t)(mt * 1024) + qpa);
                #pragma unroll
                for (int nt = 0; nt < 4; nt++) mma16816(acc[mt][nt], a, bfr[nt]);
            }
        }
        buf++; if (buf >= 3) buf = 0;
    }

    const int r = lane >> 2, q = lane & 3;
    const float g = (EPI == 1) ? *gp : 0.f;
    #pragma unroll
    for (int mt = 0; mt < 4; mt++) {
        #pragma unroll
        for (int nt = 0; nt < 4; nt++) {
            const int col = bn * 128 + wn * 32 + nt * 8 + q * 2;
            const float2 bb = *(const float2*)(bias + col);
            #pragma unroll
            for (int hh = 0; hh < 2; hh++) {
                const int row = bm * 128 + wm * 64 + mt * 16 + r + hh * 8;
                gemm_epilogue_elem<EPI>(acc[mt][nt][hh*2], acc[mt][nt][hh*2+1], bb,
                    (size_t)row * N + col, Cf, Ch, aux1, aux2, g);
            }
        }
    }
}

// ---------------- GEMM 64x128 tile, fp16 single ------------------------------
#define A64_      4096
#define B64_      8192
#define GSTAGE64  (A64_ + B64_)         // 12288
#define GEMM64_SMEM (3*GSTAGE64)        // 36864

template<int EPI>
__global__ void __launch_bounds__(128, 3) gemm_mma64_kernel(
    const __half* __restrict__ A, const __half* __restrict__ B,
    const float* __restrict__ bias,
    float* __restrict__ Cf, __half* __restrict__ Ch,
    int M, int N, int K,
    const float* __restrict__ aux1, const float* __restrict__ aux2,
    const float* __restrict__ gp)
{
    extern __shared__ char smp[];
    const uint32_t sb = smem_to_u32(smp);
    const int tid = threadIdx.x;
    const int wn = tid >> 5, lane = tid & 31;
    const int bm = blockIdx.y, bn = blockIdx.x;
    const int NC = K >> 5;

    const size_t Abase = (size_t)bm * 64 * K;
    const size_t Bbase = (size_t)bn * 128 * K;

    float acc[4][4][4];
    #pragma unroll
    for (int i = 0; i < 4; i++)
        #pragma unroll
        for (int j = 0; j < 4; j++)
            #pragma unroll
            for (int x = 0; x < 4; x++) acc[i][j][x] = 0.f;

    const int crow = tid >> 2;
    const int cq   = tid & 3;
    const uint32_t soA = (uint32_t)(crow * 64 + ((cq ^ (crow & 3)) << 4));

    auto issue = [&](int buf, int kt) {
        const int k0 = kt << 5;
        const uint32_t sbase = sb + buf * GSTAGE64;
        const size_t gc = (size_t)crow * K + k0 + cq * 8;
        cp16(sbase + soA,          A + Abase + gc);
        cp16(sbase + soA + 2048,   A + Abase + gc + (size_t)32 * K);
        #pragma unroll
        for (int j = 0; j < 4; j++)
            cp16(sbase + A64_ + soA + j*2048, B + Bbase + gc + (size_t)(32 * j) * K);
    };

    issue(0, 0); CP_COMMIT();
    issue(1, 1); CP_COMMIT();

    const uint32_t rowA = (uint32_t)(lane & 15);
    const uint32_t qa   = (uint32_t)(lane >> 4);
    const uint32_t r3a  = rowA & 3;
    const uint32_t aBase = rowA * 64;
    const uint32_t rowB = (uint32_t)(wn * 32 + (lane & 7));
    const uint32_t qb   = (uint32_t)((lane >> 3) & 1);
    const uint32_t r3b  = rowB & 3;
    const uint32_t bBase = rowB * 64;

    int buf = 0;
    for (int c = 0; c < NC; c++) {
        CP_WAIT1();
        __syncthreads();
        if (c + 2 < NC) { int nb = buf + 2; if (nb >= 3) nb -= 3; issue(nb, c + 2); }
        CP_COMMIT();

        const uint32_t s0 = sb + buf * GSTAGE64;
        #pragma unroll
        for (int ks = 0; ks < 2; ks++) {
            uint32_t bfr[4][2];
            const uint32_t qpb = ((qb + 2*ks) ^ r3b) << 4;
            #pragma unroll
            for (int nt = 0; nt < 4; nt++)
                ldsm2(bfr[nt], s0 + A64_ + bBase + (uint32_t)(nt * 512) + qpb);
            const uint32_t qpa = ((qa + 2*ks) ^ r3a) << 4;
            #pragma unroll
            for (int mt = 0; mt < 4; mt++) {
                uint32_t a[4];
                ldsm4(a, s0 + aBase + (uint32_t)(mt * 1024) + qpa);
                #pragma unroll
                for (int nt = 0; nt < 4; nt++) mma16816(acc[mt][nt], a, bfr[nt]);
            }
        }
        buf++; if (buf >= 3) buf = 0;
    }

    const int r = lane >> 2, q = lane & 3;
    const float g = (EPI == 1) ? *gp : 0.f;
    #pragma unroll
    for (int mt = 0; mt < 4; mt++) {
        #pragma unroll
        for (int nt = 0; nt < 4; nt++) {
            const int col = bn * 128 + wn * 32 + nt * 8 + q * 2;
            const float2 bb = *(const float2*)(bias + col);
            #pragma unroll
            for (int hh = 0; hh < 2; hh++) {
                const int row = bm * 64 + mt * 16 + r + hh * 8;
                gemm_epilogue_elem<EPI>(acc[mt][nt][hh*2], acc[mt][nt][hh*2+1], bb,
                    (size_t)row * N + col, Cf, Ch, aux1, aux2, g);
            }
        }
    }
}

// ---------------- fused attention: flash-mma (512) + memattn (2048) ---------
// flash smem: Q | K | Vt each [64][72] fp16 (9216B) + stats 1KB
#define FROW 144
#define FLASH_SMEM (3*9216 + 1024)

__device__ void memattn_body(const float* __restrict__ qkv,
                             const float* __restrict__ mkv,
                             float* __restrict__ outm, int row)
{
    const int tid = threadIdx.x;
    __shared__ float sc[NH * MM];
    float4 qv = *(const float4*)(qkv + (size_t)row * 3072 + tid * 4);
    qv.x *= 0.125f; qv.y *= 0.125f; qv.z *= 0.125f; qv.w *= 0.125f;
    const float* kbase = mkv + (size_t)row * MM * 2 * DMODEL;
    const int h = tid >> 4;
    #pragma unroll 4
    for (int m = 0; m < MM; m++) {
        float4 kk = *(const float4*)(kbase + (size_t)m * 2 * DMODEL + tid * 4);
        float d = qv.x * kk.x + qv.y * kk.y + qv.z * kk.z + qv.w * kk.w;
        #pragma unroll
        for (int o = 8; o; o >>= 1) d += __shfl_xor_sync(0xffffffffu, d, o);
        if ((tid & 15) == 0) sc[h * MM + m] = d;
    }
    __syncthreads();
    if (tid < NH) {
        float mx = -1e30f;
        #pragma unroll
        for (int m = 0; m < MM; m++) mx = fmaxf(mx, sc[tid * MM + m]);
        float s = 0.f;
        #pragma unroll
        for (int m = 0; m < MM; m++) {
            float e = __expf(sc[tid * MM + m] - mx);
            sc[tid * MM + m] = e; s += e;
        }
        float inv = 1.f / s;
        #pragma unroll
        for (int m = 0; m < MM; m++) sc[tid * MM + m] *= inv;
    }
    __syncthreads();
    float4 acc = make_float4(0.f, 0.f, 0.f, 0.f);
    #pragma unroll 4
    for (int m = 0; m < MM; m++) {
        float w = sc[h * MM + m];
        float4 vv = *(const float4*)(kbase + (size_t)m * 2 * DMODEL + DMODEL + tid * 4);
        acc.x += w * vv.x; acc.y += w * vv.y; acc.z += w * vv.z; acc.w += w * vv.w;
    }
    *(float4*)(outm + (size_t)row * DMODEL + tid * 4) = acc;
}

__device__ void flash_body(const float* __restrict__ qkv,
                           __half* __restrict__ outO,
                           char* sm, int fb)
{
    const int tid = threadIdx.x, lane = tid & 31, wid = tid >> 5;
    const int wm = wid & 3, wn = wid >> 2;
    const int qt = fb & 15, bhh = fb >> 4, b = bhh >> 4, h = bhh & 15;
    const int qbase = qt * 64;
    const size_t srow = (size_t)b * SEQ;

    char* Qs  = sm;
    char* Ks  = sm + 9216;
    char* Vth = sm + 2*9216;
    float* msb = (float*)(sm + 3*9216);
    float* lsb = msb + 128;

    const int lrow = tid >> 2;
    const int lc0  = (tid & 3) * 16;

    {   // Q load, scale
        const float* gq = qkv + (srow + qbase + lrow) * 3072 + h * 64 + lc0;
        char* qh = Qs + lrow * FROW + lc0 * 2;
        #pragma unroll
        for (int u = 0; u < 4; u++) {
            float4 v = *(const float4*)(gq + u * 4);
            *(uint32_t*)(qh + u*8)     = pack_h2(v.x * 0.125f, v.y * 0.125f);
            *(uint32_t*)(qh + u*8 + 4) = pack_h2(v.z * 0.125f, v.w * 0.125f);
        }
    }

    const int r = lane >> 2, q = lane & 3;
    float m0 = -1e30f, m1 = -1e30f, l0 = 0.f, l1 = 0.f;
    float o[8][4];
    #pragma unroll
    for (int i = 0; i < 8; i++) o[i][0]=o[i][1]=o[i][2]=o[i][3]=0.f;

    const uint32_t QA = smem_to_u32(Qs);
    const uint32_t qaddr0 = QA + (uint32_t)((wm*16 + (lane & 15)) * FROW + ((lane >> 4) & 1) * 16);
    const uint32_t kaddr0 = QA + 9216 + (uint32_t)((wn*32 + (lane & 7)) * FROW + ((lane >> 3) & 1) * 16);
    const uint32_t vaddr0 = QA + 2*9216 + (uint32_t)((lane & 7) * FROW + wn*64 + ((lane >> 3) & 1) * 16);

    for (int kt = 0; kt <= qt; kt++) {
        __syncthreads();
        {   // K + V transposed (single fp16)
            const float* gk = qkv + (srow + kt*64 + lrow) * 3072 + 1024 + h * 64 + lc0;
            char* kh = Ks + lrow * FROW + lc0 * 2;
            #pragma unroll
            for (int u = 0; u < 4; u++) {
                float4 kv = *(const float4*)(gk + u * 4);
                *(uint32_t*)(kh + u*8)     = pack_h2(kv.x, kv.y);
                *(uint32_t*)(kh + u*8 + 4) = pack_h2(kv.z, kv.w);
                float4 vv = *(const float4*)(gk + 1024 + u * 4);
                float vals[4] = {vv.x, vv.y, vv.z, vv.w};
                #pragma unroll
                for (int j = 0; j < 4; j++) {
                    const int c = lc0 + u*4 + j;
                    *(__half*)(Vth + c*FROW + lrow*2) = __float2half(vals[j]);
                }
            }
        }
        __syncthreads();

        // ---- S = Q K^T (fp16 single) ----
        float s[4][4];
        #pragma unroll
        for (int nt = 0; nt < 4; nt++) s[nt][0]=s[nt][1]=s[nt][2]=s[nt][3]=0.f;
        #pragma unroll
        for (int ks = 0; ks < 4; ks++) {
            uint32_t aQ[4];
            ldsm4(aQ, qaddr0 + ks*32);
            uint32_t bK[4][2];
            #pragma unroll
            for (int nt = 0; nt < 4; nt++)
                ldsm2(bK[nt], kaddr0 + (uint32_t)(nt * 8 * FROW + ks * 32));
            #pragma unroll
            for (int nt = 0; nt < 4; nt++) mma16816(s[nt], aQ, bK[nt]);
        }

        if (kt == qt) {
            const int r0 = wm*16 + r;
            #pragma unroll
            for (int nt = 0; nt < 4; nt++) {
                const int cb = wn*32 + nt*8 + q*2;
                if (cb     > r0)     s[nt][0] = -1e30f;
                if (cb + 1 > r0)     s[nt][1] = -1e30f;
                if (cb     > r0 + 8) s[nt][2] = -1e30f;
                if (cb + 1 > r0 + 8) s[nt][3] = -1e30f;
            }
        }

        // ---- online softmax stats ----
        float mx0 = fmaxf(fmaxf(s[0][0], s[0][1]), fmaxf(s[1][0], s[1][1]));
        mx0 = fmaxf(mx0, fmaxf(fmaxf(s[2][0], s[2][1]), fmaxf(s[3][0], s[3][1])));
        float mx1 = fmaxf(fmaxf(s[0][2], s[0][3]), fmaxf(s[1][2], s[1][3]));
        mx1 = fmaxf(mx1, fmaxf(fmaxf(s[2][2], s[2][3]), fmaxf(s[3][2], s[3][3])));
        mx0 = fmaxf(mx0, __shfl_xor_sync(0xffffffffu, mx0, 1));
        mx0 = fmaxf(mx0, __shfl_xor_sync(0xffffffffu, mx0, 2));
        mx1 = fmaxf(mx1, __shfl_xor_sync(0xffffffffu, mx1, 1));
        mx1 = fmaxf(mx1, __shfl_xor_sync(0xffffffffu, mx1, 2));
        if (q == 0) {
            msb[wn*64 + wm*16 + r]     = mx0;
            msb[wn*64 + wm*16 + r + 8] = mx1;
        }
        __syncthreads();
        const float mn0 = fmaxf(m0, fmaxf(mx0, msb[(1-wn)*64 + wm*16 + r]));
        const float mn1 = fmaxf(m1, fmaxf(mx1, msb[(1-wn)*64 + wm*16 + r + 8]));
        const float al0 = __expf(m0 - mn0), al1 = __expf(m1 - mn1);
        float sum0 = 0.f, sum1 = 0.f;
        #pragma unroll
        for (int nt = 0; nt < 4; nt++) {
            s[nt][0] = __expf(s[nt][0] - mn0);
            s[nt][1] = __expf(s[nt][1] - mn0);
            s[nt][2] = __expf(s[nt][2] - mn1);
            s[nt][3] = __expf(s[nt][3] - mn1);
            sum0 += s[nt][0] + s[nt][1];
            sum1 += s[nt][2] + s[nt][3];
        }
        sum0 += __shfl_xor_sync(0xffffffffu, sum0, 1);
        sum0 += __shfl_xor_sync(0xffffffffu, sum0, 2);
        sum1 += __shfl_xor_sync(0xffffffffu, sum1, 1);
        sum1 += __shfl_xor_sync(0xffffffffu, sum1, 2);
        if (q == 0) {
            lsb[wn*64 + wm*16 + r]     = sum0;
            lsb[wn*64 + wm*16 + r + 8] = sum1;
        }
        __syncthreads();
        l0 = al0 * l0 + sum0 + lsb[(1-wn)*64 + wm*16 + r];
        l1 = al1 * l1 + sum1 + lsb[(1-wn)*64 + wm*16 + r + 8];
        m0 = mn0; m1 = mn1;
        #pragma unroll
        for (int i = 0; i < 8; i++) {
            o[i][0] *= al0; o[i][1] *= al0; o[i][2] *= al1; o[i][3] *= al1;
        }

        // ---- P fragments (single fp16) ----
        uint32_t aP[2][4];
        #pragma unroll
        for (int ks = 0; ks < 2; ks++) {
            const int n0 = 2*ks, n1 = 2*ks + 1;
            aP[ks][0] = pack_h2(s[n0][0], s[n0][1]);
            aP[ks][1] = pack_h2(s[n0][2], s[n0][3]);
            aP[ks][2] = pack_h2(s[n1][0], s[n1][1]);
            aP[ks][3] = pack_h2(s[n1][2], s[n1][3]);
        }
        // ---- O += P V (fp16 single, groups of 4) ----
        #pragma unroll
        for (int ks = 0; ks < 2; ks++) {
            #pragma unroll
            for (int gq4 = 0; gq4 < 2; gq4++) {
                uint32_t bV[4][2];
                #pragma unroll
                for (int j = 0; j < 4; j++)
                    ldsm2(bV[j], vaddr0 + (uint32_t)((gq4*4 + j) * 8 * FROW + ks * 32));
                #pragma unroll
                for (int j = 0; j < 4; j++) mma16816(o[gq4*4+j], aP[ks], bV[j]);
            }
        }
    }

    // ---- combine wn partials, normalize, output ----
    __syncthreads();
    float* osum = (float*)sm;        // reuses Q+K regions (18432B >= 16384)
    if (wn == 1) {
        #pragma unroll
        for (int ntv = 0; ntv < 8; ntv++) {
            const int rg = wm*16 + r, cg = ntv*8 + q*2;
            osum[rg*64 + cg]         = o[ntv][0];
            osum[rg*64 + cg + 1]     = o[ntv][1];
            osum[(rg+8)*64 + cg]     = o[ntv][2];
            osum[(rg+8)*64 + cg + 1] = o[ntv][3];
        }
    }
    __syncthreads();
    if (wn == 0) {
        const float i0 = 1.f / l0, i1 = 1.f / l1;
        #pragma unroll
        for (int ntv = 0; ntv < 8; ntv++) {
            const int rg = wm*16 + r, cg = ntv*8 + q*2;
            float v0 = (o[ntv][0] + osum[rg*64 + cg])         * i0;
            float v1 = (o[ntv][1] + osum[rg*64 + cg + 1])     * i0;
            float v2 = (o[ntv][2] + osum[(rg+8)*64 + cg])     * i1;
            float v3 = (o[ntv][3] + osum[(rg+8)*64 + cg + 1]) * i1;
            const size_t o0 = (srow + qbase + rg) * (size_t)DMODEL + h*64 + cg;
            const size_t o1 = o0 + 8 * DMODEL;
            *(uint32_t*)(outO + o0) = pack_h2(v0, v1);
            *(uint32_t*)(outO + o1) = pack_h2(v2, v3);
        }
    }
}

__global__ void __launch_bounds__(256) attn_kernel(
    const float* __restrict__ qkv, const float* __restrict__ mkv,
    float* __restrict__ outm, __half* __restrict__ outO)
{
    extern __shared__ char sm[];
    if (blockIdx.x < 512) {
        flash_body(qkv, outO, sm, blockIdx.x);
    } else {
        memattn_body(qkv, mkv, outm, blockIdx.x - 512);
    }
}

// ------------------------------ launcher ------------------------------------
extern "C" void kernel_launch(void* const* d_in, const int* in_sizes, int n_in,
                              void* d_out, int out_size)
{
    (void)in_sizes; (void)n_in; (void)out_size;
    const float* prev  = (const float*)d_in[0];
    const float* memkv = (const float*)d_in[1];
    const float* gval  = (const float*)d_in[2];
    const float* ln1g  = (const float*)d_in[3];
    const float* ln1b  = (const float*)d_in[4];
    const float* attnw = (const float*)d_in[5];
    const float* attnb = (const float*)d_in[6];
    const float* cprw  = (const float*)d_in[7];
    const float* cprb  = (const float*)d_in[8];
    const float* ln2g  = (const float*)d_in[9];
    const float* ln2b  = (const float*)d_in[10];
    const float* fcw   = (const float*)d_in[11];
    const float* fcb   = (const float*)d_in[12];
    const float* pw    = (const float*)d_in[13];
    const float* pb    = (const float*)d_in[14];
    float* out = (float*)d_out;

    float *qkv, *mem, *hid;
    __half *h1, *att, *h2, *ff, *wq, *wp, *wf, *wo;
    cudaGetSymbolAddress((void**)&qkv, g_qkv);
    cudaGetSymbolAddress((void**)&mem, g_mem);
    cudaGetSymbolAddress((void**)&hid, g_hid);
    cudaGetSymbolAddress((void**)&h1,  g_h1);
    cudaGetSymbolAddress((void**)&att, g_att);
    cudaGetSymbolAddress((void**)&h2,  g_h2);
    cudaGetSymbolAddress((void**)&ff,  g_ff);
    cudaGetSymbolAddress((void**)&wq,  g_wq);
    cudaGetSymbolAddress((void**)&wp,  g_wp);
    cudaGetSymbolAddress((void**)&wf,  g_wf);
    cudaGetSymbolAddress((void**)&wo,  g_wo);

    cudaFuncSetAttribute(attn_kernel, cudaFuncAttributeMaxDynamicSharedMemorySize, FLASH_SMEM);
    cudaFuncSetAttribute(gemm_mma_kernel<0>, cudaFuncAttributeMaxDynamicSharedMemorySize, GEMM_SMEM);
    cudaFuncSetAttribute(gemm_mma_kernel<2>, cudaFuncAttributeMaxDynamicSharedMemorySize, GEMM_SMEM);
    cudaFuncSetAttribute(gemm_mma64_kernel<1>, cudaFuncAttributeMaxDynamicSharedMemorySize, GEMM64_SMEM);
    cudaFuncSetAttribute(gemm_mma64_kernel<3>, cudaFuncAttributeMaxDynamicSharedMemorySize, GEMM64_SMEM);

    // 1) prep: LN1 + all weight converts (fused)
    prep_kernel<<<14336, 256>>>(prev, ln1g, ln1b, h1,
        attnw, wq, cprw, wp, fcw, wf, pw, wo);
    // 2) qkv = h1 @ c_attn + b (f32)
    gemm_mma_kernel<0><<<dim3(24, 16), 256, GEMM_SMEM>>>(h1, wq, attnb,
        qkv, nullptr, ROWS, 3*DMODEL, DMODEL, nullptr, nullptr, nullptr);
    // 3) fused flash-mma + memattn
    attn_kernel<<<512 + 2048, 256, FLASH_SMEM>>>(qkv, memkv, mem, att);
    // 4) hid = (1-g)*(att@c_proj+b) + g*mem + prev
    gemm_mma64_kernel<1><<<dim3(8, 32), 128, GEMM64_SMEM>>>(att, wp, cprb,
        hid, nullptr, ROWS, DMODEL, DMODEL, mem, prev, gval);
    // 5) LN2 -> h2
    prep_kernel<<<2048, 256>>>(hid, ln2g, ln2b, h2,
        nullptr, nullptr, nullptr, nullptr, nullptr, nullptr, nullptr, nullptr);
    // 6) ff = gelu(h2 @ fc + b) -> fp16
    gemm_mma_kernel<2><<<dim3(32, 16), 256, GEMM_SMEM>>>(h2, wf, fcb,
        nullptr, ff, ROWS, 4*DMODEL, DMODEL, nullptr, nullptr, nullptr);
    // 7) out = ff @ proj + b + hid
    gemm_mma64_kernel<3><<<dim3(8, 32), 128, GEMM64_SMEM>>>(ff, wo, pb,
        out, nullptr, ROWS, DMODEL, 4*DMODEL, hid, nullptr, nullptr);
}

// round 11
// speedup vs baseline: 3.5202x; 1.0330x over previous
#include <cuda_runtime.h>
#include <cuda_fp16.h>
#include <cstdint>

#define BS_    2
#define SEQ    1024
#define DMODEL 1024
#define NH     16
#define HD     64
#define MM     32
#define ROWS   (BS_*SEQ)

// ---------------- scratch (device globals) ----------------
__device__ __half g_qkv[ROWS*3*DMODEL];
__device__ float g_mem[ROWS*DMODEL];
__device__ float g_hid[ROWS*DMODEL];
__device__ __half g_h1 [ROWS*DMODEL];
__device__ __half g_att[ROWS*DMODEL];
__device__ __half g_h2 [ROWS*DMODEL];
__device__ __half g_ff [ROWS*4*DMODEL];
__device__ __half g_wq[DMODEL*3*DMODEL];
__device__ __half g_wp[DMODEL*DMODEL];
__device__ __half g_wf[DMODEL*4*DMODEL];
__device__ __half g_wo[4*DMODEL*DMODEL];

// ---------------- helpers ----------------
__device__ __forceinline__ uint32_t smem_to_u32(const void* p) {
    uint32_t a;
    asm("{ .reg .u64 t; cvta.to.shared.u64 t, %1; cvt.u32.u64 %0, t; }" : "=r"(a) : "l"(p));
    return a;
}
__device__ __forceinline__ void cp16(uint32_t s, const void* g) {
    asm volatile("cp.async.cg.shared.global [%0], [%1], 16;" :: "r"(s), "l"(g));
}
#define CP_COMMIT() asm volatile("cp.async.commit_group;" ::: "memory")
#define CP_WAIT1()  asm volatile("cp.async.wait_group 1;" ::: "memory")

__device__ __forceinline__ void ldsm4(uint32_t* r, uint32_t addr) {
    asm volatile("ldmatrix.sync.aligned.m8n8.x4.shared.b16 {%0,%1,%2,%3}, [%4];"
        : "=r"(r[0]), "=r"(r[1]), "=r"(r[2]), "=r"(r[3]) : "r"(addr));
}
__device__ __forceinline__ void ldsm2(uint32_t* r, uint32_t addr) {
    asm volatile("ldmatrix.sync.aligned.m8n8.x2.shared.b16 {%0,%1}, [%2];"
        : "=r"(r[0]), "=r"(r[1]) : "r"(addr));
}
__device__ __forceinline__ void ldsm2t(uint32_t* r, uint32_t addr) {
    asm volatile("ldmatrix.sync.aligned.m8n8.x2.trans.shared.b16 {%0,%1}, [%2];"
        : "=r"(r[0]), "=r"(r[1]) : "r"(addr));
}
__device__ __forceinline__ void mma16816(float* d, const uint32_t* a, const uint32_t* b) {
    asm volatile(
      "mma.sync.aligned.m16n8k16.row.col.f32.f16.f16.f32 "
      "{%0,%1,%2,%3}, {%4,%5,%6,%7}, {%8,%9}, {%0,%1,%2,%3};"
      : "+f"(d[0]), "+f"(d[1]), "+f"(d[2]), "+f"(d[3])
      : "r"(a[0]), "r"(a[1]), "r"(a[2]), "r"(a[3]), "r"(b[0]), "r"(b[1]));
}

__device__ __forceinline__ float gelu_new(float x) {
    float x3 = x * x * x;
    float t  = tanhf(0.7978845608028654f * (x + 0.044715f * x3));
    return 0.5f * x * (1.f + t);
}
__device__ __forceinline__ uint32_t pack_h2(float x, float y) {
    __half2 t = __floats2half2_rn(x, y);
    return *reinterpret_cast<uint32_t*>(&t);
}

// ---------------- prep: fused 4x weight-convert + LN -----------------------
__device__ void wconv_body(float* shm,
    const float* __restrict__ W, __half* __restrict__ hi,
    int K, int N, int bx, int by)
{
    float (*s)[33] = (float(*)[33])shm;
    const int tx = threadIdx.x & 31, ty = threadIdx.x >> 5;
    const int n0 = bx * 32, k0 = by * 32;
    #pragma unroll
    for (int i = 0; i < 4; i++)
        s[ty + 8*i][tx] = W[(size_t)(k0 + ty + 8*i) * N + n0 + tx];
    __syncthreads();
    #pragma unroll
    for (int i = 0; i < 4; i++) {
        int n = ty + 8*i;
        hi[(size_t)(n0 + n) * K + k0 + tx] = __float2half(s[tx][n]);
    }
}

__device__ void ln_body(float* shm, int row,
    const float* __restrict__ x, const float* __restrict__ g,
    const float* __restrict__ b, __half* __restrict__ y)
{
    const int tid = threadIdx.x;
    float* rs = shm; float* rs2 = shm + 8;
    const float* xr = x + (size_t)row * DMODEL;
    float4 v = *(const float4*)(xr + tid * 4);
    float s  = v.x + v.y + v.z + v.w;
    float s2 = v.x*v.x + v.y*v.y + v.z*v.z + v.w*v.w;
    #pragma unroll
    for (int o = 16; o; o >>= 1) {
        s  += __shfl_xor_sync(0xffffffffu, s,  o);
        s2 += __shfl_xor_sync(0xffffffffu, s2, o);
    }
    const int w = tid >> 5, l = tid & 31;
    if (!l) { rs[w] = s; rs2[w] = s2; }
    __syncthreads();
    s = 0.f; s2 = 0.f;
    #pragma unroll
    for (int i = 0; i < 8; i++) { s += rs[i]; s2 += rs2[i]; }
    const float mean = s * (1.f / DMODEL);
    const float var  = s2 * (1.f / DMODEL) - mean * mean;
    const float rstd = rsqrtf(var + 1e-5f);
    const int c = tid * 4;
    float4 gg = *(const float4*)(g + c);
    float4 bb = *(const float4*)(b + c);
    float4 o;
    o.x = (v.x - mean) * rstd * gg.x + bb.x;
    o.y = (v.y - mean) * rstd * gg.y + bb.y;
    o.z = (v.z - mean) * rstd * gg.z + bb.z;
    o.w = (v.w - mean) * rstd * gg.w + bb.w;
    uint2 hh;
    hh.x = pack_h2(o.x, o.y); hh.y = pack_h2(o.z, o.w);
    *(uint2*)(y + (size_t)row * DMODEL + c) = hh;
}

__global__ void __launch_bounds__(256) prep_kernel(
    const float* prev, const float* ln1g, const float* ln1b, __half* h1,
    const float* attnw, __half* wq,
    const float* cprw,  __half* wp,
    const float* fcw,   __half* wf,
    const float* pw,    __half* wo)
{
    __shared__ float shm[32*33];
    int idx = blockIdx.x;
    if (idx < 2048) { ln_body(shm, idx, prev, ln1g, ln1b, h1); return; }
    idx -= 2048;
    if (idx < 3072) { wconv_body(shm, attnw, wq, 1024, 3072, idx % 96, idx / 96); return; }
    idx -= 3072;
    if (idx < 1024) { wconv_body(shm, cprw, wp, 1024, 1024, idx % 32, idx / 32); return; }
    idx -= 1024;
    if (idx < 4096) { wconv_body(shm, fcw, wf, 1024, 4096, idx % 128, idx / 128); return; }
    idx -= 4096;
    wconv_body(shm, pw, wo, 4096, 1024, idx % 32, idx / 32);
}

// ---------------- epilogue (shared) -----------------------------------------
// EPI 1: gated+residual->f32 | 2: gelu->fp16 | 3: +aux1->f32 | 4: ->fp16
template<int EPI>
__device__ __forceinline__ void gemm_epilogue_elem(
    float v0, float v1, const float2 bb, size_t o,
    float* Cf, __half* Ch,
    const float* aux1, const float* aux2, float g)
{
    v0 += bb.x; v1 += bb.y;
    if (EPI == 1) {
        float2 a1 = *(const float2*)(aux1 + o);
        float2 a2 = *(const float2*)(aux2 + o);
        v0 = (1.f - g) * v0 + g * a1.x + a2.x;
        v1 = (1.f - g) * v1 + g * a1.y + a2.y;
    }
    if (EPI == 3) {
        float2 a1 = *(const float2*)(aux1 + o);
        v0 += a1.x; v1 += a1.y;
    }
    if (EPI == 2) {
        v0 = gelu_new(v0); v1 = gelu_new(v1);
        *(uint32_t*)(Ch + o) = pack_h2(v0, v1);
    } else if (EPI == 4) {
        *(uint32_t*)(Ch + o) = pack_h2(v0, v1);
    } else {
        *(float2*)(Cf + o) = make_float2(v0, v1);
    }
}

// ---------------- GEMM 128x128 tile, fp16, K-chunk 64 ------------------------
// Stage: A0|A1|B0|B1 each 128x64B -> 32KB/stage, 3 stages = 96KB, 2 CTAs/SM.
#define AB_     8192
#define GSTAGE  (4*AB_)                 // 32768
#define GEMM_SMEM (3*GSTAGE)            // 98304

template<int EPI>
__global__ void __launch_bounds__(256, 2) gemm_mma_kernel(
    const __half* __restrict__ A, const __half* __restrict__ B,
    const float* __restrict__ bias,
    float* __restrict__ Cf, __half* __restrict__ Ch,
    int M, int N, int K,
    const float* __restrict__ aux1, const float* __restrict__ aux2,
    const float* __restrict__ gp)
{
    extern __shared__ char smp[];
    const uint32_t sb = smem_to_u32(smp);
    const int tid = threadIdx.x;
    const int wid = tid >> 5, lane = tid & 31;
    const int wm = wid & 1, wn = wid >> 1;
    const int bm = blockIdx.y, bn = blockIdx.x;
    const int NC = K >> 6;

    const size_t Abase = (size_t)bm * 128 * K;
    const size_t Bbase = (size_t)bn * 128 * K;

    float acc[4][4][4];
    #pragma unroll
    for (int i = 0; i < 4; i++)
        #pragma unroll
        for (int j = 0; j < 4; j++)
            #pragma unroll
            for (int x = 0; x < 4; x++) acc[i][j][x] = 0.f;

    const int crow = tid >> 2;
    const int cq   = tid & 3;
    const uint32_t so0 = (uint32_t)(crow * 64 + ((cq ^ (crow & 3)) << 4));
    const uint32_t so1 = so0 + 64 * 64;

    auto issue = [&](int buf, int kt) {
        const int k0 = kt << 6;
        const uint32_t sbase = sb + buf * GSTAGE;
        const size_t g0 = (size_t)crow * K + k0 + cq * 8;
        const size_t g1 = g0 + (size_t)64 * K;
        #pragma unroll
        for (int sl = 0; sl < 2; sl++) {
            cp16(sbase + sl*AB_ + so0,          A + Abase + g0 + sl*32);
            cp16(sbase + sl*AB_ + so1,          A + Abase + g1 + sl*32);
            cp16(sbase + (2+sl)*AB_ + so0,      B + Bbase + g0 + sl*32);
            cp16(sbase + (2+sl)*AB_ + so1,      B + Bbase + g1 + sl*32);
        }
    };

    issue(0, 0); CP_COMMIT();
    issue(1, 1); CP_COMMIT();

    const uint32_t rowA = (uint32_t)(wm * 64 + (lane & 15));
    const uint32_t qa   = (uint32_t)(lane >> 4);
    const uint32_t r3a  = rowA & 3;
    const uint32_t aBase = rowA * 64;
    const uint32_t rowB = (uint32_t)(wn * 32 + (lane & 7));
    const uint32_t qb   = (uint32_t)((lane >> 3) & 1);
    const uint32_t r3b  = rowB & 3;
    const uint32_t bBase = rowB * 64;

    int buf = 0;
    for (int c = 0; c < NC; c++) {
        CP_WAIT1();
        __syncthreads();
        if (c + 2 < NC) { int nb = buf + 2; if (nb >= 3) nb -= 3; issue(nb, c + 2); }
        CP_COMMIT();

        const uint32_t s0 = sb + buf * GSTAGE;
        #pragma unroll
        for (int sl = 0; sl < 2; sl++) {
            const uint32_t sA = s0 + sl*AB_;
            const uint32_t sB = s0 + (2+sl)*AB_;
            #pragma unroll
            for (int ks = 0; ks < 2; ks++) {
                uint32_t bfr[4][2];
                const uint32_t qpb = ((qb + 2*ks) ^ r3b) << 4;
                #pragma unroll
                for (int nt = 0; nt < 4; nt++)
                    ldsm2(bfr[nt], sB + bBase + (uint32_t)(nt * 512) + qpb);
                const uint32_t qpa = ((qa + 2*ks) ^ r3a) << 4;
                #pragma unroll
                for (int mt = 0; mt < 4; mt++) {
                    uint32_t a[4];
                    ldsm4(a, sA + aBase + (uint32_t)(mt * 1024) + qpa);
                    #pragma unroll
                    for (int nt = 0; nt < 4; nt++) mma16816(acc[mt][nt], a, bfr[nt]);
                }
            }
        }
        buf++; if (buf >= 3) buf = 0;
    }

    const int r = lane >> 2, q = lane & 3;
    const float g = (EPI == 1) ? *gp : 0.f;
    #pragma unroll
    for (int mt = 0; mt < 4; mt++) {
        #pragma unroll
        for (int nt = 0; nt < 4; nt++) {
            const int col = bn * 128 + wn * 32 + nt * 8 + q * 2;
            const float2 bb = *(const float2*)(bias + col);
            #pragma unroll
            for (int hh = 0; hh < 2; hh++) {
                const int row = bm * 128 + wm * 64 + mt * 16 + r + hh * 8;
                gemm_epilogue_elem<EPI>(acc[mt][nt][hh*2], acc[mt][nt][hh*2+1], bb,
                    (size_t)row * N + col, Cf, Ch, aux1, aux2, g);
            }
        }
    }
}

// ---------------- GEMM 64x128 tile, fp16, K-chunk 64 -------------------------
#define A64_      4096
#define B64_      8192
#define GSTAGE64  (2*A64_ + 2*B64_)     // 24576
#define GEMM64_SMEM (3*GSTAGE64)        // 73728

template<int EPI>
__global__ void __launch_bounds__(128, 3) gemm_mma64_kernel(
    const __half* __restrict__ A, const __half* __restrict__ B,
    const float* __restrict__ bias,
    float* __restrict__ Cf, __half* __restrict__ Ch,
    int M, int N, int K,
    const float* __restrict__ aux1, const float* __restrict__ aux2,
    const float* __restrict__ gp)
{
    extern __shared__ char smp[];
    const uint32_t sb = smem_to_u32(smp);
    const int tid = threadIdx.x;
    const int wn = tid >> 5, lane = tid & 31;
    const int bm = blockIdx.y, bn = blockIdx.x;
    const int NC = K >> 6;

    const size_t Abase = (size_t)bm * 64 * K;
    const size_t Bbase = (size_t)bn * 128 * K;

    float acc[4][4][4];
    #pragma unroll
    for (int i = 0; i < 4; i++)
        #pragma unroll
        for (int j = 0; j < 4; j++)
            #pragma unroll
            for (int x = 0; x < 4; x++) acc[i][j][x] = 0.f;

    const int crow = tid >> 2;
    const int cq   = tid & 3;
    const uint32_t soA = (uint32_t)(crow * 64 + ((cq ^ (crow & 3)) << 4));

    auto issue = [&](int buf, int kt) {
        const int k0 = kt << 6;
        const uint32_t sbase = sb + buf * GSTAGE64;
        const size_t gc = (size_t)crow * K + k0 + cq * 8;
        #pragma unroll
        for (int sl = 0; sl < 2; sl++) {
            cp16(sbase + sl*A64_ + soA,        A + Abase + gc + sl*32);
            cp16(sbase + sl*A64_ + soA + 2048, A + Abase + gc + sl*32 + (size_t)32 * K);
            #pragma unroll
            for (int j = 0; j < 4; j++)
                cp16(sbase + 2*A64_ + sl*B64_ + soA + j*2048,
                     B + Bbase + gc + sl*32 + (size_t)(32 * j) * K);
        }
    };

    issue(0, 0); CP_COMMIT();
    issue(1, 1); CP_COMMIT();

    const uint32_t rowA = (uint32_t)(lane & 15);
    const uint32_t qa   = (uint32_t)(lane >> 4);
    const uint32_t r3a  = rowA & 3;
    const uint32_t aBase = rowA * 64;
    const uint32_t rowB = (uint32_t)(wn * 32 + (lane & 7));
    const uint32_t qb   = (uint32_t)((lane >> 3) & 1);
    const uint32_t r3b  = rowB & 3;
    const uint32_t bBase = rowB * 64;

    int buf = 0;
    for (int c = 0; c < NC; c++) {
        CP_WAIT1();
        __syncthreads();
        if (c + 2 < NC) { int nb = buf + 2; if (nb >= 3) nb -= 3; issue(nb, c + 2); }
        CP_COMMIT();

        const uint32_t s0 = sb + buf * GSTAGE64;
        #pragma unroll
        for (int sl = 0; sl < 2; sl++) {
            const uint32_t sA = s0 + sl*A64_;
            const uint32_t sB = s0 + 2*A64_ + sl*B64_;
            #pragma unroll
            for (int ks = 0; ks < 2; ks++) {
                uint32_t bfr[4][2];
                const uint32_t qpb = ((qb + 2*ks) ^ r3b) << 4;
                #pragma unroll
                for (int nt = 0; nt < 4; nt++)
                    ldsm2(bfr[nt], sB + bBase + (uint32_t)(nt * 512) + qpb);
                const uint32_t qpa = ((qa + 2*ks) ^ r3a) << 4;
                #pragma unroll
                for (int mt = 0; mt < 4; mt++) {
                    uint32_t a[4];
                    ldsm4(a, sA + aBase + (uint32_t)(mt * 1024) + qpa);
                    #pragma unroll
                    for (int nt = 0; nt < 4; nt++) mma16816(acc[mt][nt], a, bfr[nt]);
                }
            }
        }
        buf++; if (buf >= 3) buf = 0;
    }

    const int r = lane >> 2, q = lane & 3;
    const float g = (EPI == 1) ? *gp : 0.f;
    #pragma unroll
    for (int mt = 0; mt < 4; mt++) {
        #pragma unroll
        for (int nt = 0; nt < 4; nt++) {
            const int col = bn * 128 + wn * 32 + nt * 8 + q * 2;
            const float2 bb = *(const float2*)(bias + col);
            #pragma unroll
            for (int hh = 0; hh < 2; hh++) {
                const int row = bm * 64 + mt * 16 + r + hh * 8;
                gemm_epilogue_elem<EPI>(acc[mt][nt][hh*2], acc[mt][nt][hh*2+1], bb,
                    (size_t)row * N + col, Cf, Ch, aux1, aux2, g);
            }
        }
    }
}

// ---------------- fused attention: flash-mma (512) + memattn (2048) ---------
// flash smem: Q | K | V each [64][72] fp16 rows (144B) + stats 1KB
#define FROW 144
#define FLASH_SMEM (3*9216 + 1024)

__device__ void memattn_body(const __half* __restrict__ qkv,
                             const float* __restrict__ mkv,
                             float* __restrict__ outm, int row)
{
    const int tid = threadIdx.x;
    __shared__ float sc[NH * MM];
    uint2 qraw = *(const uint2*)(qkv + (size_t)row * 3072 + tid * 4);
    __half2 qa = *(__half2*)&qraw.x, qb = *(__half2*)&qraw.y;
    float4 qv;
    qv.x = __low2float(qa) * 0.125f;  qv.y = __high2float(qa) * 0.125f;
    qv.z = __low2float(qb) * 0.125f;  qv.w = __high2float(qb) * 0.125f;
    const float* kbase = mkv + (size_t)row * MM * 2 * DMODEL;
    const int h = tid >> 4;
    #pragma unroll 4
    for (int m = 0; m < MM; m++) {
        float4 kk = *(const float4*)(kbase + (size_t)m * 2 * DMODEL + tid * 4);
        float d = qv.x * kk.x + qv.y * kk.y + qv.z * kk.z + qv.w * kk.w;
        #pragma unroll
        for (int o = 8; o; o >>= 1) d += __shfl_xor_sync(0xffffffffu, d, o);
        if ((tid & 15) == 0) sc[h * MM + m] = d;
    }
    __syncthreads();
    if (tid < NH) {
        float mx = -1e30f;
        #pragma unroll
        for (int m = 0; m < MM; m++) mx = fmaxf(mx, sc[tid * MM + m]);
        float s = 0.f;
        #pragma unroll
        for (int m = 0; m < MM; m++) {
            float e = __expf(sc[tid * MM + m] - mx);
            sc[tid * MM + m] = e; s += e;
        }
        float inv = 1.f / s;
        #pragma unroll
        for (int m = 0; m < MM; m++) sc[tid * MM + m] *= inv;
    }
    __syncthreads();
    float4 acc = make_float4(0.f, 0.f, 0.f, 0.f);
    #pragma unroll 4
    for (int m = 0; m < MM; m++) {
        float w = sc[h * MM + m];
        float4 vv = *(const float4*)(kbase + (size_t)m * 2 * DMODEL + DMODEL + tid * 4);
        acc.x += w * vv.x; acc.y += w * vv.y; acc.z += w * vv.z; acc.w += w * vv.w;
    }
    *(float4*)(outm + (size_t)row * DMODEL + tid * 4) = acc;
}

__device__ void flash_body(const __half* __restrict__ qkv,
                           __half* __restrict__ outO,
                           char* sm, int fb)
{
    const int tid = threadIdx.x, lane = tid & 31, wid = tid >> 5;
    const int wm = wid & 3, wn = wid >> 2;
    const int qt = fb & 15, bhh = fb >> 4, b = bhh >> 4, h = bhh & 15;
    const int qbase = qt * 64;
    const size_t srow = (size_t)b * SEQ;

    char* Qs = sm;
    char* Ks = sm + 9216;
    char* Vs = sm + 2*9216;          // [seq][hd], NOT transposed (ldsm.trans)
    float* msb = (float*)(sm + 3*9216);
    float* lsb = msb + 128;

    const int lrow = tid >> 2;
    const int lc0  = (tid & 3) * 16;  // halves

    {   // Q: pure 16B copies (unscaled; S scaled in regs)
        const __half* gq = qkv + (srow + qbase + lrow) * 3072 + h * 64 + lc0;
        char* qd = Qs + lrow * FROW + lc0 * 2;
        *(uint4*)(qd)      = *(const uint4*)(gq);
        *(uint4*)(qd + 16) = *(const uint4*)(gq + 8);
    }

    const int r = lane >> 2, q = lane & 3;
    float m0 = -1e30f, m1 = -1e30f, l0 = 0.f, l1 = 0.f;
    float o[8][4];
    #pragma unroll
    for (int i = 0; i < 8; i++) o[i][0]=o[i][1]=o[i][2]=o[i][3]=0.f;

    const uint32_t QA = smem_to_u32(Qs);
    const uint32_t qaddr0 = QA + (uint32_t)((wm*16 + (lane & 15)) * FROW + ((lane >> 4) & 1) * 16);
    const uint32_t kaddr0 = QA + 9216 + (uint32_t)((wn*32 + (lane & 7)) * FROW + ((lane >> 3) & 1) * 16);
    // V trans: lane 0..15 -> seq row (wn*32 + ks*16 + lane&15), col offset ntv*16B
    const uint32_t vaddr0 = QA + 2*9216 + (uint32_t)((wn*32 + (lane & 15)) * FROW);

    for (int kt = 0; kt <= qt; kt++) {
        __syncthreads();
        {   // K + V: pure 16B copies
            const __half* gk = qkv + (srow + kt*64 + lrow) * 3072 + 1024 + h * 64 + lc0;
            char* kd = Ks + lrow * FROW + lc0 * 2;
            *(uint4*)(kd)      = *(const uint4*)(gk);
            *(uint4*)(kd + 16) = *(const uint4*)(gk + 8);
            char* vd = Vs + lrow * FROW + lc0 * 2;
            *(uint4*)(vd)      = *(const uint4*)(gk + 1024);
            *(uint4*)(vd + 16) = *(const uint4*)(gk + 1024 + 8);
        }
        __syncthreads();

        // ---- S = Q K^T ----
        float s[4][4];
        #pragma unroll
        for (int nt = 0; nt < 4; nt++) s[nt][0]=s[nt][1]=s[nt][2]=s[nt][3]=0.f;
        #pragma unroll
        for (int ks = 0; ks < 4; ks++) {
            uint32_t aQ[4];
            ldsm4(aQ, qaddr0 + ks*32);
            uint32_t bK[4][2];
            #pragma unroll
            for (int nt = 0; nt < 4; nt++)
                ldsm2(bK[nt], kaddr0 + (uint32_t)(nt * 8 * FROW + ks * 32));
            #pragma unroll
            for (int nt = 0; nt < 4; nt++) mma16816(s[nt], aQ, bK[nt]);
        }
        // scale by 1/sqrt(HD)
        #pragma unroll
        for (int nt = 0; nt < 4; nt++) {
            s[nt][0] *= 0.125f; s[nt][1] *= 0.125f;
            s[nt][2] *= 0.125f; s[nt][3] *= 0.125f;
        }

        if (kt == qt) {
            const int r0 = wm*16 + r;
            #pragma unroll
            for (int nt = 0; nt < 4; nt++) {
                const int cb = wn*32 + nt*8 + q*2;
                if (cb     > r0)     s[nt][0] = -1e30f;
                if (cb + 1 > r0)     s[nt][1] = -1e30f;
                if (cb     > r0 + 8) s[nt][2] = -1e30f;
                if (cb + 1 > r0 + 8) s[nt][3] = -1e30f;
            }
        }

        // ---- online softmax stats ----
        float mx0 = fmaxf(fmaxf(s[0][0], s[0][1]), fmaxf(s[1][0], s[1][1]));
        mx0 = fmaxf(mx0, fmaxf(fmaxf(s[2][0], s[2][1]), fmaxf(s[3][0], s[3][1])));
        float mx1 = fmaxf(fmaxf(s[0][2], s[0][3]), fmaxf(s[1][2], s[1][3]));
        mx1 = fmaxf(mx1, fmaxf(fmaxf(s[2][2], s[2][3]), fmaxf(s[3][2], s[3][3])));
        mx0 = fmaxf(mx0, __shfl_xor_sync(0xffffffffu, mx0, 1));
        mx0 = fmaxf(mx0, __shfl_xor_sync(0xffffffffu, mx0, 2));
        mx1 = fmaxf(mx1, __shfl_xor_sync(0xffffffffu, mx1, 1));
        mx1 = fmaxf(mx1, __shfl_xor_sync(0xffffffffu, mx1, 2));
        if (q == 0) {
            msb[wn*64 + wm*16 + r]     = mx0;
            msb[wn*64 + wm*16 + r + 8] = mx1;
        }
        __syncthreads();
        const float mn0 = fmaxf(m0, fmaxf(mx0, msb[(1-wn)*64 + wm*16 + r]));
        const float mn1 = fmaxf(m1, fmaxf(mx1, msb[(1-wn)*64 + wm*16 + r + 8]));
        const float al0 = __expf(m0 - mn0), al1 = __expf(m1 - mn1);
        float sum0 = 0.f, sum1 = 0.f;
        #pragma unroll
        for (int nt = 0; nt < 4; nt++) {
            s[nt][0] = __expf(s[nt][0] - mn0);
            s[nt][1] = __expf(s[nt][1] - mn0);
            s[nt][2] = __expf(s[nt][2] - mn1);
            s[nt][3] = __expf(s[nt][3] - mn1);
            sum0 += s[nt][0] + s[nt][1];
            sum1 += s[nt][2] + s[nt][3];
        }
        sum0 += __shfl_xor_sync(0xffffffffu, sum0, 1);
        sum0 += __shfl_xor_sync(0xffffffffu, sum0, 2);
        sum1 += __shfl_xor_sync(0xffffffffu, sum1, 1);
        sum1 += __shfl_xor_sync(0xffffffffu, sum1, 2);
        if (q == 0) {
            lsb[wn*64 + wm*16 + r]     = sum0;
            lsb[wn*64 + wm*16 + r + 8] = sum1;
        }
        __syncthreads();
        l0 = al0 * l0 + sum0 + lsb[(1-wn)*64 + wm*16 + r];
        l1 = al1 * l1 + sum1 + lsb[(1-wn)*64 + wm*16 + r + 8];
        m0 = mn0; m1 = mn1;
        #pragma unroll
        for (int i = 0; i < 8; i++) {
            o[i][0] *= al0; o[i][1] *= al0; o[i][2] *= al1; o[i][3] *= al1;
        }

        // ---- P fragments ----
        uint32_t aP[2][4];
        #pragma unroll
        for (int ks = 0; ks < 2; ks++) {
            const int n0 = 2*ks, n1 = 2*ks + 1;
            aP[ks][0] = pack_h2(s[n0][0], s[n0][1]);
            aP[ks][1] = pack_h2(s[n0][2], s[n0][3]);
            aP[ks][2] = pack_h2(s[n1][0], s[n1][1]);
            aP[ks][3] = pack_h2(s[n1][2], s[n1][3]);
        }
        // ---- O += P V via ldsm.trans on [seq][hd] V ----
        #pragma unroll
        for (int ks = 0; ks < 2; ks++) {
            #pragma unroll
            for (int gq4 = 0; gq4 < 2; gq4++) {
                uint32_t bV[4][2];
                #pragma unroll
                for (int j = 0; j < 4; j++)
                    ldsm2t(bV[j], vaddr0 + (uint32_t)(ks * 16 * FROW + (gq4*4 + j) * 16));
                #pragma unroll
                for (int j = 0; j < 4; j++) mma16816(o[gq4*4+j], aP[ks], bV[j]);
            }
        }
    }

    // ---- combine wn partials, normalize, output ----
    __syncthreads();
    float* osum = (float*)sm;
    if (wn == 1) {
        #pragma unroll
        for (int ntv = 0; ntv < 8; ntv++) {
            const int rg = wm*16 + r, cg = ntv*8 + q*2;
            osum[rg*64 + cg]         = o[ntv][0];
            osum[rg*64 + cg + 1]     = o[ntv][1];
            osum[(rg+8)*64 + cg]     = o[ntv][2];
            osum[(rg+8)*64 + cg + 1] = o[ntv][3];
        }
    }
    __syncthreads();
    if (wn == 0) {
        const float i0 = 1.f / l0, i1 = 1.f / l1;
        #pragma unroll
        for (int ntv = 0; ntv < 8; ntv++) {
            const int rg = wm*16 + r, cg = ntv*8 + q*2;
            float v0 = (o[ntv][0] + osum[rg*64 + cg])         * i0;
            float v1 = (o[ntv][1] + osum[rg*64 + cg + 1])     * i0;
            float v2 = (o[ntv][2] + osum[(rg+8)*64 + cg])     * i1;
            float v3 = (o[ntv][3] + osum[(rg+8)*64 + cg + 1]) * i1;
            const size_t o0 = (srow + qbase + rg) * (size_t)DMODEL + h*64 + cg;
            const size_t o1 = o0 + 8 * DMODEL;
            *(uint32_t*)(outO + o0) = pack_h2(v0, v1);
            *(uint32_t*)(outO + o1) = pack_h2(v2, v3);
        }
    }
}

__global__ void __launch_bounds__(256) attn_kernel(
    const __half* __restrict__ qkv, const float* __restrict__ mkv,
    float* __restrict__ outm, __half* __restrict__ outO)
{
    extern __shared__ char sm[];
    if (blockIdx.x < 512) {
        flash_body(qkv, outO, sm, blockIdx.x);
    } else {
        memattn_body(qkv, mkv, outm, blockIdx.x - 512);
    }
}

// ------------------------------ launcher ------------------------------------
extern "C" void kernel_launch(void* const* d_in, const int* in_sizes, int n_in,
                              void* d_out, int out_size)
{
    (void)in_sizes; (void)n_in; (void)out_size;
    const float* prev  = (const float*)d_in[0];
    const float* memkv = (const float*)d_in[1];
    const float* gval  = (const float*)d_in[2];
    const float* ln1g  = (const float*)d_in[3];
    const float* ln1b  = (const float*)d_in[4];
    const float* attnw = (const float*)d_in[5];
    const float* attnb = (const float*)d_in[6];
    const float* cprw  = (const float*)d_in[7];
    const float* cprb  = (const float*)d_in[8];
    const float* ln2g  = (const float*)d_in[9];
    const float* ln2b  = (const float*)d_in[10];
    const float* fcw   = (const float*)d_in[11];
    const float* fcb   = (const float*)d_in[12];
    const float* pw    = (const float*)d_in[13];
    const float* pb    = (const float*)d_in[14];
    float* out = (float*)d_out;

    float *mem, *hid;
    __half *qkv, *h1, *att, *h2, *ff, *wq, *wp, *wf, *wo;
    cudaGetSymbolAddress((void**)&qkv, g_qkv);
    cudaGetSymbolAddress((void**)&mem, g_mem);
    cudaGetSymbolAddress((void**)&hid, g_hid);
    cudaGetSymbolAddress((void**)&h1,  g_h1);
    cudaGetSymbolAddress((void**)&att, g_att);
    cudaGetSymbolAddress((void**)&h2,  g_h2);
    cudaGetSymbolAddress((void**)&ff,  g_ff);
    cudaGetSymbolAddress((void**)&wq,  g_wq);
    cudaGetSymbolAddress((void**)&wp,  g_wp);
    cudaGetSymbolAddress((void**)&wf,  g_wf);
    cudaGetSymbolAddress((void**)&wo,  g_wo);

    cudaFuncSetAttribute(attn_kernel, cudaFuncAttributeMaxDynamicSharedMemorySize, FLASH_SMEM);
    cudaFuncSetAttribute(gemm_mma_kernel<4>, cudaFuncAttributeMaxDynamicSharedMemorySize, GEMM_SMEM);
    cudaFuncSetAttribute(gemm_mma_kernel<2>, cudaFuncAttributeMaxDynamicSharedMemorySize, GEMM_SMEM);
    cudaFuncSetAttribute(gemm_mma64_kernel<1>, cudaFuncAttributeMaxDynamicSharedMemorySize, GEMM64_SMEM);
    cudaFuncSetAttribute(gemm_mma64_kernel<3>, cudaFuncAttributeMaxDynamicSharedMemorySize, GEMM64_SMEM);

    // 1) prep: LN1 + all weight converts (fused)
    prep_kernel<<<14336, 256>>>(prev, ln1g, ln1b, h1,
        attnw, wq, cprw, wp, fcw, wf, pw, wo);
    // 2) qkv = h1 @ c_attn + b (fp16)
    gemm_mma_kernel<4><<<dim3(24, 16), 256, GEMM_SMEM>>>(h1, wq, attnb,
        nullptr, qkv, ROWS, 3*DMODEL, DMODEL, nullptr, nullptr, nullptr);
    // 3) fused flash-mma + memattn
    attn_kernel<<<512 + 2048, 256, FLASH_SMEM>>>(qkv, memkv, mem, att);
    // 4) hid = (1-g)*(att@c_proj+b) + g*mem + prev
    gemm_mma64_kernel<1><<<dim3(8, 32), 128, GEMM64_SMEM>>>(att, wp, cprb,
        hid, nullptr, ROWS, DMODEL, DMODEL, mem, prev, gval);
    // 5) LN2 -> h2
    prep_kernel<<<2048, 256>>>(hid, ln2g, ln2b, h2,
        nullptr, nullptr, nullptr, nullptr, nullptr, nullptr, nullptr, nullptr);
    // 6) ff = gelu(h2 @ fc + b) -> fp16
    gemm_mma_kernel<2><<<dim3(32, 16), 256, GEMM_SMEM>>>(h2, wf, fcb,
        nullptr, ff, ROWS, 4*DMODEL, DMODEL, nullptr, nullptr, nullptr);
    // 7) out = ff @ proj + b + hid
    gemm_mma64_kernel<3><<<dim3(8, 32), 128, GEMM64_SMEM>>>(ff, wo, pb,
        out, nullptr, ROWS, DMODEL, 4*DMODEL, hid, nullptr, nullptr);
}

// round 13
// speedup vs baseline: 3.6035x; 1.0236x over previous
#include <cuda_runtime.h>
#include <cuda_fp16.h>
#include <cstdint>

#define BS_    2
#define SEQ    1024
#define DMODEL 1024
#define NH     16
#define HD     64
#define MM     32
#define ROWS   (BS_*SEQ)

// ---------------- scratch (device globals) ----------------
__device__ __half g_qkv[ROWS*3*DMODEL];
__device__ float g_mem[ROWS*DMODEL];
__device__ float g_hid[ROWS*DMODEL];
__device__ __half g_h1 [ROWS*DMODEL];
__device__ __half g_att[ROWS*DMODEL];
__device__ __half g_h2 [ROWS*DMODEL];
__device__ __half g_ff [ROWS*4*DMODEL];
__device__ __half g_wq[DMODEL*3*DMODEL];
__device__ __half g_wp[DMODEL*DMODEL];
__device__ __half g_wf[DMODEL*4*DMODEL];
__device__ __half g_wo[4*DMODEL*DMODEL];

// ---------------- helpers ----------------
__device__ __forceinline__ uint32_t smem_to_u32(const void* p) {
    uint32_t a;
    asm("{ .reg .u64 t; cvta.to.shared.u64 t, %1; cvt.u32.u64 %0, t; }" : "=r"(a) : "l"(p));
    return a;
}
__device__ __forceinline__ void cp16(uint32_t s, const void* g) {
    asm volatile("cp.async.cg.shared.global [%0], [%1], 16;" :: "r"(s), "l"(g));
}
#define CP_COMMIT() asm volatile("cp.async.commit_group;" ::: "memory")
#define CP_WAIT1()  asm volatile("cp.async.wait_group 1;" ::: "memory")

__device__ __forceinline__ void ldsm4(uint32_t* r, uint32_t addr) {
    asm volatile("ldmatrix.sync.aligned.m8n8.x4.shared.b16 {%0,%1,%2,%3}, [%4];"
        : "=r"(r[0]), "=r"(r[1]), "=r"(r[2]), "=r"(r[3]) : "r"(addr));
}
__device__ __forceinline__ void ldsm2(uint32_t* r, uint32_t addr) {
    asm volatile("ldmatrix.sync.aligned.m8n8.x2.shared.b16 {%0,%1}, [%2];"
        : "=r"(r[0]), "=r"(r[1]) : "r"(addr));
}
__device__ __forceinline__ void ldsm2t(uint32_t* r, uint32_t addr) {
    asm volatile("ldmatrix.sync.aligned.m8n8.x2.trans.shared.b16 {%0,%1}, [%2];"
        : "=r"(r[0]), "=r"(r[1]) : "r"(addr));
}
__device__ __forceinline__ void mma16816(float* d, const uint32_t* a, const uint32_t* b) {
    asm volatile(
      "mma.sync.aligned.m16n8k16.row.col.f32.f16.f16.f32 "
      "{%0,%1,%2,%3}, {%4,%5,%6,%7}, {%8,%9}, {%0,%1,%2,%3};"
      : "+f"(d[0]), "+f"(d[1]), "+f"(d[2]), "+f"(d[3])
      : "r"(a[0]), "r"(a[1]), "r"(a[2]), "r"(a[3]), "r"(b[0]), "r"(b[1]));
}

__device__ __forceinline__ float gelu_new(float x) {
    float x3 = x * x * x;
    float t  = tanhf(0.7978845608028654f * (x + 0.044715f * x3));
    return 0.5f * x * (1.f + t);
}
__device__ __forceinline__ uint32_t pack_h2(float x, float y) {
    __half2 t = __floats2half2_rn(x, y);
    return *reinterpret_cast<uint32_t*>(&t);
}

// ---------------- prep: fused 4x weight-convert + LN -----------------------
__device__ void wconv_body(float* shm,
    const float* __restrict__ W, __half* __restrict__ hi,
    int K, int N, int bx, int by)
{
    float (*s)[33] = (float(*)[33])shm;
    const int tx = threadIdx.x & 31, ty = threadIdx.x >> 5;
    const int n0 = bx * 32, k0 = by * 32;
    #pragma unroll
    for (int i = 0; i < 4; i++)
        s[ty + 8*i][tx] = W[(size_t)(k0 + ty + 8*i) * N + n0 + tx];
    __syncthreads();
    #pragma unroll
    for (int i = 0; i < 4; i++) {
        int n = ty + 8*i;
        hi[(size_t)(n0 + n) * K + k0 + tx] = __float2half(s[tx][n]);
    }
}

__device__ void ln_body(float* shm, int row,
    const float* __restrict__ x, const float* __restrict__ g,
    const float* __restrict__ b, __half* __restrict__ y)
{
    const int tid = threadIdx.x;
    float* rs = shm; float* rs2 = shm + 8;
    const float* xr = x + (size_t)row * DMODEL;
    float4 v = *(const float4*)(xr + tid * 4);
    float s  = v.x + v.y + v.z + v.w;
    float s2 = v.x*v.x + v.y*v.y + v.z*v.z + v.w*v.w;
    #pragma unroll
    for (int o = 16; o; o >>= 1) {
        s  += __shfl_xor_sync(0xffffffffu, s,  o);
        s2 += __shfl_xor_sync(0xffffffffu, s2, o);
    }
    const int w = tid >> 5, l = tid & 31;
    if (!l) { rs[w] = s; rs2[w] = s2; }
    __syncthreads();
    s = 0.f; s2 = 0.f;
    #pragma unroll
    for (int i = 0; i < 8; i++) { s += rs[i]; s2 += rs2[i]; }
    const float mean = s * (1.f / DMODEL);
    const float var  = s2 * (1.f / DMODEL) - mean * mean;
    const float rstd = rsqrtf(var + 1e-5f);
    const int c = tid * 4;
    float4 gg = *(const float4*)(g + c);
    float4 bb = *(const float4*)(b + c);
    float4 o;
    o.x = (v.x - mean) * rstd * gg.x + bb.x;
    o.y = (v.y - mean) * rstd * gg.y + bb.y;
    o.z = (v.z - mean) * rstd * gg.z + bb.z;
    o.w = (v.w - mean) * rstd * gg.w + bb.w;
    uint2 hh;
    hh.x = pack_h2(o.x, o.y); hh.y = pack_h2(o.z, o.w);
    *(uint2*)(y + (size_t)row * DMODEL + c) = hh;
}

__global__ void __launch_bounds__(256) prep_kernel(
    const float* prev, const float* ln1g, const float* ln1b, __half* h1,
    const float* attnw, __half* wq,
    const float* cprw,  __half* wp,
    const float* fcw,   __half* wf,
    const float* pw,    __half* wo)
{
    __shared__ float shm[32*33];
    int idx = blockIdx.x;
    if (idx < 2048) { ln_body(shm, idx, prev, ln1g, ln1b, h1); return; }
    idx -= 2048;
    if (idx < 3072) { wconv_body(shm, attnw, wq, 1024, 3072, idx % 96, idx / 96); return; }
    idx -= 3072;
    if (idx < 1024) { wconv_body(shm, cprw, wp, 1024, 1024, idx % 32, idx / 32); return; }
    idx -= 1024;
    if (idx < 4096) { wconv_body(shm, fcw, wf, 1024, 4096, idx % 128, idx / 128); return; }
    idx -= 4096;
    wconv_body(shm, pw, wo, 4096, 1024, idx % 32, idx / 32);
}

// ---------------- epilogue (shared) -----------------------------------------
template<int EPI>
__device__ __forceinline__ void gemm_epilogue_elem(
    float v0, float v1, const float2 bb, size_t o,
    float* Cf, __half* Ch,
    const float* aux1, const float* aux2, float g)
{
    v0 += bb.x; v1 += bb.y;
    if (EPI == 1) {
        float2 a1 = *(const float2*)(aux1 + o);
        float2 a2 = *(const float2*)(aux2 + o);
        v0 = (1.f - g) * v0 + g * a1.x + a2.x;
        v1 = (1.f - g) * v1 + g * a1.y + a2.y;
    }
    if (EPI == 3) {
        float2 a1 = *(const float2*)(aux1 + o);
        v0 += a1.x; v1 += a1.y;
    }
    if (EPI == 2) {
        v0 = gelu_new(v0); v1 = gelu_new(v1);
        *(uint32_t*)(Ch + o) = pack_h2(v0, v1);
    } else if (EPI == 4) {
        *(uint32_t*)(Ch + o) = pack_h2(v0, v1);
    } else {
        *(float2*)(Cf + o) = make_float2(v0, v1);
    }
}

// ---------------- GEMM 128x128 tile, fp16, K-chunk 64 ------------------------
#define AB_     8192
#define GSTAGE  (4*AB_)                 // 32768
#define GEMM_SMEM (3*GSTAGE)            // 98304

template<int EPI>
__global__ void __launch_bounds__(256, 2) gemm_mma_kernel(
    const __half* __restrict__ A, const __half* __restrict__ B,
    const float* __restrict__ bias,
    float* __restrict__ Cf, __half* __restrict__ Ch,
    int M, int N, int K,
    const float* __restrict__ aux1, const float* __restrict__ aux2,
    const float* __restrict__ gp)
{
    extern __shared__ char smp[];
    const uint32_t sb = smem_to_u32(smp);
    const int tid = threadIdx.x;
    const int wid = tid >> 5, lane = tid & 31;
    const int wm = wid & 1, wn = wid >> 1;
    const int bm = blockIdx.y, bn = blockIdx.x;
    const int NC = K >> 6;

    const size_t Abase = (size_t)bm * 128 * K;
    const size_t Bbase = (size_t)bn * 128 * K;

    float acc[4][4][4];
    #pragma unroll
    for (int i = 0; i < 4; i++)
        #pragma unroll
        for (int j = 0; j < 4; j++)
            #pragma unroll
            for (int x = 0; x < 4; x++) acc[i][j][x] = 0.f;

    const int crow = tid >> 2;
    const int cq   = tid & 3;
    const uint32_t so0 = (uint32_t)(crow * 64 + ((cq ^ (crow & 3)) << 4));
    const uint32_t so1 = so0 + 64 * 64;

    auto issue = [&](int buf, int kt) {
        const int k0 = kt << 6;
        const uint32_t sbase = sb + buf * GSTAGE;
        const size_t g0 = (size_t)crow * K + k0 + cq * 8;
        const size_t g1 = g0 + (size_t)64 * K;
        #pragma unroll
        for (int sl = 0; sl < 2; sl++) {
            cp16(sbase + sl*AB_ + so0,          A + Abase + g0 + sl*32);
            cp16(sbase + sl*AB_ + so1,          A + Abase + g1 + sl*32);
            cp16(sbase + (2+sl)*AB_ + so0,      B + Bbase + g0 + sl*32);
            cp16(sbase + (2+sl)*AB_ + so1,      B + Bbase + g1 + sl*32);
        }
    };

    issue(0, 0); CP_COMMIT();
    issue(1, 1); CP_COMMIT();

    const uint32_t rowA = (uint32_t)(wm * 64 + (lane & 15));
    const uint32_t qa   = (uint32_t)(lane >> 4);
    const uint32_t r3a  = rowA & 3;
    const uint32_t aBase = rowA * 64;
    const uint32_t rowB = (uint32_t)(wn * 32 + (lane & 7));
    const uint32_t qb   = (uint32_t)((lane >> 3) & 1);
    const uint32_t r3b  = rowB & 3;
    const uint32_t bBase = rowB * 64;

    int buf = 0;
    for (int c = 0; c < NC; c++) {
        CP_WAIT1();
        __syncthreads();
        if (c + 2 < NC) { int nb = buf + 2; if (nb >= 3) nb -= 3; issue(nb, c + 2); }
        CP_COMMIT();

        const uint32_t s0 = sb + buf * GSTAGE;
        #pragma unroll
        for (int sl = 0; sl < 2; sl++) {
            const uint32_t sA = s0 + sl*AB_;
            const uint32_t sB = s0 + (2+sl)*AB_;
            #pragma unroll
            for (int ks = 0; ks < 2; ks++) {
                uint32_t bfr[4][2];
                const uint32_t qpb = ((qb + 2*ks) ^ r3b) << 4;
                #pragma unroll
                for (int nt = 0; nt < 4; nt++)
                    ldsm2(bfr[nt], sB + bBase + (uint32_t)(nt * 512) + qpb);
                const uint32_t qpa = ((qa + 2*ks) ^ r3a) << 4;
                #pragma unroll
                for (int mt = 0; mt < 4; mt++) {
                    uint32_t a[4];
                    ldsm4(a, sA + aBase + (uint32_t)(mt * 1024) + qpa);
                    #pragma unroll
                    for (int nt = 0; nt < 4; nt++) mma16816(acc[mt][nt], a, bfr[nt]);
                }
            }
        }
        buf++; if (buf >= 3) buf = 0;
    }

    const int r = lane >> 2, q = lane & 3;
    const float g = (EPI == 1) ? *gp : 0.f;
    #pragma unroll
    for (int mt = 0; mt < 4; mt++) {
        #pragma unroll
        for (int nt = 0; nt < 4; nt++) {
            const int col = bn * 128 + wn * 32 + nt * 8 + q * 2;
            const float2 bb = *(const float2*)(bias + col);
            #pragma unroll
            for (int hh = 0; hh < 2; hh++) {
                const int row = bm * 128 + wm * 64 + mt * 16 + r + hh * 8;
                gemm_epilogue_elem<EPI>(acc[mt][nt][hh*2], acc[mt][nt][hh*2+1], bb,
                    (size_t)row * N + col, Cf, Ch, aux1, aux2, g);
            }
        }
    }
}

// ---------------- GEMM 64x128 tile, fp16, K-chunk 64 -------------------------
#define A64_      4096
#define B64_      8192
#define GSTAGE64  (2*A64_ + 2*B64_)     // 24576
#define GEMM64_SMEM (3*GSTAGE64)        // 73728

template<int EPI>
__global__ void __launch_bounds__(128, 3) gemm_mma64_kernel(
    const __half* __restrict__ A, const __half* __restrict__ B,
    const float* __restrict__ bias,
    float* __restrict__ Cf, __half* __restrict__ Ch,
    int M, int N, int K,
    const float* __restrict__ aux1, const float* __restrict__ aux2,
    const float* __restrict__ gp)
{
    extern __shared__ char smp[];
    const uint32_t sb = smem_to_u32(smp);
    const int tid = threadIdx.x;
    const int wn = tid >> 5, lane = tid & 31;
    const int bm = blockIdx.y, bn = blockIdx.x;
    const int NC = K >> 6;

    const size_t Abase = (size_t)bm * 64 * K;
    const size_t Bbase = (size_t)bn * 128 * K;

    float acc[4][4][4];
    #pragma unroll
    for (int i = 0; i < 4; i++)
        #pragma unroll
        for (int j = 0; j < 4; j++)
            #pragma unroll
            for (int x = 0; x < 4; x++) acc[i][j][x] = 0.f;

    const int crow = tid >> 2;
    const int cq   = tid & 3;
    const uint32_t soA = (uint32_t)(crow * 64 + ((cq ^ (crow & 3)) << 4));

    auto issue = [&](int buf, int kt) {
        const int k0 = kt << 6;
        const uint32_t sbase = sb + buf * GSTAGE64;
        const size_t gc = (size_t)crow * K + k0 + cq * 8;
        #pragma unroll
        for (int sl = 0; sl < 2; sl++) {
            cp16(sbase + sl*A64_ + soA,        A + Abase + gc + sl*32);
            cp16(sbase + sl*A64_ + soA + 2048, A + Abase + gc + sl*32 + (size_t)32 * K);
            #pragma unroll
            for (int j = 0; j < 4; j++)
                cp16(sbase + 2*A64_ + sl*B64_ + soA + j*2048,
                     B + Bbase + gc + sl*32 + (size_t)(32 * j) * K);
        }
    };

    issue(0, 0); CP_COMMIT();
    issue(1, 1); CP_COMMIT();

    const uint32_t rowA = (uint32_t)(lane & 15);
    const uint32_t qa   = (uint32_t)(lane >> 4);
    const uint32_t r3a  = rowA & 3;
    const uint32_t aBase = rowA * 64;
    const uint32_t rowB = (uint32_t)(wn * 32 + (lane & 7));
    const uint32_t qb   = (uint32_t)((lane >> 3) & 1);
    const uint32_t r3b  = rowB & 3;
    const uint32_t bBase = rowB * 64;

    int buf = 0;
    for (int c = 0; c < NC; c++) {
        CP_WAIT1();
        __syncthreads();
        if (c + 2 < NC) { int nb = buf + 2; if (nb >= 3) nb -= 3; issue(nb, c + 2); }
        CP_COMMIT();

        const uint32_t s0 = sb + buf * GSTAGE64;
        #pragma unroll
        for (int sl = 0; sl < 2; sl++) {
            const uint32_t sA = s0 + sl*A64_;
            const uint32_t sB = s0 + 2*A64_ + sl*B64_;
            #pragma unroll
            for (int ks = 0; ks < 2; ks++) {
                uint32_t bfr[4][2];
                const uint32_t qpb = ((qb + 2*ks) ^ r3b) << 4;
                #pragma unroll
                for (int nt = 0; nt < 4; nt++)
                    ldsm2(bfr[nt], sB + bBase + (uint32_t)(nt * 512) + qpb);
                const uint32_t qpa = ((qa + 2*ks) ^ r3a) << 4;
                #pragma unroll
                for (int mt = 0; mt < 4; mt++) {
                    uint32_t a[4];
                    ldsm4(a, sA + aBase + (uint32_t)(mt * 1024) + qpa);
                    #pragma unroll
                    for (int nt = 0; nt < 4; nt++) mma16816(acc[mt][nt], a, bfr[nt]);
                }
            }
        }
        buf++; if (buf >= 3) buf = 0;
    }

    const int r = lane >> 2, q = lane & 3;
    const float g = (EPI == 1) ? *gp : 0.f;
    #pragma unroll
    for (int mt = 0; mt < 4; mt++) {
        #pragma unroll
        for (int nt = 0; nt < 4; nt++) {
            const int col = bn * 128 + wn * 32 + nt * 8 + q * 2;
            const float2 bb = *(const float2*)(bias + col);
            #pragma unroll
            for (int hh = 0; hh < 2; hh++) {
                const int row = bm * 64 + mt * 16 + r + hh * 8;
                gemm_epilogue_elem<EPI>(acc[mt][nt][hh*2], acc[mt][nt][hh*2+1], bb,
                    (size_t)row * N + col, Cf, Ch, aux1, aux2, g);
            }
        }
    }
}

// ---------------- fused attention (128 threads): flash (512) + memattn ------
// flash: 4 warps, warp w owns rows w*16..w*16+15, ALL 64 cols.
// Producers: each thread copies 64B per row half (FIXED from R12's 32B bug).
#define FROW 144
#define FLASH_SMEM (3*9216)

__device__ void memattn_body(const __half* __restrict__ qkv,
                             const float* __restrict__ mkv,
                             float* __restrict__ outm, int row)
{
    const int tid = threadIdx.x;              // 0..127
    const int h = tid >> 3, t8 = tid & 7;     // 8 lanes per head
    __shared__ float sc[NH * MM];
    const int co = h * 64 + t8 * 8;
    uint4 qraw = *(const uint4*)(qkv + (size_t)row * 3072 + co);
    float qv[8];
    {
        __half2* qh = (__half2*)&qraw;
        #pragma unroll
        for (int i = 0; i < 4; i++) {
            qv[2*i]   = __low2float(qh[i])  * 0.125f;
            qv[2*i+1] = __high2float(qh[i]) * 0.125f;
        }
    }
    const float* kbase = mkv + (size_t)row * MM * 2 * DMODEL;
    #pragma unroll 4
    for (int m = 0; m < MM; m++) {
        const float* kp = kbase + (size_t)m * 2 * DMODEL + co;
        float4 k0 = *(const float4*)(kp);
        float4 k1 = *(const float4*)(kp + 4);
        float d = qv[0]*k0.x + qv[1]*k0.y + qv[2]*k0.z + qv[3]*k0.w
                + qv[4]*k1.x + qv[5]*k1.y + qv[6]*k1.z + qv[7]*k1.w;
        #pragma unroll
        for (int o = 4; o; o >>= 1) d += __shfl_xor_sync(0xffffffffu, d, o);
        if (t8 == 0) sc[h * MM + m] = d;
    }
    __syncthreads();
    if (tid < NH) {
        float mx = -1e30f;
        #pragma unroll
        for (int m = 0; m < MM; m++) mx = fmaxf(mx, sc[tid * MM + m]);
        float s = 0.f;
        #pragma unroll
        for (int m = 0; m < MM; m++) {
            float e = __expf(sc[tid * MM + m] - mx);
            sc[tid * MM + m] = e; s += e;
        }
        float inv = 1.f / s;
        #pragma unroll
        for (int m = 0; m < MM; m++) sc[tid * MM + m] *= inv;
    }
    __syncthreads();
    float a0 = 0.f, a1 = 0.f, a2 = 0.f, a3 = 0.f, a4 = 0.f, a5 = 0.f, a6 = 0.f, a7 = 0.f;
    #pragma unroll 4
    for (int m = 0; m < MM; m++) {
        float w = sc[h * MM + m];
        const float* vp = kbase + (size_t)m * 2 * DMODEL + DMODEL + co;
        float4 v0 = *(const float4*)(vp);
        float4 v1 = *(const float4*)(vp + 4);
        a0 += w*v0.x; a1 += w*v0.y; a2 += w*v0.z; a3 += w*v0.w;
        a4 += w*v1.x; a5 += w*v1.y; a6 += w*v1.z; a7 += w*v1.w;
    }
    float* op = outm + (size_t)row * DMODEL + co;
    *(float4*)(op)     = make_float4(a0, a1, a2, a3);
    *(float4*)(op + 4) = make_float4(a4, a5, a6, a7);
}

__device__ void flash_body(const __half* __restrict__ qkv,
                           __half* __restrict__ outO,
                           char* sm, int fb)
{
    const int tid = threadIdx.x, lane = tid & 31, wm = tid >> 5;  // 4 warps
    const int qt = 15 - (fb & 15);            // big tiles first
    const int bhh = fb >> 4, b = bhh >> 4, h = bhh & 15;
    const int qbase = qt * 64;
    const size_t srow = (size_t)b * SEQ;

    char* Qs = sm;
    char* Ks = sm + 9216;
    char* Vs = sm + 2*9216;          // [seq][hd], ldsm.trans for PV

    const int lrow = tid >> 1;              // 0..63
    const int lh   = (tid & 1) * 32;        // half of the 64-half row (64B)

    {   // Q: 4x16B copies per thread = full 128B row across 2 threads
        const __half* gq = qkv + (srow + qbase + lrow) * 3072 + h * 64 + lh;
        char* qd = Qs + lrow * FROW + lh * 2;
        *(uint4*)(qd)      = *(const uint4*)(gq);
        *(uint4*)(qd + 16) = *(const uint4*)(gq + 8);
        *(uint4*)(qd + 32) = *(const uint4*)(gq + 16);
        *(uint4*)(qd + 48) = *(const uint4*)(gq + 24);
    }

    const int r = lane >> 2, q = lane & 3;
    float m0 = -1e30f, m1 = -1e30f, l0 = 0.f, l1 = 0.f;
    float o[8][4];
    #pragma unroll
    for (int i = 0; i < 8; i++) o[i][0]=o[i][1]=o[i][2]=o[i][3]=0.f;

    const uint32_t QA = smem_to_u32(Qs);
    const uint32_t qaddr0 = QA + (uint32_t)((wm*16 + (lane & 15)) * FROW + ((lane >> 4) & 1) * 16);
    const uint32_t kaddr0 = QA + 9216 + (uint32_t)((lane & 7) * FROW + ((lane >> 3) & 1) * 16);
    const uint32_t vaddr0 = QA + 2*9216 + (uint32_t)((lane & 15) * FROW);

    for (int kt = 0; kt <= qt; kt++) {
        __syncthreads();
        {   // K + V: 4x16B copies each
            const __half* gk = qkv + (srow + kt*64 + lrow) * 3072 + 1024 + h * 64 + lh;
            char* kd = Ks + lrow * FROW + lh * 2;
            *(uint4*)(kd)      = *(const uint4*)(gk);
            *(uint4*)(kd + 16) = *(const uint4*)(gk + 8);
            *(uint4*)(kd + 32) = *(const uint4*)(gk + 16);
            *(uint4*)(kd + 48) = *(const uint4*)(gk + 24);
            char* vd = Vs + lrow * FROW + lh * 2;
            *(uint4*)(vd)      = *(const uint4*)(gk + 1024);
            *(uint4*)(vd + 16) = *(const uint4*)(gk + 1024 + 8);
            *(uint4*)(vd + 32) = *(const uint4*)(gk + 1024 + 16);
            *(uint4*)(vd + 48) = *(const uint4*)(gk + 1024 + 24);
        }
        __syncthreads();

        // ---- S = Q K^T: warp covers 16 rows x 64 cols ----
        float s[8][4];
        #pragma unroll
        for (int nt = 0; nt < 8; nt++) s[nt][0]=s[nt][1]=s[nt][2]=s[nt][3]=0.f;
        #pragma unroll
        for (int ks = 0; ks < 4; ks++) {
            uint32_t aQ[4];
            ldsm4(aQ, qaddr0 + ks*32);
            uint32_t bK[8][2];
            #pragma unroll
            for (int nt = 0; nt < 8; nt++)
                ldsm2(bK[nt], kaddr0 + (uint32_t)(nt * 8 * FROW + ks * 32));
            #pragma unroll
            for (int nt = 0; nt < 8; nt++) mma16816(s[nt], aQ, bK[nt]);
        }
        #pragma unroll
        for (int nt = 0; nt < 8; nt++) {
            s[nt][0] *= 0.125f; s[nt][1] *= 0.125f;
            s[nt][2] *= 0.125f; s[nt][3] *= 0.125f;
        }

        if (kt == qt) {
            const int r0 = wm*16 + r;
            #pragma unroll
            for (int nt = 0; nt < 8; nt++) {
                const int cb = nt*8 + q*2;
                if (cb     > r0)     s[nt][0] = -1e30f;
                if (cb + 1 > r0)     s[nt][1] = -1e30f;
                if (cb     > r0 + 8) s[nt][2] = -1e30f;
                if (cb + 1 > r0 + 8) s[nt][3] = -1e30f;
            }
        }

        // ---- online softmax: quad-shuffle only ----
        float mx0 = -1e30f, mx1 = -1e30f;
        #pragma unroll
        for (int nt = 0; nt < 8; nt++) {
            mx0 = fmaxf(mx0, fmaxf(s[nt][0], s[nt][1]));
            mx1 = fmaxf(mx1, fmaxf(s[nt][2], s[nt][3]));
        }
        mx0 = fmaxf(mx0, __shfl_xor_sync(0xffffffffu, mx0, 1));
        mx0 = fmaxf(mx0, __shfl_xor_sync(0xffffffffu, mx0, 2));
        mx1 = fmaxf(mx1, __shfl_xor_sync(0xffffffffu, mx1, 1));
        mx1 = fmaxf(mx1, __shfl_xor_sync(0xffffffffu, mx1, 2));
        const float mn0 = fmaxf(m0, mx0);
        const float mn1 = fmaxf(m1, mx1);
        const float al0 = __expf(m0 - mn0), al1 = __expf(m1 - mn1);
        float sum0 = 0.f, sum1 = 0.f;
        #pragma unroll
        for (int nt = 0; nt < 8; nt++) {
            s[nt][0] = __expf(s[nt][0] - mn0);
            s[nt][1] = __expf(s[nt][1] - mn0);
            s[nt][2] = __expf(s[nt][2] - mn1);
            s[nt][3] = __expf(s[nt][3] - mn1);
            sum0 += s[nt][0] + s[nt][1];
            sum1 += s[nt][2] + s[nt][3];
        }
        sum0 += __shfl_xor_sync(0xffffffffu, sum0, 1);
        sum0 += __shfl_xor_sync(0xffffffffu, sum0, 2);
        sum1 += __shfl_xor_sync(0xffffffffu, sum1, 1);
        sum1 += __shfl_xor_sync(0xffffffffu, sum1, 2);
        l0 = al0 * l0 + sum0;
        l1 = al1 * l1 + sum1;
        m0 = mn0; m1 = mn1;
        #pragma unroll
        for (int i = 0; i < 8; i++) {
            o[i][0] *= al0; o[i][1] *= al0; o[i][2] *= al1; o[i][3] *= al1;
        }

        // ---- P fragments: 4 k16-steps over 64 seq keys ----
        uint32_t aP[4][4];
        #pragma unroll
        for (int ks = 0; ks < 4; ks++) {
            const int n0 = 2*ks, n1 = 2*ks + 1;
            aP[ks][0] = pack_h2(s[n0][0], s[n0][1]);
            aP[ks][1] = pack_h2(s[n0][2], s[n0][3]);
            aP[ks][2] = pack_h2(s[n1][0], s[n1][1]);
            aP[ks][3] = pack_h2(s[n1][2], s[n1][3]);
        }
        // ---- O += P V via ldsm.trans, 8 col-fragments ----
        #pragma unroll
        for (int ks = 0; ks < 4; ks++) {
            #pragma unroll
            for (int gq4 = 0; gq4 < 2; gq4++) {
                uint32_t bV[4][2];
                #pragma unroll
                for (int j = 0; j < 4; j++)
                    ldsm2t(bV[j], vaddr0 + (uint32_t)(ks * 16 * FROW + (gq4*4 + j) * 16));
                #pragma unroll
                for (int j = 0; j < 4; j++) mma16816(o[gq4*4+j], aP[ks], bV[j]);
            }
        }
    }

    // ---- normalize, output directly ----
    const float i0 = 1.f / l0, i1 = 1.f / l1;
    #pragma unroll
    for (int ntv = 0; ntv < 8; ntv++) {
        const int rg = wm*16 + r, cg = ntv*8 + q*2;
        const size_t o0 = (srow + qbase + rg) * (size_t)DMODEL + h*64 + cg;
        const size_t o1 = o0 + 8 * DMODEL;
        *(uint32_t*)(outO + o0) = pack_h2(o[ntv][0] * i0, o[ntv][1] * i0);
        *(uint32_t*)(outO + o1) = pack_h2(o[ntv][2] * i1, o[ntv][3] * i1);
    }
}

__global__ void __launch_bounds__(128) attn_kernel(
    const __half* __restrict__ qkv, const float* __restrict__ mkv,
    float* __restrict__ outm, __half* __restrict__ outO)
{
    extern __shared__ char sm[];
    if (blockIdx.x < 512) {
        flash_body(qkv, outO, sm, blockIdx.x);
    } else {
        memattn_body(qkv, mkv, outm, blockIdx.x - 512);
    }
}

// ------------------------------ launcher ------------------------------------
extern "C" void kernel_launch(void* const* d_in, const int* in_sizes, int n_in,
                              void* d_out, int out_size)
{
    (void)in_sizes; (void)n_in; (void)out_size;
    const float* prev  = (const float*)d_in[0];
    const float* memkv = (const float*)d_in[1];
    const float* gval  = (const float*)d_in[2];
    const float* ln1g  = (const float*)d_in[3];
    const float* ln1b  = (const float*)d_in[4];
    const float* attnw = (const float*)d_in[5];
    const float* attnb = (const float*)d_in[6];
    const float* cprw  = (const float*)d_in[7];
    const float* cprb  = (const float*)d_in[8];
    const float* ln2g  = (const float*)d_in[9];
    const float* ln2b  = (const float*)d_in[10];
    const float* fcw   = (const float*)d_in[11];
    const float* fcb   = (const float*)d_in[12];
    const float* pw    = (const float*)d_in[13];
    const float* pb    = (const float*)d_in[14];
    float* out = (float*)d_out;

    float *mem, *hid;
    __half *qkv, *h1, *att, *h2, *ff, *wq, *wp, *wf, *wo;
    cudaGetSymbolAddress((void**)&qkv, g_qkv);
    cudaGetSymbolAddress((void**)&mem, g_mem);
    cudaGetSymbolAddress((void**)&hid, g_hid);
    cudaGetSymbolAddress((void**)&h1,  g_h1);
    cudaGetSymbolAddress((void**)&att, g_att);
    cudaGetSymbolAddress((void**)&h2,  g_h2);
    cudaGetSymbolAddress((void**)&ff,  g_ff);
    cudaGetSymbolAddress((void**)&wq,  g_wq);
    cudaGetSymbolAddress((void**)&wp,  g_wp);
    cudaGetSymbolAddress((void**)&wf,  g_wf);
    cudaGetSymbolAddress((void**)&wo,  g_wo);

    cudaFuncSetAttribute(attn_kernel, cudaFuncAttributeMaxDynamicSharedMemorySize, FLASH_SMEM);
    cudaFuncSetAttribute(gemm_mma_kernel<4>, cudaFuncAttributeMaxDynamicSharedMemorySize, GEMM_SMEM);
    cudaFuncSetAttribute(gemm_mma_kernel<2>, cudaFuncAttributeMaxDynamicSharedMemorySize, GEMM_SMEM);
    cudaFuncSetAttribute(gemm_mma64_kernel<1>, cudaFuncAttributeMaxDynamicSharedMemorySize, GEMM64_SMEM);
    cudaFuncSetAttribute(gemm_mma64_kernel<3>, cudaFuncAttributeMaxDynamicSharedMemorySize, GEMM64_SMEM);

    // 1) prep: LN1 + all weight converts (fused)
    prep_kernel<<<14336, 256>>>(prev, ln1g, ln1b, h1,
        attnw, wq, cprw, wp, fcw, wf, pw, wo);
    // 2) qkv = h1 @ c_attn + b (fp16)
    gemm_mma_kernel<4><<<dim3(24, 16), 256, GEMM_SMEM>>>(h1, wq, attnb,
        nullptr, qkv, ROWS, 3*DMODEL, DMODEL, nullptr, nullptr, nullptr);
    // 3) fused flash-mma + memattn (128 threads)
    attn_kernel<<<512 + 2048, 128, FLASH_SMEM>>>(qkv, memkv, mem, att);
    // 4) hid = (1-g)*(att@c_proj+b) + g*mem + prev
    gemm_mma64_kernel<1><<<dim3(8, 32), 128, GEMM64_SMEM>>>(att, wp, cprb,
        hid, nullptr, ROWS, DMODEL, DMODEL, mem, prev, gval);
    // 5) LN2 -> h2
    prep_kernel<<<2048, 256>>>(hid, ln2g, ln2b, h2,
        nullptr, nullptr, nullptr, nullptr, nullptr, nullptr, nullptr, nullptr);
    // 6) ff = gelu(h2 @ fc + b) -> fp16
    gemm_mma_kernel<2><<<dim3(32, 16), 256, GEMM_SMEM>>>(h2, wf, fcb,
        nullptr, ff, ROWS, 4*DMODEL, DMODEL, nullptr, nullptr, nullptr);
    // 7) out = ff @ proj + b + hid
    gemm_mma64_kernel<3><<<dim3(8, 32), 128, GEMM64_SMEM>>>(ff, wo, pb,
        out, nullptr, ROWS, DMODEL, 4*DMODEL, hid, nullptr, nullptr);
}